// round 5
// baseline (speedup 1.0000x reference)
#include <cuda_runtime.h>
#include <cuda_bf16.h>
#include <cstdint>

// Problem dims
#define Bsz   2
#define Ssz   2048
#define Hsz   2048
#define NHEAD 16
#define HDIM  128
#define Mrows (Bsz*Ssz)   // 4096

typedef __nv_bfloat16 bf16;

// ---------------- scratch (static device globals) ----------------
__device__ bf16 g_xh [Mrows*Hsz], g_xl [Mrows*Hsz];
__device__ bf16 g_qh [Mrows*Hsz], g_ql [Mrows*Hsz];
__device__ bf16 g_kh [Mrows*Hsz], g_kl [Mrows*Hsz];
__device__ bf16 g_vh [Mrows*Hsz], g_vl [Mrows*Hsz];
__device__ bf16 g_aoh[Mrows*Hsz], g_aol[Mrows*Hsz];
__device__ bf16 g_wh [4][Hsz*Hsz], g_wl [4][Hsz*Hsz];

// ---------------- helpers ----------------
__device__ __forceinline__ uint32_t smem_u32(const void* p) {
    uint32_t a;
    asm("{ .reg .u64 t; cvta.to.shared.u64 t, %1; cvt.u32.u64 %0, t; }" : "=r"(a) : "l"(p));
    return a;
}
#define CP_ASYNC16(sa, ga) \
    asm volatile("cp.async.cg.shared.global [%0], [%1], 16;" :: "r"((uint32_t)(sa)), "l"(ga))
#define CP_COMMIT() asm volatile("cp.async.commit_group;" ::: "memory")
#define CP_WAIT(n)  asm volatile("cp.async.wait_group %0;" :: "n"(n) : "memory")

__device__ __forceinline__ void ldsm4(uint32_t* r, uint32_t addr) {
    asm volatile("ldmatrix.sync.aligned.m8n8.x4.shared.b16 {%0,%1,%2,%3}, [%4];"
                 : "=r"(r[0]), "=r"(r[1]), "=r"(r[2]), "=r"(r[3]) : "r"(addr));
}
__device__ __forceinline__ void ldsm4t(uint32_t* r, uint32_t addr) {
    asm volatile("ldmatrix.sync.aligned.m8n8.x4.trans.shared.b16 {%0,%1,%2,%3}, [%4];"
                 : "=r"(r[0]), "=r"(r[1]), "=r"(r[2]), "=r"(r[3]) : "r"(addr));
}
__device__ __forceinline__ void mma16816(float* c, const uint32_t* a,
                                         uint32_t b0, uint32_t b1) {
    asm volatile(
        "mma.sync.aligned.m16n8k16.row.col.f32.bf16.bf16.f32 "
        "{%0,%1,%2,%3}, {%4,%5,%6,%7}, {%8,%9}, {%0,%1,%2,%3};"
        : "+f"(c[0]), "+f"(c[1]), "+f"(c[2]), "+f"(c[3])
        : "r"(a[0]), "r"(a[1]), "r"(a[2]), "r"(a[3]), "r"(b0), "r"(b1));
}
__device__ __forceinline__ void split2(float a, float b, uint32_t& hi, uint32_t& lo) {
    bf16 ha = __float2bfloat16(a), hb = __float2bfloat16(b);
    bf16 la = __float2bfloat16(a - __bfloat162float(ha));
    bf16 lb = __float2bfloat16(b - __bfloat162float(hb));
    __nv_bfloat162 h(ha, hb), l(la, lb);
    hi = *(uint32_t*)&h; lo = *(uint32_t*)&l;
}

// ============================================================
// split fp32 -> (bf16 hi, bf16 lo)
// ============================================================
__global__ void split_bf16(const float4* __restrict__ in,
                           __nv_bfloat162* __restrict__ hi,
                           __nv_bfloat162* __restrict__ lo, int n4)
{
    for (int i = blockIdx.x * blockDim.x + threadIdx.x; i < n4; i += gridDim.x * blockDim.x) {
        float4 v = in[i];
        uint32_t h0, l0, h1, l1;
        split2(v.x, v.y, h0, l0);
        split2(v.z, v.w, h1, l1);
        ((uint32_t*)hi)[2*i] = h0; ((uint32_t*)hi)[2*i+1] = h1;
        ((uint32_t*)lo)[2*i] = l0; ((uint32_t*)lo)[2*i+1] = l1;
    }
}

// ============================================================
// mma.sync GEMM (3-pass bf16 split), 3-stage cp.async pipeline.
// CTA tile 128x256, BK=32, 8 warps 2x4, warp tile 64x64.
// Region-fused: blockIdx.x selects {region = bx>>3, bn = (bx&7)*256},
// so one launch can do Q,K,V (grid.x=24) or a single GEMM (grid.x=8).
// ============================================================
#define OFF_AH 0
#define OFF_AL (128*80)
#define OFF_BH (2*128*80)
#define OFF_BL (2*128*80 + 256*80)
#define STAGE_SZ (2*128*80 + 2*256*80)   // 61440
#define GSMEM3  (3*STAGE_SZ)             // 184320

struct GemmPtrs {
    const bf16* Bh[3];
    const bf16* Bl[3];
    const float* bias[3];
    bf16* Ch[3];
    bf16* Cl[3];
    float* C[3];
};

__device__ __forceinline__ void g_load_tile(uint32_t sbase, const bf16* g,
                                            int nrows, int row0, int k0, int tid)
{
    const char* gp = (const char*)(g + (size_t)row0 * Hsz + k0);
    for (int c = tid; c < nrows * 4; c += 256) {
        int row = c >> 2, ch = c & 3;
        CP_ASYNC16(sbase + row * 80 + ch * 16, gp + (size_t)row * (Hsz * 2) + ch * 16);
    }
}
__device__ __forceinline__ void g_load_stage(uint32_t st, const bf16* Ah, const bf16* Al,
                                             const bf16* Bh, const bf16* Bl,
                                             int bm, int bn, int k0, int tid)
{
    g_load_tile(st + OFF_AH, Ah, 128, bm, k0, tid);
    g_load_tile(st + OFF_AL, Al, 128, bm, k0, tid);
    g_load_tile(st + OFF_BH, Bh, 256, bn, k0, tid);
    g_load_tile(st + OFF_BL, Bl, 256, bn, k0, tid);
}

template <bool BF16OUT>
__global__ void __launch_bounds__(256, 1)
gemm_mma3(const bf16* __restrict__ Ah, const bf16* __restrict__ Al, GemmPtrs p)
{
    extern __shared__ __align__(128) char sm[];
    const uint32_t sb = smem_u32(sm);
    const int tid  = threadIdx.x;
    const int lane = tid & 31;
    const int wid  = tid >> 5;
    const int wm   = wid >> 2;
    const int wn   = wid & 3;
    const int region = blockIdx.x >> 3;
    const int bm = blockIdx.y * 128;
    const int bn = (blockIdx.x & 7) * 256;
    const bf16* Bh = p.Bh[region];
    const bf16* Bl = p.Bl[region];

    float acc[4][8][4];
    #pragma unroll
    for (int i = 0; i < 4; i++)
        #pragma unroll
        for (int j = 0; j < 8; j++)
            #pragma unroll
            for (int t = 0; t < 4; t++) acc[i][j][t] = 0.f;

    // prologue: stages 0 and 1
    g_load_stage(sb,            Ah, Al, Bh, Bl, bm, bn, 0,  tid); CP_COMMIT();
    g_load_stage(sb + STAGE_SZ, Ah, Al, Bh, Bl, bm, bn, 32, tid); CP_COMMIT();

    const int a_row = lane & 15;
    const int a_kb  = (lane >> 4) * 16;
    const int b_row = ((lane >> 4) & 1) * 8 + (lane & 7);
    const int b_kb  = ((lane >> 3) & 1) * 16;

    int snext = 2;
    for (int kt = 0; kt < 64; kt++) {
        if (kt < 62) {
            g_load_stage(sb + snext * STAGE_SZ, Ah, Al, Bh, Bl, bm, bn, (kt + 2) * 32, tid);
            CP_COMMIT();
            CP_WAIT(2);
            snext = (snext == 2) ? 0 : snext + 1;
        } else if (kt == 62) {
            CP_WAIT(1);
        } else {
            CP_WAIT(0);
        }
        __syncthreads();

        const uint32_t st = sb + (kt % 3) * STAGE_SZ;
        #pragma unroll
        for (int kk = 0; kk < 2; kk++) {
            uint32_t ah[4][4], al[4][4];
            #pragma unroll
            for (int mi = 0; mi < 4; mi++) {
                uint32_t ra = (uint32_t)((wm * 64 + mi * 16 + a_row) * 80 + a_kb + kk * 32);
                ldsm4(ah[mi], st + OFF_AH + ra);
                ldsm4(al[mi], st + OFF_AL + ra);
            }
            #pragma unroll
            for (int half = 0; half < 2; half++) {
                uint32_t bh[2][4], bl[2][4];
                #pragma unroll
                for (int g = 0; g < 2; g++) {
                    uint32_t rb = (uint32_t)((wn * 64 + half * 32 + g * 16 + b_row) * 80
                                             + b_kb + kk * 32);
                    ldsm4(bh[g], st + OFF_BH + rb);
                    ldsm4(bl[g], st + OFF_BL + rb);
                }
                #pragma unroll
                for (int pp = 0; pp < 3; pp++) {
                    #pragma unroll
                    for (int mi = 0; mi < 4; mi++) {
                        #pragma unroll
                        for (int t = 0; t < 4; t++) {
                            const int g = t >> 1, hsel = t & 1;
                            const uint32_t* af = (pp == 2) ? al[mi] : ah[mi];
                            const uint32_t* bf = (pp == 1) ? bl[g] : bh[g];
                            mma16816(acc[mi][half * 4 + t], af, bf[hsel * 2], bf[hsel * 2 + 1]);
                        }
                    }
                }
            }
        }
        __syncthreads();
    }

    const int rbase = bm + wm * 64 + (lane >> 2);
    const int cbase = bn + wn * 64 + (lane & 3) * 2;
    const float* bias = p.bias[region];
    #pragma unroll
    for (int mi = 0; mi < 4; mi++) {
        #pragma unroll
        for (int nj = 0; nj < 8; nj++) {
            int row = rbase + mi * 16;
            int col = cbase + nj * 8;
            float b0 = __ldg(&bias[col]), b1 = __ldg(&bias[col + 1]);
            float* c = acc[mi][nj];
            float v00 = c[0] + b0, v01 = c[1] + b1;
            float v10 = c[2] + b0, v11 = c[3] + b1;
            if (BF16OUT) {
                bf16* Ch = p.Ch[region];
                bf16* Cl = p.Cl[region];
                uint32_t h, l;
                split2(v00, v01, h, l);
                *(uint32_t*)(Ch + (size_t)row * Hsz + col) = h;
                *(uint32_t*)(Cl + (size_t)row * Hsz + col) = l;
                split2(v10, v11, h, l);
                *(uint32_t*)(Ch + (size_t)(row + 8) * Hsz + col) = h;
                *(uint32_t*)(Cl + (size_t)(row + 8) * Hsz + col) = l;
            } else {
                float* C = p.C[region];
                *(float2*)(C + (size_t)row * Hsz + col) = make_float2(v00, v01);
                *(float2*)(C + (size_t)(row + 8) * Hsz + col) = make_float2(v10, v11);
            }
        }
    }
}

// ============================================================
// Flash attention via mma.sync, 3-pass split on QK and PV.
// BQ=128, BKV=64, 256 threads (8 warps x 16 query rows).
// ============================================================
#define VST 272
#define AKH 0
#define AKL (64*VST)
#define AVH (2*64*VST)
#define AVL (3*64*VST)
#define ASMEM (4*64*VST)

__device__ __forceinline__ void fa_load64(uint32_t sbase, const bf16* g, size_t gelem, int tid) {
    const char* gp = (const char*)(g + gelem);
    for (int c = tid; c < 1024; c += 256) {
        int r = c >> 4, ch = c & 15;
        CP_ASYNC16(sbase + r * VST + ch * 16, gp + (size_t)r * (Hsz * 2) + ch * 16);
    }
}
__device__ __forceinline__ void fa_load128(uint32_t sbase, const bf16* g, size_t gelem, int tid) {
    const char* gp = (const char*)(g + gelem);
    for (int c = tid; c < 2048; c += 256) {
        int r = c >> 4, ch = c & 15;
        CP_ASYNC16(sbase + r * VST + ch * 16, gp + (size_t)r * (Hsz * 2) + ch * 16);
    }
}

__global__ void __launch_bounds__(256, 1)
flash_mma(const bf16* __restrict__ Qh, const bf16* __restrict__ Ql,
          const bf16* __restrict__ Kh, const bf16* __restrict__ Kl,
          const bf16* __restrict__ Vh, const bf16* __restrict__ Vl,
          bf16* __restrict__ AOh, bf16* __restrict__ AOl)
{
    extern __shared__ __align__(128) char sm[];
    const uint32_t sb = smem_u32(sm);
    const int tid = threadIdx.x;
    const int lane = tid & 31;
    const int w = tid >> 5;
    const int wrow = w * 16;
    const int qb = blockIdx.x, h = blockIdx.y, b = blockIdx.z;
    const int q0 = qb * 128;
    const size_t baseKV = (size_t)(b * Ssz) * Hsz + h * HDIM;
    const size_t baseQ  = baseKV + (size_t)q0 * Hsz;

    const int a_row = lane & 15;
    const int a_kb  = (lane >> 4) * 16;
    const int b_row = ((lane >> 4) & 1) * 8 + (lane & 7);
    const int b_kb  = ((lane >> 3) & 1) * 16;
    const int t_row = lane & 15;
    const int t_cb  = (lane >> 4) * 16;

    uint32_t qfh[8][4], qfl[8][4];
    fa_load128(sb, Qh, baseQ, tid); CP_COMMIT(); CP_WAIT(0); __syncthreads();
    #pragma unroll
    for (int t = 0; t < 8; t++)
        ldsm4(qfh[t], sb + (uint32_t)((wrow + a_row) * VST + a_kb + t * 32));
    __syncthreads();
    fa_load128(sb, Ql, baseQ, tid); CP_COMMIT(); CP_WAIT(0); __syncthreads();
    #pragma unroll
    for (int t = 0; t < 8; t++)
        ldsm4(qfl[t], sb + (uint32_t)((wrow + a_row) * VST + a_kb + t * 32));
    __syncthreads();

    fa_load64(sb + AKH, Kh, baseKV, tid);
    fa_load64(sb + AKL, Kl, baseKV, tid);
    CP_COMMIT();

    float o[16][4];
    #pragma unroll
    for (int j = 0; j < 16; j++)
        #pragma unroll
        for (int t = 0; t < 4; t++) o[j][t] = 0.f;
    float m_i[2] = {-1e30f, -1e30f}, l_i[2] = {0.f, 0.f};

    const int ktmax = 2 * qb + 1;
    const int r0 = lane >> 2;
    const float sc = 0.08838834764831845f;

    for (int kt = 0; kt <= ktmax; kt++) {
        fa_load64(sb + AVH, Vh, baseKV + (size_t)(kt * 64) * Hsz, tid);
        fa_load64(sb + AVL, Vl, baseKV + (size_t)(kt * 64) * Hsz, tid);
        CP_COMMIT();
        CP_WAIT(1);
        __syncthreads();

        const bool active = (kt * 64 <= q0 + wrow + 15);
        float s[8][4];
        if (active) {
            #pragma unroll
            for (int j = 0; j < 8; j++)
                #pragma unroll
                for (int t = 0; t < 4; t++) s[j][t] = 0.f;
            #pragma unroll
            for (int t = 0; t < 8; t++) {
                uint32_t kbh[4][4], kbl[4][4];
                #pragma unroll
                for (int pp = 0; pp < 4; pp++) {
                    uint32_t ra = (uint32_t)((pp * 16 + b_row) * VST + b_kb + t * 32);
                    ldsm4(kbh[pp], sb + AKH + ra);
                    ldsm4(kbl[pp], sb + AKL + ra);
                }
                #pragma unroll
                for (int pp = 0; pp < 4; pp++) {
                    #pragma unroll
                    for (int hh = 0; hh < 2; hh++) {
                        mma16816(s[2*pp+hh], qfh[t], kbh[pp][hh*2], kbh[pp][hh*2+1]);
                        mma16816(s[2*pp+hh], qfh[t], kbl[pp][hh*2], kbl[pp][hh*2+1]);
                        mma16816(s[2*pp+hh], qfl[t], kbh[pp][hh*2], kbh[pp][hh*2+1]);
                    }
                }
            }
        }
        __syncthreads();

        const bool more = kt < ktmax;
        if (more) {
            fa_load64(sb + AKH, Kh, baseKV + (size_t)((kt + 1) * 64) * Hsz, tid);
            fa_load64(sb + AKL, Kl, baseKV + (size_t)((kt + 1) * 64) * Hsz, tid);
            CP_COMMIT();
        }

        uint32_t pah[4][4], pal[4][4];
        float fac[2];
        if (active) {
            #pragma unroll
            for (int j = 0; j < 8; j++)
                #pragma unroll
                for (int t = 0; t < 4; t++) s[j][t] *= sc;
            if (kt * 64 + 63 > q0 + wrow) {
                #pragma unroll
                for (int j = 0; j < 8; j++) {
                    int col = kt * 64 + j * 8 + (lane & 3) * 2;
                    int row = q0 + wrow + r0;
                    if (col > row)          s[j][0] = -1e30f;
                    if (col + 1 > row)      s[j][1] = -1e30f;
                    if (col > row + 8)      s[j][2] = -1e30f;
                    if (col + 1 > row + 8)  s[j][3] = -1e30f;
                }
            }
            #pragma unroll
            for (int r = 0; r < 2; r++) {
                float rm = -1e30f;
                #pragma unroll
                for (int j = 0; j < 8; j++) rm = fmaxf(rm, fmaxf(s[j][r*2], s[j][r*2+1]));
                rm = fmaxf(rm, __shfl_xor_sync(0xffffffffu, rm, 1));
                rm = fmaxf(rm, __shfl_xor_sync(0xffffffffu, rm, 2));
                float mn = fmaxf(m_i[r], rm);
                fac[r] = __expf(m_i[r] - mn);
                float rs = 0.f;
                #pragma unroll
                for (int j = 0; j < 8; j++) {
                    s[j][r*2]   = __expf(s[j][r*2]   - mn);
                    s[j][r*2+1] = __expf(s[j][r*2+1] - mn);
                    rs += s[j][r*2] + s[j][r*2+1];
                }
                rs += __shfl_xor_sync(0xffffffffu, rs, 1);
                rs += __shfl_xor_sync(0xffffffffu, rs, 2);
                l_i[r] = l_i[r] * fac[r] + rs;
                m_i[r] = mn;
            }
            #pragma unroll
            for (int t2 = 0; t2 < 4; t2++) {
                split2(s[2*t2][0],   s[2*t2][1],   pah[t2][0], pal[t2][0]);
                split2(s[2*t2][2],   s[2*t2][3],   pah[t2][1], pal[t2][1]);
                split2(s[2*t2+1][0], s[2*t2+1][1], pah[t2][2], pal[t2][2]);
                split2(s[2*t2+1][2], s[2*t2+1][3], pah[t2][3], pal[t2][3]);
            }
            #pragma unroll
            for (int j = 0; j < 16; j++) {
                o[j][0] *= fac[0]; o[j][1] *= fac[0];
                o[j][2] *= fac[1]; o[j][3] *= fac[1];
            }
        }

        if (more) { CP_WAIT(1); } else { CP_WAIT(0); }
        __syncthreads();

        if (active) {
            #pragma unroll
            for (int j2 = 0; j2 < 8; j2++) {
                #pragma unroll
                for (int t = 0; t < 4; t++) {
                    uint32_t bvh[4], bvl[4];
                    uint32_t ra = (uint32_t)((t * 16 + t_row) * VST + t_cb + j2 * 32);
                    ldsm4t(bvh, sb + AVH + ra);
                    ldsm4t(bvl, sb + AVL + ra);
                    mma16816(o[2*j2],   pah[t], bvh[0], bvh[1]);
                    mma16816(o[2*j2+1], pah[t], bvh[2], bvh[3]);
                    mma16816(o[2*j2],   pah[t], bvl[0], bvl[1]);
                    mma16816(o[2*j2+1], pah[t], bvl[2], bvl[3]);
                    mma16816(o[2*j2],   pal[t], bvh[0], bvh[1]);
                    mma16816(o[2*j2+1], pal[t], bvh[2], bvh[3]);
                }
            }
        }
        __syncthreads();
    }

    const float inv0 = 1.0f / l_i[0], inv1 = 1.0f / l_i[1];
    const int grow0 = q0 + wrow + r0;
    #pragma unroll
    for (int j = 0; j < 16; j++) {
        int col = j * 8 + (lane & 3) * 2;
        size_t e0 = baseKV + (size_t)grow0 * Hsz + col;
        size_t e1 = baseKV + (size_t)(grow0 + 8) * Hsz + col;
        uint32_t hh, ll;
        split2(o[j][0] * inv0, o[j][1] * inv0, hh, ll);
        *(uint32_t*)(AOh + e0) = hh; *(uint32_t*)(AOl + e0) = ll;
        split2(o[j][2] * inv1, o[j][3] * inv1, hh, ll);
        *(uint32_t*)(AOh + e1) = hh; *(uint32_t*)(AOl + e1) = ll;
    }
}

// ============================================================
extern "C" void kernel_launch(void* const* d_in, const int* in_sizes, int n_in,
                              void* d_out, int out_size) {
    const float* x  = (const float*)d_in[0];
    const float* Wf[4] = { (const float*)d_in[1], (const float*)d_in[3],
                           (const float*)d_in[5], (const float*)d_in[7] };
    const float* bQ = (const float*)d_in[2];
    const float* bK = (const float*)d_in[4];
    const float* bV = (const float*)d_in[6];
    const float* bO = (const float*)d_in[8];
    float* out = (float*)d_out;

    bf16 *xh, *xl, *qh, *ql, *kh, *kl, *vh, *vl, *aoh, *aol, *wh, *wl;
    cudaGetSymbolAddress((void**)&xh,  g_xh);  cudaGetSymbolAddress((void**)&xl,  g_xl);
    cudaGetSymbolAddress((void**)&qh,  g_qh);  cudaGetSymbolAddress((void**)&ql,  g_ql);
    cudaGetSymbolAddress((void**)&kh,  g_kh);  cudaGetSymbolAddress((void**)&kl,  g_kl);
    cudaGetSymbolAddress((void**)&vh,  g_vh);  cudaGetSymbolAddress((void**)&vl,  g_vl);
    cudaGetSymbolAddress((void**)&aoh, g_aoh); cudaGetSymbolAddress((void**)&aol, g_aol);
    cudaGetSymbolAddress((void**)&wh,  g_wh);  cudaGetSymbolAddress((void**)&wl,  g_wl);

    const size_t HH = (size_t)Hsz * Hsz;

    // launches 1..5 (splits) — launch 6 is the fused QKV GEMM (ncu -s 5 captures it)
    split_bf16<<<2048, 256>>>((const float4*)x, (__nv_bfloat162*)xh,
                              (__nv_bfloat162*)xl, Mrows * Hsz / 4);
    for (int i = 0; i < 4; i++)
        split_bf16<<<2048, 256>>>((const float4*)Wf[i],
                                  (__nv_bfloat162*)(wh + i * HH),
                                  (__nv_bfloat162*)(wl + i * HH),
                                  Hsz * Hsz / 4);

    cudaFuncSetAttribute(gemm_mma3<true>,  cudaFuncAttributeMaxDynamicSharedMemorySize, GSMEM3);
    cudaFuncSetAttribute(gemm_mma3<false>, cudaFuncAttributeMaxDynamicSharedMemorySize, GSMEM3);

    GemmPtrs pq;
    pq.Bh[0] = wh;          pq.Bh[1] = wh + HH;     pq.Bh[2] = wh + 2 * HH;
    pq.Bl[0] = wl;          pq.Bl[1] = wl + HH;     pq.Bl[2] = wl + 2 * HH;
    pq.bias[0] = bQ;        pq.bias[1] = bK;        pq.bias[2] = bV;
    pq.Ch[0] = qh;          pq.Ch[1] = kh;          pq.Ch[2] = vh;
    pq.Cl[0] = ql;          pq.Cl[1] = kl;          pq.Cl[2] = vl;
    pq.C[0] = pq.C[1] = pq.C[2] = nullptr;
    gemm_mma3<true><<<dim3(24, Mrows / 128), 256, GSMEM3>>>(xh, xl, pq);

    cudaFuncSetAttribute(flash_mma, cudaFuncAttributeMaxDynamicSharedMemorySize, ASMEM);
    flash_mma<<<dim3(Ssz / 128, NHEAD, Bsz), 256, ASMEM>>>(qh, ql, kh, kl, vh, vl, aoh, aol);

    GemmPtrs po;
    po.Bh[0] = wh + 3 * HH; po.Bh[1] = po.Bh[2] = nullptr;
    po.Bl[0] = wl + 3 * HH; po.Bl[1] = po.Bl[2] = nullptr;
    po.bias[0] = bO;        po.bias[1] = po.bias[2] = nullptr;
    po.Ch[0] = po.Ch[1] = po.Ch[2] = nullptr;
    po.Cl[0] = po.Cl[1] = po.Cl[2] = nullptr;
    po.C[0] = out;          po.C[1] = po.C[2] = nullptr;
    gemm_mma3<false><<<dim3(8, Mrows / 128), 256, GSMEM3>>>(aoh, aol, po);
}

// round 6
// speedup vs baseline: 1.1076x; 1.1076x over previous
#include <cuda_runtime.h>
#include <cuda_bf16.h>
#include <cstdint>

// Problem dims
#define Bsz   2
#define Ssz   2048
#define Hsz   2048
#define NHEAD 16
#define HDIM  128
#define Mrows (Bsz*Ssz)   // 4096

typedef __nv_bfloat16 bf16;

// ---------------- scratch (static device globals) ----------------
__device__ bf16 g_xh [Mrows*Hsz], g_xl [Mrows*Hsz];
__device__ bf16 g_qh [Mrows*Hsz], g_ql [Mrows*Hsz];
__device__ bf16 g_kh [Mrows*Hsz], g_kl [Mrows*Hsz];
__device__ bf16 g_vh [Mrows*Hsz], g_vl [Mrows*Hsz];
__device__ bf16 g_aoh[Mrows*Hsz], g_aol[Mrows*Hsz];
__device__ bf16 g_wh [4][Hsz*Hsz], g_wl [4][Hsz*Hsz];

// ---------------- helpers ----------------
__device__ __forceinline__ uint32_t smem_u32(const void* p) {
    uint32_t a;
    asm("{ .reg .u64 t; cvta.to.shared.u64 t, %1; cvt.u32.u64 %0, t; }" : "=r"(a) : "l"(p));
    return a;
}
#define CP_ASYNC16(sa, ga) \
    asm volatile("cp.async.cg.shared.global [%0], [%1], 16;" :: "r"((uint32_t)(sa)), "l"(ga))
#define CP_COMMIT() asm volatile("cp.async.commit_group;" ::: "memory")
#define CP_WAIT(n)  asm volatile("cp.async.wait_group %0;" :: "n"(n) : "memory")

__device__ __forceinline__ void ldsm4(uint32_t* r, uint32_t addr) {
    asm volatile("ldmatrix.sync.aligned.m8n8.x4.shared.b16 {%0,%1,%2,%3}, [%4];"
                 : "=r"(r[0]), "=r"(r[1]), "=r"(r[2]), "=r"(r[3]) : "r"(addr));
}
__device__ __forceinline__ void ldsm4t(uint32_t* r, uint32_t addr) {
    asm volatile("ldmatrix.sync.aligned.m8n8.x4.trans.shared.b16 {%0,%1,%2,%3}, [%4];"
                 : "=r"(r[0]), "=r"(r[1]), "=r"(r[2]), "=r"(r[3]) : "r"(addr));
}
__device__ __forceinline__ void mma16816(float* c, const uint32_t* a,
                                         uint32_t b0, uint32_t b1) {
    asm volatile(
        "mma.sync.aligned.m16n8k16.row.col.f32.bf16.bf16.f32 "
        "{%0,%1,%2,%3}, {%4,%5,%6,%7}, {%8,%9}, {%0,%1,%2,%3};"
        : "+f"(c[0]), "+f"(c[1]), "+f"(c[2]), "+f"(c[3])
        : "r"(a[0]), "r"(a[1]), "r"(a[2]), "r"(a[3]), "r"(b0), "r"(b1));
}
__device__ __forceinline__ void split2(float a, float b, uint32_t& hi, uint32_t& lo) {
    bf16 ha = __float2bfloat16(a), hb = __float2bfloat16(b);
    bf16 la = __float2bfloat16(a - __bfloat162float(ha));
    bf16 lb = __float2bfloat16(b - __bfloat162float(hb));
    __nv_bfloat162 h(ha, hb), l(la, lb);
    hi = *(uint32_t*)&h; lo = *(uint32_t*)&l;
}

// ============================================================
// Fused split: fp32 -> (bf16 hi, bf16 lo) for all 5 input tensors
// ============================================================
struct SplitJobs {
    const float4* in[5];
    __nv_bfloat162* hi[5];
    __nv_bfloat162* lo[5];
    int n4[5];
    int blk0[5];   // first block of each region; region r spans [blk0[r], blk0[r+1])
};

__global__ void split_bf16_multi(SplitJobs j, int totblk)
{
    int r = 0;
    #pragma unroll
    for (int i = 1; i < 5; i++) if ((int)blockIdx.x >= j.blk0[i]) r = i;
    const int rel  = blockIdx.x - j.blk0[r];
    const int nblk = ((r + 1 < 5) ? j.blk0[r + 1] : totblk) - j.blk0[r];
    const float4* in = j.in[r];
    uint32_t* hi = (uint32_t*)j.hi[r];
    uint32_t* lo = (uint32_t*)j.lo[r];
    const int n4 = j.n4[r];
    for (int i = rel * blockDim.x + threadIdx.x; i < n4; i += nblk * blockDim.x) {
        float4 v = in[i];
        uint32_t h0, l0, h1, l1;
        split2(v.x, v.y, h0, l0);
        split2(v.z, v.w, h1, l1);
        hi[2*i] = h0; hi[2*i+1] = h1;
        lo[2*i] = l0; lo[2*i+1] = l1;
    }
}

// ============================================================
// mma.sync GEMM (3-pass bf16 split), CTA tile 128x128, BK=32,
// 2-stage cp.async, 2 CTAs/SM. 8 warps 2(m)x4(n), warp tile 64x32.
// Region-fused via blockIdx.x: region = bx>>4, bn = (bx&15)*128.
// ============================================================
#define OFF_AH 0
#define OFF_AL (128*80)          // 10240
#define OFF_BH (2*128*80)        // 20480
#define OFF_BL (3*128*80)        // 30720
#define STAGE_SZ (4*128*80)      // 40960
#define GSMEM2  (2*STAGE_SZ)     // 81920

struct GemmPtrs {
    const bf16* Bh[3];
    const bf16* Bl[3];
    const float* bias[3];
    bf16* Ch[3];
    bf16* Cl[3];
    float* C[3];
};

__device__ __forceinline__ void g_load_tile(uint32_t sbase, const bf16* g,
                                            int row0, int k0, int tid)
{
    const char* gp = (const char*)(g + (size_t)row0 * Hsz + k0);
    for (int c = tid; c < 512; c += 256) {
        int row = c >> 2, ch = c & 3;
        CP_ASYNC16(sbase + row * 80 + ch * 16, gp + (size_t)row * (Hsz * 2) + ch * 16);
    }
}
__device__ __forceinline__ void g_load_stage(uint32_t st, const bf16* Ah, const bf16* Al,
                                             const bf16* Bh, const bf16* Bl,
                                             int bm, int bn, int k0, int tid)
{
    g_load_tile(st + OFF_AH, Ah, bm, k0, tid);
    g_load_tile(st + OFF_AL, Al, bm, k0, tid);
    g_load_tile(st + OFF_BH, Bh, bn, k0, tid);
    g_load_tile(st + OFF_BL, Bl, bn, k0, tid);
}

template <bool BF16OUT>
__global__ void __launch_bounds__(256, 2)
gemm_mma3(const bf16* __restrict__ Ah, const bf16* __restrict__ Al, GemmPtrs p)
{
    extern __shared__ __align__(128) char sm[];
    const uint32_t sb = smem_u32(sm);
    const int tid  = threadIdx.x;
    const int lane = tid & 31;
    const int wid  = tid >> 5;
    const int wm   = wid >> 2;        // 0..1
    const int wn   = wid & 3;         // 0..3
    const int region = blockIdx.x >> 4;
    const int bm = blockIdx.y * 128;
    const int bn = (blockIdx.x & 15) * 128;
    const bf16* Bh = p.Bh[region];
    const bf16* Bl = p.Bl[region];

    float acc[4][4][4];
    #pragma unroll
    for (int i = 0; i < 4; i++)
        #pragma unroll
        for (int j = 0; j < 4; j++)
            #pragma unroll
            for (int t = 0; t < 4; t++) acc[i][j][t] = 0.f;

    g_load_stage(sb, Ah, Al, Bh, Bl, bm, bn, 0, tid);
    CP_COMMIT();

    const int a_row = lane & 15;
    const int a_kb  = (lane >> 4) * 16;
    const int b_row = ((lane >> 4) & 1) * 8 + (lane & 7);
    const int b_kb  = ((lane >> 3) & 1) * 16;

    for (int kt = 0; kt < 64; kt++) {
        const int s = kt & 1;
        if (kt + 1 < 64) {
            g_load_stage(sb + (s ^ 1) * STAGE_SZ, Ah, Al, Bh, Bl, bm, bn, (kt + 1) * 32, tid);
            CP_COMMIT();
            CP_WAIT(1);
        } else {
            CP_WAIT(0);
        }
        __syncthreads();

        const uint32_t st = sb + s * STAGE_SZ;
        #pragma unroll
        for (int kk = 0; kk < 2; kk++) {
            uint32_t ah[4][4], al[4][4];
            #pragma unroll
            for (int mi = 0; mi < 4; mi++) {
                uint32_t ra = (uint32_t)((wm * 64 + mi * 16 + a_row) * 80 + a_kb + kk * 32);
                ldsm4(ah[mi], st + OFF_AH + ra);
                ldsm4(al[mi], st + OFF_AL + ra);
            }
            uint32_t bh[2][4], bl[2][4];
            #pragma unroll
            for (int g = 0; g < 2; g++) {
                uint32_t rb = (uint32_t)((wn * 32 + g * 16 + b_row) * 80 + b_kb + kk * 32);
                ldsm4(bh[g], st + OFF_BH + rb);
                ldsm4(bl[g], st + OFF_BL + rb);
            }
            #pragma unroll
            for (int pp = 0; pp < 3; pp++) {
                #pragma unroll
                for (int mi = 0; mi < 4; mi++) {
                    #pragma unroll
                    for (int t = 0; t < 4; t++) {
                        const int g = t >> 1, hsel = t & 1;
                        const uint32_t* af = (pp == 2) ? al[mi] : ah[mi];
                        const uint32_t* bf = (pp == 1) ? bl[g] : bh[g];
                        mma16816(acc[mi][t], af, bf[hsel * 2], bf[hsel * 2 + 1]);
                    }
                }
            }
        }
        __syncthreads();
    }

    const int rbase = bm + wm * 64 + (lane >> 2);
    const int cbase = bn + wn * 32 + (lane & 3) * 2;
    const float* bias = p.bias[region];
    #pragma unroll
    for (int mi = 0; mi < 4; mi++) {
        #pragma unroll
        for (int nj = 0; nj < 4; nj++) {
            int row = rbase + mi * 16;
            int col = cbase + (nj >> 1) * 16 + (nj & 1) * 8;
            float b0 = __ldg(&bias[col]), b1 = __ldg(&bias[col + 1]);
            float* c = acc[mi][nj];
            float v00 = c[0] + b0, v01 = c[1] + b1;
            float v10 = c[2] + b0, v11 = c[3] + b1;
            if (BF16OUT) {
                bf16* Ch = p.Ch[region];
                bf16* Cl = p.Cl[region];
                uint32_t h, l;
                split2(v00, v01, h, l);
                *(uint32_t*)(Ch + (size_t)row * Hsz + col) = h;
                *(uint32_t*)(Cl + (size_t)row * Hsz + col) = l;
                split2(v10, v11, h, l);
                *(uint32_t*)(Ch + (size_t)(row + 8) * Hsz + col) = h;
                *(uint32_t*)(Cl + (size_t)(row + 8) * Hsz + col) = l;
            } else {
                float* C = p.C[region];
                *(float2*)(C + (size_t)row * Hsz + col) = make_float2(v00, v01);
                *(float2*)(C + (size_t)(row + 8) * Hsz + col) = make_float2(v10, v11);
            }
        }
    }
}

// ============================================================
// Flash attention via mma.sync, 3-pass split on QK and PV.
// BQ=128, BKV=64, 256 threads (8 warps x 16 query rows).
// ============================================================
#define VST 272
#define AKH 0
#define AKL (64*VST)
#define AVH (2*64*VST)
#define AVL (3*64*VST)
#define ASMEM (4*64*VST)

__device__ __forceinline__ void fa_load64(uint32_t sbase, const bf16* g, size_t gelem, int tid) {
    const char* gp = (const char*)(g + gelem);
    for (int c = tid; c < 1024; c += 256) {
        int r = c >> 4, ch = c & 15;
        CP_ASYNC16(sbase + r * VST + ch * 16, gp + (size_t)r * (Hsz * 2) + ch * 16);
    }
}
__device__ __forceinline__ void fa_load128(uint32_t sbase, const bf16* g, size_t gelem, int tid) {
    const char* gp = (const char*)(g + gelem);
    for (int c = tid; c < 2048; c += 256) {
        int r = c >> 4, ch = c & 15;
        CP_ASYNC16(sbase + r * VST + ch * 16, gp + (size_t)r * (Hsz * 2) + ch * 16);
    }
}

__global__ void __launch_bounds__(256, 1)
flash_mma(const bf16* __restrict__ Qh, const bf16* __restrict__ Ql,
          const bf16* __restrict__ Kh, const bf16* __restrict__ Kl,
          const bf16* __restrict__ Vh, const bf16* __restrict__ Vl,
          bf16* __restrict__ AOh, bf16* __restrict__ AOl)
{
    extern __shared__ __align__(128) char sm[];
    const uint32_t sb = smem_u32(sm);
    const int tid = threadIdx.x;
    const int lane = tid & 31;
    const int w = tid >> 5;
    const int wrow = w * 16;
    const int qb = blockIdx.x, h = blockIdx.y, b = blockIdx.z;
    const int q0 = qb * 128;
    const size_t baseKV = (size_t)(b * Ssz) * Hsz + h * HDIM;
    const size_t baseQ  = baseKV + (size_t)q0 * Hsz;

    const int a_row = lane & 15;
    const int a_kb  = (lane >> 4) * 16;
    const int b_row = ((lane >> 4) & 1) * 8 + (lane & 7);
    const int b_kb  = ((lane >> 3) & 1) * 16;
    const int t_row = lane & 15;
    const int t_cb  = (lane >> 4) * 16;

    uint32_t qfh[8][4], qfl[8][4];
    fa_load128(sb, Qh, baseQ, tid); CP_COMMIT(); CP_WAIT(0); __syncthreads();
    #pragma unroll
    for (int t = 0; t < 8; t++)
        ldsm4(qfh[t], sb + (uint32_t)((wrow + a_row) * VST + a_kb + t * 32));
    __syncthreads();
    fa_load128(sb, Ql, baseQ, tid); CP_COMMIT(); CP_WAIT(0); __syncthreads();
    #pragma unroll
    for (int t = 0; t < 8; t++)
        ldsm4(qfl[t], sb + (uint32_t)((wrow + a_row) * VST + a_kb + t * 32));
    __syncthreads();

    fa_load64(sb + AKH, Kh, baseKV, tid);
    fa_load64(sb + AKL, Kl, baseKV, tid);
    CP_COMMIT();

    float o[16][4];
    #pragma unroll
    for (int j = 0; j < 16; j++)
        #pragma unroll
        for (int t = 0; t < 4; t++) o[j][t] = 0.f;
    float m_i[2] = {-1e30f, -1e30f}, l_i[2] = {0.f, 0.f};

    const int ktmax = 2 * qb + 1;
    const int r0 = lane >> 2;
    const float sc = 0.08838834764831845f;

    for (int kt = 0; kt <= ktmax; kt++) {
        fa_load64(sb + AVH, Vh, baseKV + (size_t)(kt * 64) * Hsz, tid);
        fa_load64(sb + AVL, Vl, baseKV + (size_t)(kt * 64) * Hsz, tid);
        CP_COMMIT();
        CP_WAIT(1);
        __syncthreads();

        const bool active = (kt * 64 <= q0 + wrow + 15);
        float s[8][4];
        if (active) {
            #pragma unroll
            for (int j = 0; j < 8; j++)
                #pragma unroll
                for (int t = 0; t < 4; t++) s[j][t] = 0.f;
            #pragma unroll
            for (int t = 0; t < 8; t++) {
                uint32_t kbh[4][4], kbl[4][4];
                #pragma unroll
                for (int pp = 0; pp < 4; pp++) {
                    uint32_t ra = (uint32_t)((pp * 16 + b_row) * VST + b_kb + t * 32);
                    ldsm4(kbh[pp], sb + AKH + ra);
                    ldsm4(kbl[pp], sb + AKL + ra);
                }
                #pragma unroll
                for (int pp = 0; pp < 4; pp++) {
                    #pragma unroll
                    for (int hh = 0; hh < 2; hh++) {
                        mma16816(s[2*pp+hh], qfh[t], kbh[pp][hh*2], kbh[pp][hh*2+1]);
                        mma16816(s[2*pp+hh], qfh[t], kbl[pp][hh*2], kbl[pp][hh*2+1]);
                        mma16816(s[2*pp+hh], qfl[t], kbh[pp][hh*2], kbh[pp][hh*2+1]);
                    }
                }
            }
        }
        __syncthreads();

        const bool more = kt < ktmax;
        if (more) {
            fa_load64(sb + AKH, Kh, baseKV + (size_t)((kt + 1) * 64) * Hsz, tid);
            fa_load64(sb + AKL, Kl, baseKV + (size_t)((kt + 1) * 64) * Hsz, tid);
            CP_COMMIT();
        }

        uint32_t pah[4][4], pal[4][4];
        float fac[2];
        if (active) {
            #pragma unroll
            for (int j = 0; j < 8; j++)
                #pragma unroll
                for (int t = 0; t < 4; t++) s[j][t] *= sc;
            if (kt * 64 + 63 > q0 + wrow) {
                #pragma unroll
                for (int j = 0; j < 8; j++) {
                    int col = kt * 64 + j * 8 + (lane & 3) * 2;
                    int row = q0 + wrow + r0;
                    if (col > row)          s[j][0] = -1e30f;
                    if (col + 1 > row)      s[j][1] = -1e30f;
                    if (col > row + 8)      s[j][2] = -1e30f;
                    if (col + 1 > row + 8)  s[j][3] = -1e30f;
                }
            }
            #pragma unroll
            for (int r = 0; r < 2; r++) {
                float rm = -1e30f;
                #pragma unroll
                for (int j = 0; j < 8; j++) rm = fmaxf(rm, fmaxf(s[j][r*2], s[j][r*2+1]));
                rm = fmaxf(rm, __shfl_xor_sync(0xffffffffu, rm, 1));
                rm = fmaxf(rm, __shfl_xor_sync(0xffffffffu, rm, 2));
                float mn = fmaxf(m_i[r], rm);
                fac[r] = __expf(m_i[r] - mn);
                float rs = 0.f;
                #pragma unroll
                for (int j = 0; j < 8; j++) {
                    s[j][r*2]   = __expf(s[j][r*2]   - mn);
                    s[j][r*2+1] = __expf(s[j][r*2+1] - mn);
                    rs += s[j][r*2] + s[j][r*2+1];
                }
                rs += __shfl_xor_sync(0xffffffffu, rs, 1);
                rs += __shfl_xor_sync(0xffffffffu, rs, 2);
                l_i[r] = l_i[r] * fac[r] + rs;
                m_i[r] = mn;
            }
            #pragma unroll
            for (int t2 = 0; t2 < 4; t2++) {
                split2(s[2*t2][0],   s[2*t2][1],   pah[t2][0], pal[t2][0]);
                split2(s[2*t2][2],   s[2*t2][3],   pah[t2][1], pal[t2][1]);
                split2(s[2*t2+1][0], s[2*t2+1][1], pah[t2][2], pal[t2][2]);
                split2(s[2*t2+1][2], s[2*t2+1][3], pah[t2][3], pal[t2][3]);
            }
            #pragma unroll
            for (int j = 0; j < 16; j++) {
                o[j][0] *= fac[0]; o[j][1] *= fac[0];
                o[j][2] *= fac[1]; o[j][3] *= fac[1];
            }
        }

        if (more) { CP_WAIT(1); } else { CP_WAIT(0); }
        __syncthreads();

        if (active) {
            #pragma unroll
            for (int j2 = 0; j2 < 8; j2++) {
                #pragma unroll
                for (int t = 0; t < 4; t++) {
                    uint32_t bvh[4], bvl[4];
                    uint32_t ra = (uint32_t)((t * 16 + t_row) * VST + t_cb + j2 * 32);
                    ldsm4t(bvh, sb + AVH + ra);
                    ldsm4t(bvl, sb + AVL + ra);
                    mma16816(o[2*j2],   pah[t], bvh[0], bvh[1]);
                    mma16816(o[2*j2+1], pah[t], bvh[2], bvh[3]);
                    mma16816(o[2*j2],   pah[t], bvl[0], bvl[1]);
                    mma16816(o[2*j2+1], pah[t], bvl[2], bvl[3]);
                    mma16816(o[2*j2],   pal[t], bvh[0], bvh[1]);
                    mma16816(o[2*j2+1], pal[t], bvh[2], bvh[3]);
                }
            }
        }
        __syncthreads();
    }

    const float inv0 = 1.0f / l_i[0], inv1 = 1.0f / l_i[1];
    const int grow0 = q0 + wrow + r0;
    #pragma unroll
    for (int j = 0; j < 16; j++) {
        int col = j * 8 + (lane & 3) * 2;
        size_t e0 = baseKV + (size_t)grow0 * Hsz + col;
        size_t e1 = baseKV + (size_t)(grow0 + 8) * Hsz + col;
        uint32_t hh, ll;
        split2(o[j][0] * inv0, o[j][1] * inv0, hh, ll);
        *(uint32_t*)(AOh + e0) = hh; *(uint32_t*)(AOl + e0) = ll;
        split2(o[j][2] * inv1, o[j][3] * inv1, hh, ll);
        *(uint32_t*)(AOh + e1) = hh; *(uint32_t*)(AOl + e1) = ll;
    }
}

// ============================================================
extern "C" void kernel_launch(void* const* d_in, const int* in_sizes, int n_in,
                              void* d_out, int out_size) {
    const float* x  = (const float*)d_in[0];
    const float* Wf[4] = { (const float*)d_in[1], (const float*)d_in[3],
                           (const float*)d_in[5], (const float*)d_in[7] };
    const float* bQ = (const float*)d_in[2];
    const float* bK = (const float*)d_in[4];
    const float* bV = (const float*)d_in[6];
    const float* bO = (const float*)d_in[8];
    float* out = (float*)d_out;

    bf16 *xh, *xl, *qh, *ql, *kh, *kl, *vh, *vl, *aoh, *aol, *wh, *wl;
    cudaGetSymbolAddress((void**)&xh,  g_xh);  cudaGetSymbolAddress((void**)&xl,  g_xl);
    cudaGetSymbolAddress((void**)&qh,  g_qh);  cudaGetSymbolAddress((void**)&ql,  g_ql);
    cudaGetSymbolAddress((void**)&kh,  g_kh);  cudaGetSymbolAddress((void**)&kl,  g_kl);
    cudaGetSymbolAddress((void**)&vh,  g_vh);  cudaGetSymbolAddress((void**)&vl,  g_vl);
    cudaGetSymbolAddress((void**)&aoh, g_aoh); cudaGetSymbolAddress((void**)&aol, g_aol);
    cudaGetSymbolAddress((void**)&wh,  g_wh);  cudaGetSymbolAddress((void**)&wl,  g_wl);

    const size_t HH = (size_t)Hsz * Hsz;

    // Launch 1: fused split (x + 4 weights)
    SplitJobs sj;
    sj.in[0] = (const float4*)x;
    sj.hi[0] = (__nv_bfloat162*)xh; sj.lo[0] = (__nv_bfloat162*)xl;
    sj.n4[0] = Mrows * Hsz / 4;     sj.blk0[0] = 0;
    for (int i = 0; i < 4; i++) {
        sj.in[i+1] = (const float4*)Wf[i];
        sj.hi[i+1] = (__nv_bfloat162*)(wh + i * HH);
        sj.lo[i+1] = (__nv_bfloat162*)(wl + i * HH);
        sj.n4[i+1] = Hsz * Hsz / 4;
        sj.blk0[i+1] = 768 + i * 384;
    }
    const int totblk = 768 + 4 * 384;   // 2304
    split_bf16_multi<<<totblk, 256>>>(sj, totblk);

    cudaFuncSetAttribute(gemm_mma3<true>,  cudaFuncAttributeMaxDynamicSharedMemorySize, GSMEM2);
    cudaFuncSetAttribute(gemm_mma3<false>, cudaFuncAttributeMaxDynamicSharedMemorySize, GSMEM2);

    // Launch 2: fused QKV GEMM (regions 0..2, 16 col-blocks each)
    GemmPtrs pq;
    pq.Bh[0] = wh;          pq.Bh[1] = wh + HH;     pq.Bh[2] = wh + 2 * HH;
    pq.Bl[0] = wl;          pq.Bl[1] = wl + HH;     pq.Bl[2] = wl + 2 * HH;
    pq.bias[0] = bQ;        pq.bias[1] = bK;        pq.bias[2] = bV;
    pq.Ch[0] = qh;          pq.Ch[1] = kh;          pq.Ch[2] = vh;
    pq.Cl[0] = ql;          pq.Cl[1] = kl;          pq.Cl[2] = vl;
    pq.C[0] = pq.C[1] = pq.C[2] = nullptr;
    gemm_mma3<true><<<dim3(48, Mrows / 128), 256, GSMEM2>>>(xh, xl, pq);

    // Launch 3: attention
    cudaFuncSetAttribute(flash_mma, cudaFuncAttributeMaxDynamicSharedMemorySize, ASMEM);
    flash_mma<<<dim3(Ssz / 128, NHEAD, Bsz), 256, ASMEM>>>(qh, ql, kh, kl, vh, vl, aoh, aol);

    // Launch 4: output projection
    GemmPtrs po;
    po.Bh[0] = wh + 3 * HH; po.Bh[1] = po.Bh[2] = nullptr;
    po.Bl[0] = wl + 3 * HH; po.Bl[1] = po.Bl[2] = nullptr;
    po.bias[0] = bO;        po.bias[1] = po.bias[2] = nullptr;
    po.Ch[0] = po.Ch[1] = po.Ch[2] = nullptr;
    po.Cl[0] = po.Cl[1] = po.Cl[2] = nullptr;
    po.C[0] = out;          po.C[1] = po.C[2] = nullptr;
    gemm_mma3<false><<<dim3(16, Mrows / 128), 256, GSMEM2>>>(aoh, aol, po);
}

// round 7
// speedup vs baseline: 1.1917x; 1.0759x over previous
#include <cuda_runtime.h>
#include <cuda_bf16.h>
#include <cstdint>

// Problem dims
#define Bsz   2
#define Ssz   2048
#define Hsz   2048
#define NHEAD 16
#define HDIM  128
#define Mrows (Bsz*Ssz)   // 4096

typedef __nv_bfloat16 bf16;

// ---------------- scratch (static device globals) ----------------
__device__ bf16 g_xh [Mrows*Hsz], g_xl [Mrows*Hsz];
__device__ bf16 g_qh [Mrows*Hsz], g_ql [Mrows*Hsz];
__device__ bf16 g_kh [Mrows*Hsz], g_kl [Mrows*Hsz];
__device__ bf16 g_vh [Mrows*Hsz], g_vl [Mrows*Hsz];
__device__ bf16 g_aoh[Mrows*Hsz], g_aol[Mrows*Hsz];
__device__ bf16 g_wh [4][Hsz*Hsz], g_wl [4][Hsz*Hsz];

// ---------------- helpers ----------------
__device__ __forceinline__ uint32_t smem_u32(const void* p) {
    uint32_t a;
    asm("{ .reg .u64 t; cvta.to.shared.u64 t, %1; cvt.u32.u64 %0, t; }" : "=r"(a) : "l"(p));
    return a;
}
#define CP_ASYNC16(sa, ga) \
    asm volatile("cp.async.cg.shared.global [%0], [%1], 16;" :: "r"((uint32_t)(sa)), "l"(ga))
#define CP_COMMIT() asm volatile("cp.async.commit_group;" ::: "memory")
#define CP_WAIT(n)  asm volatile("cp.async.wait_group %0;" :: "n"(n) : "memory")

__device__ __forceinline__ void ldsm4(uint32_t* r, uint32_t addr) {
    asm volatile("ldmatrix.sync.aligned.m8n8.x4.shared.b16 {%0,%1,%2,%3}, [%4];"
                 : "=r"(r[0]), "=r"(r[1]), "=r"(r[2]), "=r"(r[3]) : "r"(addr));
}
__device__ __forceinline__ void ldsm4t(uint32_t* r, uint32_t addr) {
    asm volatile("ldmatrix.sync.aligned.m8n8.x4.trans.shared.b16 {%0,%1,%2,%3}, [%4];"
                 : "=r"(r[0]), "=r"(r[1]), "=r"(r[2]), "=r"(r[3]) : "r"(addr));
}
__device__ __forceinline__ void mma16816(float* c, const uint32_t* a,
                                         uint32_t b0, uint32_t b1) {
    asm volatile(
        "mma.sync.aligned.m16n8k16.row.col.f32.bf16.bf16.f32 "
        "{%0,%1,%2,%3}, {%4,%5,%6,%7}, {%8,%9}, {%0,%1,%2,%3};"
        : "+f"(c[0]), "+f"(c[1]), "+f"(c[2]), "+f"(c[3])
        : "r"(a[0]), "r"(a[1]), "r"(a[2]), "r"(a[3]), "r"(b0), "r"(b1));
}
__device__ __forceinline__ void split2(float a, float b, uint32_t& hi, uint32_t& lo) {
    bf16 ha = __float2bfloat16(a), hb = __float2bfloat16(b);
    bf16 la = __float2bfloat16(a - __bfloat162float(ha));
    bf16 lb = __float2bfloat16(b - __bfloat162float(hb));
    __nv_bfloat162 h(ha, hb), l(la, lb);
    hi = *(uint32_t*)&h; lo = *(uint32_t*)&l;
}

// ============================================================
// Fused split: fp32 -> (bf16 hi, bf16 lo) for all 5 input tensors
// ============================================================
struct SplitJobs {
    const float4* in[5];
    __nv_bfloat162* hi[5];
    __nv_bfloat162* lo[5];
    int n4[5];
    int blk0[5];
};

__global__ void split_bf16_multi(SplitJobs j, int totblk)
{
    int r = 0;
    #pragma unroll
    for (int i = 1; i < 5; i++) if ((int)blockIdx.x >= j.blk0[i]) r = i;
    const int rel  = blockIdx.x - j.blk0[r];
    const int nblk = ((r + 1 < 5) ? j.blk0[r + 1] : totblk) - j.blk0[r];
    const float4* in = j.in[r];
    uint32_t* hi = (uint32_t*)j.hi[r];
    uint32_t* lo = (uint32_t*)j.lo[r];
    const int n4 = j.n4[r];
    for (int i = rel * blockDim.x + threadIdx.x; i < n4; i += nblk * blockDim.x) {
        float4 v = in[i];
        uint32_t h0, l0, h1, l1;
        split2(v.x, v.y, h0, l0);
        split2(v.z, v.w, h1, l1);
        hi[2*i] = h0; hi[2*i+1] = h1;
        lo[2*i] = l0; lo[2*i+1] = l1;
    }
}

// ============================================================
// mma.sync GEMM (3-pass bf16 split), CTA tile 128x128, BK=32,
// 2-stage cp.async, 2 CTAs/SM. 4 warps 2(m)x2(n), warp tile 64x64.
// 16 ldsm feed 96 MMAs per kk-step (dense tensor issue).
// Region-fused via blockIdx.x: region = bx>>4, bn = (bx&15)*128.
// ============================================================
#define OFF_AH 0
#define OFF_AL (128*80)          // 10240
#define OFF_BH (2*128*80)        // 20480
#define OFF_BL (3*128*80)        // 30720
#define STAGE_SZ (4*128*80)      // 40960
#define GSMEM2  (2*STAGE_SZ)     // 81920
#define GT 128                   // threads per GEMM CTA

struct GemmPtrs {
    const bf16* Bh[3];
    const bf16* Bl[3];
    const float* bias[3];
    bf16* Ch[3];
    bf16* Cl[3];
    float* C[3];
};

__device__ __forceinline__ void g_load_tile(uint32_t sbase, const bf16* g,
                                            int row0, int k0, int tid)
{
    const char* gp = (const char*)(g + (size_t)row0 * Hsz + k0);
    for (int c = tid; c < 512; c += GT) {
        int row = c >> 2, ch = c & 3;
        CP_ASYNC16(sbase + row * 80 + ch * 16, gp + (size_t)row * (Hsz * 2) + ch * 16);
    }
}
__device__ __forceinline__ void g_load_stage(uint32_t st, const bf16* Ah, const bf16* Al,
                                             const bf16* Bh, const bf16* Bl,
                                             int bm, int bn, int k0, int tid)
{
    g_load_tile(st + OFF_AH, Ah, bm, k0, tid);
    g_load_tile(st + OFF_AL, Al, bm, k0, tid);
    g_load_tile(st + OFF_BH, Bh, bn, k0, tid);
    g_load_tile(st + OFF_BL, Bl, bn, k0, tid);
}

template <bool BF16OUT>
__global__ void __launch_bounds__(GT, 2)
gemm_mma3(const bf16* __restrict__ Ah, const bf16* __restrict__ Al, GemmPtrs p)
{
    extern __shared__ __align__(128) char sm[];
    const uint32_t sb = smem_u32(sm);
    const int tid  = threadIdx.x;
    const int lane = tid & 31;
    const int wid  = tid >> 5;
    const int wm   = wid >> 1;        // 0..1
    const int wn   = wid & 1;         // 0..1
    const int region = blockIdx.x >> 4;
    const int bm = blockIdx.y * 128;
    const int bn = (blockIdx.x & 15) * 128;
    const bf16* Bh = p.Bh[region];
    const bf16* Bl = p.Bl[region];

    float acc[4][8][4];
    #pragma unroll
    for (int i = 0; i < 4; i++)
        #pragma unroll
        for (int j = 0; j < 8; j++)
            #pragma unroll
            for (int t = 0; t < 4; t++) acc[i][j][t] = 0.f;

    g_load_stage(sb, Ah, Al, Bh, Bl, bm, bn, 0, tid);
    CP_COMMIT();

    const int a_row = lane & 15;
    const int a_kb  = (lane >> 4) * 16;
    const int b_row = ((lane >> 4) & 1) * 8 + (lane & 7);
    const int b_kb  = ((lane >> 3) & 1) * 16;

    for (int kt = 0; kt < 64; kt++) {
        const int s = kt & 1;
        if (kt + 1 < 64) {
            g_load_stage(sb + (s ^ 1) * STAGE_SZ, Ah, Al, Bh, Bl, bm, bn, (kt + 1) * 32, tid);
            CP_COMMIT();
            CP_WAIT(1);
        } else {
            CP_WAIT(0);
        }
        __syncthreads();

        const uint32_t st = sb + s * STAGE_SZ;
        #pragma unroll
        for (int kk = 0; kk < 2; kk++) {
            uint32_t ah[4][4], al[4][4];
            #pragma unroll
            for (int mi = 0; mi < 4; mi++) {
                uint32_t ra = (uint32_t)((wm * 64 + mi * 16 + a_row) * 80 + a_kb + kk * 32);
                ldsm4(ah[mi], st + OFF_AH + ra);
                ldsm4(al[mi], st + OFF_AL + ra);
            }
            uint32_t bh[4][4], bl[4][4];
            #pragma unroll
            for (int g = 0; g < 4; g++) {
                uint32_t rb = (uint32_t)((wn * 64 + g * 16 + b_row) * 80 + b_kb + kk * 32);
                ldsm4(bh[g], st + OFF_BH + rb);
                ldsm4(bl[g], st + OFF_BL + rb);
            }
            #pragma unroll
            for (int pp = 0; pp < 3; pp++) {
                #pragma unroll
                for (int mi = 0; mi < 4; mi++) {
                    #pragma unroll
                    for (int nj = 0; nj < 8; nj++) {
                        const int g = nj >> 1, hsel = nj & 1;
                        const uint32_t* af = (pp == 2) ? al[mi] : ah[mi];
                        const uint32_t* bf = (pp == 1) ? bl[g] : bh[g];
                        mma16816(acc[mi][nj], af, bf[hsel * 2], bf[hsel * 2 + 1]);
                    }
                }
            }
        }
        __syncthreads();
    }

    const int rbase = bm + wm * 64 + (lane >> 2);
    const int cbase = bn + wn * 64 + (lane & 3) * 2;
    const float* bias = p.bias[region];
    #pragma unroll
    for (int mi = 0; mi < 4; mi++) {
        #pragma unroll
        for (int nj = 0; nj < 8; nj++) {
            int row = rbase + mi * 16;
            int col = cbase + nj * 8;
            float b0 = __ldg(&bias[col]), b1 = __ldg(&bias[col + 1]);
            float* c = acc[mi][nj];
            float v00 = c[0] + b0, v01 = c[1] + b1;
            float v10 = c[2] + b0, v11 = c[3] + b1;
            if (BF16OUT) {
                bf16* Ch = p.Ch[region];
                bf16* Cl = p.Cl[region];
                uint32_t h, l;
                split2(v00, v01, h, l);
                *(uint32_t*)(Ch + (size_t)row * Hsz + col) = h;
                *(uint32_t*)(Cl + (size_t)row * Hsz + col) = l;
                split2(v10, v11, h, l);
                *(uint32_t*)(Ch + (size_t)(row + 8) * Hsz + col) = h;
                *(uint32_t*)(Cl + (size_t)(row + 8) * Hsz + col) = l;
            } else {
                float* C = p.C[region];
                *(float2*)(C + (size_t)row * Hsz + col) = make_float2(v00, v01);
                *(float2*)(C + (size_t)(row + 8) * Hsz + col) = make_float2(v10, v11);
            }
        }
    }
}

// ============================================================
// Flash attention via mma.sync, 3-pass split on QK and PV.
// BQ=128, BKV=64, 256 threads (8 warps x 16 query rows).
// Heavy tiles (large qb) scheduled first via reversed blockIdx.x.
// ============================================================
#define VST 272
#define AKH 0
#define AKL (64*VST)
#define AVH (2*64*VST)
#define AVL (3*64*VST)
#define ASMEM (4*64*VST)

__device__ __forceinline__ void fa_load64(uint32_t sbase, const bf16* g, size_t gelem, int tid) {
    const char* gp = (const char*)(g + gelem);
    for (int c = tid; c < 1024; c += 256) {
        int r = c >> 4, ch = c & 15;
        CP_ASYNC16(sbase + r * VST + ch * 16, gp + (size_t)r * (Hsz * 2) + ch * 16);
    }
}
__device__ __forceinline__ void fa_load128(uint32_t sbase, const bf16* g, size_t gelem, int tid) {
    const char* gp = (const char*)(g + gelem);
    for (int c = tid; c < 2048; c += 256) {
        int r = c >> 4, ch = c & 15;
        CP_ASYNC16(sbase + r * VST + ch * 16, gp + (size_t)r * (Hsz * 2) + ch * 16);
    }
}

__global__ void __launch_bounds__(256, 1)
flash_mma(const bf16* __restrict__ Qh, const bf16* __restrict__ Ql,
          const bf16* __restrict__ Kh, const bf16* __restrict__ Kl,
          const bf16* __restrict__ Vh, const bf16* __restrict__ Vl,
          bf16* __restrict__ AOh, bf16* __restrict__ AOl)
{
    extern __shared__ __align__(128) char sm[];
    const uint32_t sb = smem_u32(sm);
    const int tid = threadIdx.x;
    const int lane = tid & 31;
    const int w = tid >> 5;
    const int wrow = w * 16;
    const int qb = gridDim.x - 1 - blockIdx.x;   // heavy-first scheduling
    const int h = blockIdx.y, b = blockIdx.z;
    const int q0 = qb * 128;
    const size_t baseKV = (size_t)(b * Ssz) * Hsz + h * HDIM;
    const size_t baseQ  = baseKV + (size_t)q0 * Hsz;

    const int a_row = lane & 15;
    const int a_kb  = (lane >> 4) * 16;
    const int b_row = ((lane >> 4) & 1) * 8 + (lane & 7);
    const int b_kb  = ((lane >> 3) & 1) * 16;
    const int t_row = lane & 15;
    const int t_cb  = (lane >> 4) * 16;

    uint32_t qfh[8][4], qfl[8][4];
    fa_load128(sb, Qh, baseQ, tid); CP_COMMIT(); CP_WAIT(0); __syncthreads();
    #pragma unroll
    for (int t = 0; t < 8; t++)
        ldsm4(qfh[t], sb + (uint32_t)((wrow + a_row) * VST + a_kb + t * 32));
    __syncthreads();
    fa_load128(sb, Ql, baseQ, tid); CP_COMMIT(); CP_WAIT(0); __syncthreads();
    #pragma unroll
    for (int t = 0; t < 8; t++)
        ldsm4(qfl[t], sb + (uint32_t)((wrow + a_row) * VST + a_kb + t * 32));
    __syncthreads();

    fa_load64(sb + AKH, Kh, baseKV, tid);
    fa_load64(sb + AKL, Kl, baseKV, tid);
    CP_COMMIT();

    float o[16][4];
    #pragma unroll
    for (int j = 0; j < 16; j++)
        #pragma unroll
        for (int t = 0; t < 4; t++) o[j][t] = 0.f;
    float m_i[2] = {-1e30f, -1e30f}, l_i[2] = {0.f, 0.f};

    const int ktmax = 2 * qb + 1;
    const int r0 = lane >> 2;
    const float sc = 0.08838834764831845f;

    for (int kt = 0; kt <= ktmax; kt++) {
        fa_load64(sb + AVH, Vh, baseKV + (size_t)(kt * 64) * Hsz, tid);
        fa_load64(sb + AVL, Vl, baseKV + (size_t)(kt * 64) * Hsz, tid);
        CP_COMMIT();
        CP_WAIT(1);
        __syncthreads();

        const bool active = (kt * 64 <= q0 + wrow + 15);
        float s[8][4];
        if (active) {
            #pragma unroll
            for (int j = 0; j < 8; j++)
                #pragma unroll
                for (int t = 0; t < 4; t++) s[j][t] = 0.f;
            #pragma unroll
            for (int t = 0; t < 8; t++) {
                uint32_t kbh[4][4], kbl[4][4];
                #pragma unroll
                for (int pp = 0; pp < 4; pp++) {
                    uint32_t ra = (uint32_t)((pp * 16 + b_row) * VST + b_kb + t * 32);
                    ldsm4(kbh[pp], sb + AKH + ra);
                    ldsm4(kbl[pp], sb + AKL + ra);
                }
                #pragma unroll
                for (int pp = 0; pp < 4; pp++) {
                    #pragma unroll
                    for (int hh = 0; hh < 2; hh++) {
                        mma16816(s[2*pp+hh], qfh[t], kbh[pp][hh*2], kbh[pp][hh*2+1]);
                        mma16816(s[2*pp+hh], qfh[t], kbl[pp][hh*2], kbl[pp][hh*2+1]);
                        mma16816(s[2*pp+hh], qfl[t], kbh[pp][hh*2], kbh[pp][hh*2+1]);
                    }
                }
            }
        }
        __syncthreads();

        const bool more = kt < ktmax;
        if (more) {
            fa_load64(sb + AKH, Kh, baseKV + (size_t)((kt + 1) * 64) * Hsz, tid);
            fa_load64(sb + AKL, Kl, baseKV + (size_t)((kt + 1) * 64) * Hsz, tid);
            CP_COMMIT();
        }

        uint32_t pah[4][4], pal[4][4];
        float fac[2];
        if (active) {
            #pragma unroll
            for (int j = 0; j < 8; j++)
                #pragma unroll
                for (int t = 0; t < 4; t++) s[j][t] *= sc;
            if (kt * 64 + 63 > q0 + wrow) {
                #pragma unroll
                for (int j = 0; j < 8; j++) {
                    int col = kt * 64 + j * 8 + (lane & 3) * 2;
                    int row = q0 + wrow + r0;
                    if (col > row)          s[j][0] = -1e30f;
                    if (col + 1 > row)      s[j][1] = -1e30f;
                    if (col > row + 8)      s[j][2] = -1e30f;
                    if (col + 1 > row + 8)  s[j][3] = -1e30f;
                }
            }
            #pragma unroll
            for (int r = 0; r < 2; r++) {
                float rm = -1e30f;
                #pragma unroll
                for (int j = 0; j < 8; j++) rm = fmaxf(rm, fmaxf(s[j][r*2], s[j][r*2+1]));
                rm = fmaxf(rm, __shfl_xor_sync(0xffffffffu, rm, 1));
                rm = fmaxf(rm, __shfl_xor_sync(0xffffffffu, rm, 2));
                float mn = fmaxf(m_i[r], rm);
                fac[r] = __expf(m_i[r] - mn);
                float rs = 0.f;
                #pragma unroll
                for (int j = 0; j < 8; j++) {
                    s[j][r*2]   = __expf(s[j][r*2]   - mn);
                    s[j][r*2+1] = __expf(s[j][r*2+1] - mn);
                    rs += s[j][r*2] + s[j][r*2+1];
                }
                rs += __shfl_xor_sync(0xffffffffu, rs, 1);
                rs += __shfl_xor_sync(0xffffffffu, rs, 2);
                l_i[r] = l_i[r] * fac[r] + rs;
                m_i[r] = mn;
            }
            #pragma unroll
            for (int t2 = 0; t2 < 4; t2++) {
                split2(s[2*t2][0],   s[2*t2][1],   pah[t2][0], pal[t2][0]);
                split2(s[2*t2][2],   s[2*t2][3],   pah[t2][1], pal[t2][1]);
                split2(s[2*t2+1][0], s[2*t2+1][1], pah[t2][2], pal[t2][2]);
                split2(s[2*t2+1][2], s[2*t2+1][3], pah[t2][3], pal[t2][3]);
            }
            #pragma unroll
            for (int j = 0; j < 16; j++) {
                o[j][0] *= fac[0]; o[j][1] *= fac[0];
                o[j][2] *= fac[1]; o[j][3] *= fac[1];
            }
        }

        if (more) { CP_WAIT(1); } else { CP_WAIT(0); }
        __syncthreads();

        if (active) {
            #pragma unroll
            for (int j2 = 0; j2 < 8; j2++) {
                #pragma unroll
                for (int t = 0; t < 4; t++) {
                    uint32_t bvh[4], bvl[4];
                    uint32_t ra = (uint32_t)((t * 16 + t_row) * VST + t_cb + j2 * 32);
                    ldsm4t(bvh, sb + AVH + ra);
                    ldsm4t(bvl, sb + AVL + ra);
                    mma16816(o[2*j2],   pah[t], bvh[0], bvh[1]);
                    mma16816(o[2*j2+1], pah[t], bvh[2], bvh[3]);
                    mma16816(o[2*j2],   pah[t], bvl[0], bvl[1]);
                    mma16816(o[2*j2+1], pah[t], bvl[2], bvl[3]);
                    mma16816(o[2*j2],   pal[t], bvh[0], bvh[1]);
                    mma16816(o[2*j2+1], pal[t], bvh[2], bvh[3]);
                }
            }
        }
        __syncthreads();
    }

    const float inv0 = 1.0f / l_i[0], inv1 = 1.0f / l_i[1];
    const int grow0 = q0 + wrow + r0;
    #pragma unroll
    for (int j = 0; j < 16; j++) {
        int col = j * 8 + (lane & 3) * 2;
        size_t e0 = baseKV + (size_t)grow0 * Hsz + col;
        size_t e1 = baseKV + (size_t)(grow0 + 8) * Hsz + col;
        uint32_t hh, ll;
        split2(o[j][0] * inv0, o[j][1] * inv0, hh, ll);
        *(uint32_t*)(AOh + e0) = hh; *(uint32_t*)(AOl + e0) = ll;
        split2(o[j][2] * inv1, o[j][3] * inv1, hh, ll);
        *(uint32_t*)(AOh + e1) = hh; *(uint32_t*)(AOl + e1) = ll;
    }
}

// ============================================================
extern "C" void kernel_launch(void* const* d_in, const int* in_sizes, int n_in,
                              void* d_out, int out_size) {
    const float* x  = (const float*)d_in[0];
    const float* Wf[4] = { (const float*)d_in[1], (const float*)d_in[3],
                           (const float*)d_in[5], (const float*)d_in[7] };
    const float* bQ = (const float*)d_in[2];
    const float* bK = (const float*)d_in[4];
    const float* bV = (const float*)d_in[6];
    const float* bO = (const float*)d_in[8];
    float* out = (float*)d_out;

    bf16 *xh, *xl, *qh, *ql, *kh, *kl, *vh, *vl, *aoh, *aol, *wh, *wl;
    cudaGetSymbolAddress((void**)&xh,  g_xh);  cudaGetSymbolAddress((void**)&xl,  g_xl);
    cudaGetSymbolAddress((void**)&qh,  g_qh);  cudaGetSymbolAddress((void**)&ql,  g_ql);
    cudaGetSymbolAddress((void**)&kh,  g_kh);  cudaGetSymbolAddress((void**)&kl,  g_kl);
    cudaGetSymbolAddress((void**)&vh,  g_vh);  cudaGetSymbolAddress((void**)&vl,  g_vl);
    cudaGetSymbolAddress((void**)&aoh, g_aoh); cudaGetSymbolAddress((void**)&aol, g_aol);
    cudaGetSymbolAddress((void**)&wh,  g_wh);  cudaGetSymbolAddress((void**)&wl,  g_wl);

    const size_t HH = (size_t)Hsz * Hsz;

    // Launch 1: fused split (x + 4 weights)
    SplitJobs sj;
    sj.in[0] = (const float4*)x;
    sj.hi[0] = (__nv_bfloat162*)xh; sj.lo[0] = (__nv_bfloat162*)xl;
    sj.n4[0] = Mrows * Hsz / 4;     sj.blk0[0] = 0;
    for (int i = 0; i < 4; i++) {
        sj.in[i+1] = (const float4*)Wf[i];
        sj.hi[i+1] = (__nv_bfloat162*)(wh + i * HH);
        sj.lo[i+1] = (__nv_bfloat162*)(wl + i * HH);
        sj.n4[i+1] = Hsz * Hsz / 4;
        sj.blk0[i+1] = 768 + i * 384;
    }
    const int totblk = 768 + 4 * 384;   // 2304
    split_bf16_multi<<<totblk, 256>>>(sj, totblk);

    cudaFuncSetAttribute(gemm_mma3<true>,  cudaFuncAttributeMaxDynamicSharedMemorySize, GSMEM2);
    cudaFuncSetAttribute(gemm_mma3<false>, cudaFuncAttributeMaxDynamicSharedMemorySize, GSMEM2);

    // Launch 2: fused QKV GEMM
    GemmPtrs pq;
    pq.Bh[0] = wh;          pq.Bh[1] = wh + HH;     pq.Bh[2] = wh + 2 * HH;
    pq.Bl[0] = wl;          pq.Bl[1] = wl + HH;     pq.Bl[2] = wl + 2 * HH;
    pq.bias[0] = bQ;        pq.bias[1] = bK;        pq.bias[2] = bV;
    pq.Ch[0] = qh;          pq.Ch[1] = kh;          pq.Ch[2] = vh;
    pq.Cl[0] = ql;          pq.Cl[1] = kl;          pq.Cl[2] = vl;
    pq.C[0] = pq.C[1] = pq.C[2] = nullptr;
    gemm_mma3<true><<<dim3(48, Mrows / 128), GT, GSMEM2>>>(xh, xl, pq);

    // Launch 3: attention
    cudaFuncSetAttribute(flash_mma, cudaFuncAttributeMaxDynamicSharedMemorySize, ASMEM);
    flash_mma<<<dim3(Ssz / 128, NHEAD, Bsz), 256, ASMEM>>>(qh, ql, kh, kl, vh, vl, aoh, aol);

    // Launch 4: output projection
    GemmPtrs po;
    po.Bh[0] = wh + 3 * HH; po.Bh[1] = po.Bh[2] = nullptr;
    po.Bl[0] = wl + 3 * HH; po.Bl[1] = po.Bl[2] = nullptr;
    po.bias[0] = bO;        po.bias[1] = po.bias[2] = nullptr;
    po.Ch[0] = po.Ch[1] = po.Ch[2] = nullptr;
    po.Cl[0] = po.Cl[1] = po.Cl[2] = nullptr;
    po.C[0] = out;          po.C[1] = po.C[2] = nullptr;
    gemm_mma3<false><<<dim3(16, Mrows / 128), GT, GSMEM2>>>(aoh, aol, po);
}

// round 8
// speedup vs baseline: 1.3009x; 1.0916x over previous
#include <cuda_runtime.h>
#include <cuda_bf16.h>
#include <cstdint>

// Problem dims
#define Bsz   2
#define Ssz   2048
#define Hsz   2048
#define NHEAD 16
#define HDIM  128
#define Mrows (Bsz*Ssz)   // 4096

typedef __nv_bfloat16 bf16;

// ---------------- scratch (static device globals) ----------------
__device__ bf16 g_xh [Mrows*Hsz], g_xl [Mrows*Hsz];
__device__ bf16 g_qh [Mrows*Hsz], g_ql [Mrows*Hsz];
__device__ bf16 g_kh [Mrows*Hsz], g_kl [Mrows*Hsz];
__device__ bf16 g_vh [Mrows*Hsz], g_vl [Mrows*Hsz];
__device__ bf16 g_aoh[Mrows*Hsz], g_aol[Mrows*Hsz];
__device__ bf16 g_wh [4][Hsz*Hsz], g_wl [4][Hsz*Hsz];

// ---------------- helpers ----------------
__device__ __forceinline__ uint32_t smem_u32(const void* p) {
    uint32_t a;
    asm("{ .reg .u64 t; cvta.to.shared.u64 t, %1; cvt.u32.u64 %0, t; }" : "=r"(a) : "l"(p));
    return a;
}
#define CP_ASYNC16(sa, ga) \
    asm volatile("cp.async.cg.shared.global [%0], [%1], 16;" :: "r"((uint32_t)(sa)), "l"(ga))
#define CP_COMMIT() asm volatile("cp.async.commit_group;" ::: "memory")
#define CP_WAIT(n)  asm volatile("cp.async.wait_group %0;" :: "n"(n) : "memory")

__device__ __forceinline__ void ldsm4(uint32_t* r, uint32_t addr) {
    asm volatile("ldmatrix.sync.aligned.m8n8.x4.shared.b16 {%0,%1,%2,%3}, [%4];"
                 : "=r"(r[0]), "=r"(r[1]), "=r"(r[2]), "=r"(r[3]) : "r"(addr));
}
__device__ __forceinline__ void ldsm4t(uint32_t* r, uint32_t addr) {
    asm volatile("ldmatrix.sync.aligned.m8n8.x4.trans.shared.b16 {%0,%1,%2,%3}, [%4];"
                 : "=r"(r[0]), "=r"(r[1]), "=r"(r[2]), "=r"(r[3]) : "r"(addr));
}
__device__ __forceinline__ void mma16816(float* c, const uint32_t* a,
                                         uint32_t b0, uint32_t b1) {
    asm volatile(
        "mma.sync.aligned.m16n8k16.row.col.f32.bf16.bf16.f32 "
        "{%0,%1,%2,%3}, {%4,%5,%6,%7}, {%8,%9}, {%0,%1,%2,%3};"
        : "+f"(c[0]), "+f"(c[1]), "+f"(c[2]), "+f"(c[3])
        : "r"(a[0]), "r"(a[1]), "r"(a[2]), "r"(a[3]), "r"(b0), "r"(b1));
}
__device__ __forceinline__ void split2(float a, float b, uint32_t& hi, uint32_t& lo) {
    bf16 ha = __float2bfloat16(a), hb = __float2bfloat16(b);
    bf16 la = __float2bfloat16(a - __bfloat162float(ha));
    bf16 lb = __float2bfloat16(b - __bfloat162float(hb));
    __nv_bfloat162 h(ha, hb), l(la, lb);
    hi = *(uint32_t*)&h; lo = *(uint32_t*)&l;
}

// 64B-row swizzle: conflict-free ldmatrix + cp.async for rows of 4x16B chunks
__device__ __forceinline__ uint32_t swz64(int row, int kbyte) {
    return (uint32_t)(row * 64 + (kbyte ^ (((row >> 1) & 3) << 4)));
}

// ============================================================
// Fused split: fp32 -> (bf16 hi, bf16 lo) for all 5 input tensors
// ============================================================
struct SplitJobs {
    const float4* in[5];
    __nv_bfloat162* hi[5];
    __nv_bfloat162* lo[5];
    int n4[5];
    int blk0[5];
};

__global__ void split_bf16_multi(SplitJobs j, int totblk)
{
    int r = 0;
    #pragma unroll
    for (int i = 1; i < 5; i++) if ((int)blockIdx.x >= j.blk0[i]) r = i;
    const int rel  = blockIdx.x - j.blk0[r];
    const int nblk = ((r + 1 < 5) ? j.blk0[r + 1] : totblk) - j.blk0[r];
    const float4* in = j.in[r];
    uint32_t* hi = (uint32_t*)j.hi[r];
    uint32_t* lo = (uint32_t*)j.lo[r];
    const int n4 = j.n4[r];
    for (int i = rel * blockDim.x + threadIdx.x; i < n4; i += nblk * blockDim.x) {
        float4 v = in[i];
        uint32_t h0, l0, h1, l1;
        split2(v.x, v.y, h0, l0);
        split2(v.z, v.w, h1, l1);
        hi[2*i] = h0; hi[2*i+1] = h1;
        lo[2*i] = l0; lo[2*i+1] = l1;
    }
}

// ============================================================
// mma.sync GEMM (3-pass bf16 split), CTA tile 128x128, BK=32.
// 3-stage cp.async + swizzled 64B rows -> ONE sync per k-iter,
// 2 CTAs/SM. 4 warps 2x2, warp tile 64x64.
// ============================================================
#define OFF_AH 0
#define OFF_AL (128*64)          // 8192
#define OFF_BH (2*128*64)        // 16384
#define OFF_BL (3*128*64)        // 24576
#define STAGE_SZ (4*128*64)      // 32768
#define GSMEM3  (3*STAGE_SZ)     // 98304
#define GT 128                   // threads per GEMM CTA

struct GemmPtrs {
    const bf16* Bh[3];
    const bf16* Bl[3];
    const float* bias[3];
    bf16* Ch[3];
    bf16* Cl[3];
    float* C[3];
};

__device__ __forceinline__ void g_load_tile(uint32_t sbase, const bf16* g,
                                            int row0, int k0, int tid)
{
    const char* gp = (const char*)(g + (size_t)row0 * Hsz + k0);
    #pragma unroll
    for (int c = tid; c < 512; c += GT) {
        int row = c >> 2, ch = (c & 3) << 4;
        CP_ASYNC16(sbase + swz64(row, ch), gp + (size_t)row * (Hsz * 2) + ch);
    }
}
__device__ __forceinline__ void g_load_stage(uint32_t st, const bf16* Ah, const bf16* Al,
                                             const bf16* Bh, const bf16* Bl,
                                             int bm, int bn, int k0, int tid)
{
    g_load_tile(st + OFF_AH, Ah, bm, k0, tid);
    g_load_tile(st + OFF_AL, Al, bm, k0, tid);
    g_load_tile(st + OFF_BH, Bh, bn, k0, tid);
    g_load_tile(st + OFF_BL, Bl, bn, k0, tid);
}

template <bool BF16OUT>
__global__ void __launch_bounds__(GT, 2)
gemm_mma3(const bf16* __restrict__ Ah, const bf16* __restrict__ Al, GemmPtrs p)
{
    extern __shared__ __align__(128) char sm[];
    const uint32_t sb = smem_u32(sm);
    const int tid  = threadIdx.x;
    const int lane = tid & 31;
    const int wid  = tid >> 5;
    const int wm   = wid >> 1;        // 0..1
    const int wn   = wid & 1;         // 0..1
    const int region = blockIdx.x >> 4;
    const int bm = blockIdx.y * 128;
    const int bn = (blockIdx.x & 15) * 128;
    const bf16* Bh = p.Bh[region];
    const bf16* Bl = p.Bl[region];

    float acc[4][8][4];
    #pragma unroll
    for (int i = 0; i < 4; i++)
        #pragma unroll
        for (int j = 0; j < 8; j++)
            #pragma unroll
            for (int t = 0; t < 4; t++) acc[i][j][t] = 0.f;

    // prologue: stages 0, 1
    g_load_stage(sb,            Ah, Al, Bh, Bl, bm, bn, 0,  tid); CP_COMMIT();
    g_load_stage(sb + STAGE_SZ, Ah, Al, Bh, Bl, bm, bn, 32, tid); CP_COMMIT();

    const int a_row = lane & 15;
    const int a_kb  = (lane >> 4) * 16;
    const int b_row = ((lane >> 4) & 1) * 8 + (lane & 7);
    const int b_kb  = ((lane >> 3) & 1) * 16;

    for (int kt = 0; kt < 64; kt++) {
        // retire stage kt's copies, then one barrier
        if (kt < 63) { CP_WAIT(1); } else { CP_WAIT(0); }
        __syncthreads();

        // issue loads for kt+2 into the buffer freed by iteration kt-1
        if (kt + 2 < 64) {
            g_load_stage(sb + ((kt + 2) % 3) * STAGE_SZ, Ah, Al, Bh, Bl,
                         bm, bn, (kt + 2) * 32, tid);
            CP_COMMIT();
        }

        const uint32_t st = sb + (kt % 3) * STAGE_SZ;
        #pragma unroll
        for (int kk = 0; kk < 2; kk++) {
            uint32_t ah[4][4], al[4][4];
            #pragma unroll
            for (int mi = 0; mi < 4; mi++) {
                const int row = wm * 64 + mi * 16 + a_row;
                uint32_t ra = swz64(row, a_kb + kk * 32);
                ldsm4(ah[mi], st + OFF_AH + ra);
                ldsm4(al[mi], st + OFF_AL + ra);
            }
            uint32_t bh[4][4], bl[4][4];
            #pragma unroll
            for (int g = 0; g < 4; g++) {
                const int row = wn * 64 + g * 16 + b_row;
                uint32_t rb = swz64(row, b_kb + kk * 32);
                ldsm4(bh[g], st + OFF_BH + rb);
                ldsm4(bl[g], st + OFF_BL + rb);
            }
            #pragma unroll
            for (int pp = 0; pp < 3; pp++) {
                #pragma unroll
                for (int mi = 0; mi < 4; mi++) {
                    #pragma unroll
                    for (int nj = 0; nj < 8; nj++) {
                        const int g = nj >> 1, hsel = nj & 1;
                        const uint32_t* af = (pp == 2) ? al[mi] : ah[mi];
                        const uint32_t* bf = (pp == 1) ? bl[g] : bh[g];
                        mma16816(acc[mi][nj], af, bf[hsel * 2], bf[hsel * 2 + 1]);
                    }
                }
            }
        }
    }

    const int rbase = bm + wm * 64 + (lane >> 2);
    const int cbase = bn + wn * 64 + (lane & 3) * 2;
    const float* bias = p.bias[region];
    #pragma unroll
    for (int mi = 0; mi < 4; mi++) {
        #pragma unroll
        for (int nj = 0; nj < 8; nj++) {
            int row = rbase + mi * 16;
            int col = cbase + nj * 8;
            float b0 = __ldg(&bias[col]), b1 = __ldg(&bias[col + 1]);
            float* c = acc[mi][nj];
            float v00 = c[0] + b0, v01 = c[1] + b1;
            float v10 = c[2] + b0, v11 = c[3] + b1;
            if (BF16OUT) {
                bf16* Ch = p.Ch[region];
                bf16* Cl = p.Cl[region];
                uint32_t h, l;
                split2(v00, v01, h, l);
                *(uint32_t*)(Ch + (size_t)row * Hsz + col) = h;
                *(uint32_t*)(Cl + (size_t)row * Hsz + col) = l;
                split2(v10, v11, h, l);
                *(uint32_t*)(Ch + (size_t)(row + 8) * Hsz + col) = h;
                *(uint32_t*)(Cl + (size_t)(row + 8) * Hsz + col) = l;
            } else {
                float* C = p.C[region];
                *(float2*)(C + (size_t)row * Hsz + col) = make_float2(v00, v01);
                *(float2*)(C + (size_t)(row + 8) * Hsz + col) = make_float2(v10, v11);
            }
        }
    }
}

// ============================================================
// Flash attention via mma.sync, 3-pass split on QK and PV.
// BQ=128, BKV=64, 256 threads (8 warps x 16 query rows).
// Heavy tiles first (reversed blockIdx.x).
// ============================================================
#define VST 272
#define AKH 0
#define AKL (64*VST)
#define AVH (2*64*VST)
#define AVL (3*64*VST)
#define ASMEM (4*64*VST)

__device__ __forceinline__ void fa_load64(uint32_t sbase, const bf16* g, size_t gelem, int tid) {
    const char* gp = (const char*)(g + gelem);
    for (int c = tid; c < 1024; c += 256) {
        int r = c >> 4, ch = c & 15;
        CP_ASYNC16(sbase + r * VST + ch * 16, gp + (size_t)r * (Hsz * 2) + ch * 16);
    }
}
__device__ __forceinline__ void fa_load128(uint32_t sbase, const bf16* g, size_t gelem, int tid) {
    const char* gp = (const char*)(g + gelem);
    for (int c = tid; c < 2048; c += 256) {
        int r = c >> 4, ch = c & 15;
        CP_ASYNC16(sbase + r * VST + ch * 16, gp + (size_t)r * (Hsz * 2) + ch * 16);
    }
}

__global__ void __launch_bounds__(256, 1)
flash_mma(const bf16* __restrict__ Qh, const bf16* __restrict__ Ql,
          const bf16* __restrict__ Kh, const bf16* __restrict__ Kl,
          const bf16* __restrict__ Vh, const bf16* __restrict__ Vl,
          bf16* __restrict__ AOh, bf16* __restrict__ AOl)
{
    extern __shared__ __align__(128) char sm[];
    const uint32_t sb = smem_u32(sm);
    const int tid = threadIdx.x;
    const int lane = tid & 31;
    const int w = tid >> 5;
    const int wrow = w * 16;
    const int qb = gridDim.x - 1 - blockIdx.x;   // heavy-first
    const int h = blockIdx.y, b = blockIdx.z;
    const int q0 = qb * 128;
    const size_t baseKV = (size_t)(b * Ssz) * Hsz + h * HDIM;
    const size_t baseQ  = baseKV + (size_t)q0 * Hsz;

    const int a_row = lane & 15;
    const int a_kb  = (lane >> 4) * 16;
    const int b_row = ((lane >> 4) & 1) * 8 + (lane & 7);
    const int b_kb  = ((lane >> 3) & 1) * 16;
    const int t_row = lane & 15;
    const int t_cb  = (lane >> 4) * 16;

    uint32_t qfh[8][4], qfl[8][4];
    fa_load128(sb, Qh, baseQ, tid); CP_COMMIT(); CP_WAIT(0); __syncthreads();
    #pragma unroll
    for (int t = 0; t < 8; t++)
        ldsm4(qfh[t], sb + (uint32_t)((wrow + a_row) * VST + a_kb + t * 32));
    __syncthreads();
    fa_load128(sb, Ql, baseQ, tid); CP_COMMIT(); CP_WAIT(0); __syncthreads();
    #pragma unroll
    for (int t = 0; t < 8; t++)
        ldsm4(qfl[t], sb + (uint32_t)((wrow + a_row) * VST + a_kb + t * 32));
    __syncthreads();

    fa_load64(sb + AKH, Kh, baseKV, tid);
    fa_load64(sb + AKL, Kl, baseKV, tid);
    CP_COMMIT();

    float o[16][4];
    #pragma unroll
    for (int j = 0; j < 16; j++)
        #pragma unroll
        for (int t = 0; t < 4; t++) o[j][t] = 0.f;
    float m_i[2] = {-1e30f, -1e30f}, l_i[2] = {0.f, 0.f};

    const int ktmax = 2 * qb + 1;
    const int r0 = lane >> 2;
    const float sc = 0.08838834764831845f;

    for (int kt = 0; kt <= ktmax; kt++) {
        fa_load64(sb + AVH, Vh, baseKV + (size_t)(kt * 64) * Hsz, tid);
        fa_load64(sb + AVL, Vl, baseKV + (size_t)(kt * 64) * Hsz, tid);
        CP_COMMIT();
        CP_WAIT(1);
        __syncthreads();

        const bool active = (kt * 64 <= q0 + wrow + 15);
        float s[8][4];
        if (active) {
            #pragma unroll
            for (int j = 0; j < 8; j++)
                #pragma unroll
                for (int t = 0; t < 4; t++) s[j][t] = 0.f;
            #pragma unroll
            for (int t = 0; t < 8; t++) {
                uint32_t kbh[4][4], kbl[4][4];
                #pragma unroll
                for (int pp = 0; pp < 4; pp++) {
                    uint32_t ra = (uint32_t)((pp * 16 + b_row) * VST + b_kb + t * 32);
                    ldsm4(kbh[pp], sb + AKH + ra);
                    ldsm4(kbl[pp], sb + AKL + ra);
                }
                #pragma unroll
                for (int pp = 0; pp < 4; pp++) {
                    #pragma unroll
                    for (int hh = 0; hh < 2; hh++) {
                        mma16816(s[2*pp+hh], qfh[t], kbh[pp][hh*2], kbh[pp][hh*2+1]);
                        mma16816(s[2*pp+hh], qfh[t], kbl[pp][hh*2], kbl[pp][hh*2+1]);
                        mma16816(s[2*pp+hh], qfl[t], kbh[pp][hh*2], kbh[pp][hh*2+1]);
                    }
                }
            }
        }
        __syncthreads();

        const bool more = kt < ktmax;
        if (more) {
            fa_load64(sb + AKH, Kh, baseKV + (size_t)((kt + 1) * 64) * Hsz, tid);
            fa_load64(sb + AKL, Kl, baseKV + (size_t)((kt + 1) * 64) * Hsz, tid);
            CP_COMMIT();
        }

        uint32_t pah[4][4], pal[4][4];
        float fac[2];
        if (active) {
            #pragma unroll
            for (int j = 0; j < 8; j++)
                #pragma unroll
                for (int t = 0; t < 4; t++) s[j][t] *= sc;
            if (kt * 64 + 63 > q0 + wrow) {
                #pragma unroll
                for (int j = 0; j < 8; j++) {
                    int col = kt * 64 + j * 8 + (lane & 3) * 2;
                    int row = q0 + wrow + r0;
                    if (col > row)          s[j][0] = -1e30f;
                    if (col + 1 > row)      s[j][1] = -1e30f;
                    if (col > row + 8)      s[j][2] = -1e30f;
                    if (col + 1 > row + 8)  s[j][3] = -1e30f;
                }
            }
            #pragma unroll
            for (int r = 0; r < 2; r++) {
                float rm = -1e30f;
                #pragma unroll
                for (int j = 0; j < 8; j++) rm = fmaxf(rm, fmaxf(s[j][r*2], s[j][r*2+1]));
                rm = fmaxf(rm, __shfl_xor_sync(0xffffffffu, rm, 1));
                rm = fmaxf(rm, __shfl_xor_sync(0xffffffffu, rm, 2));
                float mn = fmaxf(m_i[r], rm);
                fac[r] = __expf(m_i[r] - mn);
                float rs = 0.f;
                #pragma unroll
                for (int j = 0; j < 8; j++) {
                    s[j][r*2]   = __expf(s[j][r*2]   - mn);
                    s[j][r*2+1] = __expf(s[j][r*2+1] - mn);
                    rs += s[j][r*2] + s[j][r*2+1];
                }
                rs += __shfl_xor_sync(0xffffffffu, rs, 1);
                rs += __shfl_xor_sync(0xffffffffu, rs, 2);
                l_i[r] = l_i[r] * fac[r] + rs;
                m_i[r] = mn;
            }
            #pragma unroll
            for (int t2 = 0; t2 < 4; t2++) {
                split2(s[2*t2][0],   s[2*t2][1],   pah[t2][0], pal[t2][0]);
                split2(s[2*t2][2],   s[2*t2][3],   pah[t2][1], pal[t2][1]);
                split2(s[2*t2+1][0], s[2*t2+1][1], pah[t2][2], pal[t2][2]);
                split2(s[2*t2+1][2], s[2*t2+1][3], pah[t2][3], pal[t2][3]);
            }
            #pragma unroll
            for (int j = 0; j < 16; j++) {
                o[j][0] *= fac[0]; o[j][1] *= fac[0];
                o[j][2] *= fac[1]; o[j][3] *= fac[1];
            }
        }

        if (more) { CP_WAIT(1); } else { CP_WAIT(0); }
        __syncthreads();

        if (active) {
            #pragma unroll
            for (int j2 = 0; j2 < 8; j2++) {
                #pragma unroll
                for (int t = 0; t < 4; t++) {
                    uint32_t bvh[4], bvl[4];
                    uint32_t ra = (uint32_t)((t * 16 + t_row) * VST + t_cb + j2 * 32);
                    ldsm4t(bvh, sb + AVH + ra);
                    ldsm4t(bvl, sb + AVL + ra);
                    mma16816(o[2*j2],   pah[t], bvh[0], bvh[1]);
                    mma16816(o[2*j2+1], pah[t], bvh[2], bvh[3]);
                    mma16816(o[2*j2],   pah[t], bvl[0], bvl[1]);
                    mma16816(o[2*j2+1], pah[t], bvl[2], bvl[3]);
                    mma16816(o[2*j2],   pal[t], bvh[0], bvh[1]);
                    mma16816(o[2*j2+1], pal[t], bvh[2], bvh[3]);
                }
            }
        }
        __syncthreads();
    }

    const float inv0 = 1.0f / l_i[0], inv1 = 1.0f / l_i[1];
    const int grow0 = q0 + wrow + r0;
    #pragma unroll
    for (int j = 0; j < 16; j++) {
        int col = j * 8 + (lane & 3) * 2;
        size_t e0 = baseKV + (size_t)grow0 * Hsz + col;
        size_t e1 = baseKV + (size_t)(grow0 + 8) * Hsz + col;
        uint32_t hh, ll;
        split2(o[j][0] * inv0, o[j][1] * inv0, hh, ll);
        *(uint32_t*)(AOh + e0) = hh; *(uint32_t*)(AOl + e0) = ll;
        split2(o[j][2] * inv1, o[j][3] * inv1, hh, ll);
        *(uint32_t*)(AOh + e1) = hh; *(uint32_t*)(AOl + e1) = ll;
    }
}

// ============================================================
extern "C" void kernel_launch(void* const* d_in, const int* in_sizes, int n_in,
                              void* d_out, int out_size) {
    const float* x  = (const float*)d_in[0];
    const float* Wf[4] = { (const float*)d_in[1], (const float*)d_in[3],
                           (const float*)d_in[5], (const float*)d_in[7] };
    const float* bQ = (const float*)d_in[2];
    const float* bK = (const float*)d_in[4];
    const float* bV = (const float*)d_in[6];
    const float* bO = (const float*)d_in[8];
    float* out = (float*)d_out;

    bf16 *xh, *xl, *qh, *ql, *kh, *kl, *vh, *vl, *aoh, *aol, *wh, *wl;
    cudaGetSymbolAddress((void**)&xh,  g_xh);  cudaGetSymbolAddress((void**)&xl,  g_xl);
    cudaGetSymbolAddress((void**)&qh,  g_qh);  cudaGetSymbolAddress((void**)&ql,  g_ql);
    cudaGetSymbolAddress((void**)&kh,  g_kh);  cudaGetSymbolAddress((void**)&kl,  g_kl);
    cudaGetSymbolAddress((void**)&vh,  g_vh);  cudaGetSymbolAddress((void**)&vl,  g_vl);
    cudaGetSymbolAddress((void**)&aoh, g_aoh); cudaGetSymbolAddress((void**)&aol, g_aol);
    cudaGetSymbolAddress((void**)&wh,  g_wh);  cudaGetSymbolAddress((void**)&wl,  g_wl);

    const size_t HH = (size_t)Hsz * Hsz;

    // Launch 1: fused split (x + 4 weights)
    SplitJobs sj;
    sj.in[0] = (const float4*)x;
    sj.hi[0] = (__nv_bfloat162*)xh; sj.lo[0] = (__nv_bfloat162*)xl;
    sj.n4[0] = Mrows * Hsz / 4;     sj.blk0[0] = 0;
    for (int i = 0; i < 4; i++) {
        sj.in[i+1] = (const float4*)Wf[i];
        sj.hi[i+1] = (__nv_bfloat162*)(wh + i * HH);
        sj.lo[i+1] = (__nv_bfloat162*)(wl + i * HH);
        sj.n4[i+1] = Hsz * Hsz / 4;
        sj.blk0[i+1] = 768 + i * 384;
    }
    const int totblk = 768 + 4 * 384;   // 2304
    split_bf16_multi<<<totblk, 256>>>(sj, totblk);

    cudaFuncSetAttribute(gemm_mma3<true>,  cudaFuncAttributeMaxDynamicSharedMemorySize, GSMEM3);
    cudaFuncSetAttribute(gemm_mma3<false>, cudaFuncAttributeMaxDynamicSharedMemorySize, GSMEM3);

    // Launch 2: fused QKV GEMM
    GemmPtrs pq;
    pq.Bh[0] = wh;          pq.Bh[1] = wh + HH;     pq.Bh[2] = wh + 2 * HH;
    pq.Bl[0] = wl;          pq.Bl[1] = wl + HH;     pq.Bl[2] = wl + 2 * HH;
    pq.bias[0] = bQ;        pq.bias[1] = bK;        pq.bias[2] = bV;
    pq.Ch[0] = qh;          pq.Ch[1] = kh;          pq.Ch[2] = vh;
    pq.Cl[0] = ql;          pq.Cl[1] = kl;          pq.Cl[2] = vl;
    pq.C[0] = pq.C[1] = pq.C[2] = nullptr;
    gemm_mma3<true><<<dim3(48, Mrows / 128), GT, GSMEM3>>>(xh, xl, pq);

    // Launch 3: attention
    cudaFuncSetAttribute(flash_mma, cudaFuncAttributeMaxDynamicSharedMemorySize, ASMEM);
    flash_mma<<<dim3(Ssz / 128, NHEAD, Bsz), 256, ASMEM>>>(qh, ql, kh, kl, vh, vl, aoh, aol);

    // Launch 4: output projection
    GemmPtrs po;
    po.Bh[0] = wh + 3 * HH; po.Bh[1] = po.Bh[2] = nullptr;
    po.Bl[0] = wl + 3 * HH; po.Bl[1] = po.Bl[2] = nullptr;
    po.bias[0] = bO;        po.bias[1] = po.bias[2] = nullptr;
    po.Ch[0] = po.Ch[1] = po.Ch[2] = nullptr;
    po.Cl[0] = po.Cl[1] = po.Cl[2] = nullptr;
    po.C[0] = out;          po.C[1] = po.C[2] = nullptr;
    gemm_mma3<false><<<dim3(16, Mrows / 128), GT, GSMEM3>>>(aoh, aol, po);
}

// round 9
// speedup vs baseline: 1.3348x; 1.0261x over previous
#include <cuda_runtime.h>
#include <cuda_bf16.h>
#include <cstdint>

// Problem dims
#define Bsz   2
#define Ssz   2048
#define Hsz   2048
#define NHEAD 16
#define HDIM  128
#define Mrows (Bsz*Ssz)   // 4096

typedef __nv_bfloat16 bf16;

// ---------------- scratch (static device globals) ----------------
__device__ bf16 g_xh [Mrows*Hsz], g_xl [Mrows*Hsz];
__device__ bf16 g_qh [Mrows*Hsz], g_ql [Mrows*Hsz];
__device__ bf16 g_kh [Mrows*Hsz], g_kl [Mrows*Hsz];
__device__ bf16 g_vh [Mrows*Hsz], g_vl [Mrows*Hsz];
__device__ bf16 g_aoh[Mrows*Hsz], g_aol[Mrows*Hsz];
__device__ bf16 g_wh [4][Hsz*Hsz], g_wl [4][Hsz*Hsz];

// ---------------- helpers ----------------
__device__ __forceinline__ uint32_t smem_u32(const void* p) {
    uint32_t a;
    asm("{ .reg .u64 t; cvta.to.shared.u64 t, %1; cvt.u32.u64 %0, t; }" : "=r"(a) : "l"(p));
    return a;
}
#define CP_ASYNC16(sa, ga) \
    asm volatile("cp.async.cg.shared.global [%0], [%1], 16;" :: "r"((uint32_t)(sa)), "l"(ga))
#define CP_COMMIT() asm volatile("cp.async.commit_group;" ::: "memory")
#define CP_WAIT(n)  asm volatile("cp.async.wait_group %0;" :: "n"(n) : "memory")

__device__ __forceinline__ void ldsm4(uint32_t* r, uint32_t addr) {
    asm volatile("ldmatrix.sync.aligned.m8n8.x4.shared.b16 {%0,%1,%2,%3}, [%4];"
                 : "=r"(r[0]), "=r"(r[1]), "=r"(r[2]), "=r"(r[3]) : "r"(addr));
}
__device__ __forceinline__ void ldsm4t(uint32_t* r, uint32_t addr) {
    asm volatile("ldmatrix.sync.aligned.m8n8.x4.trans.shared.b16 {%0,%1,%2,%3}, [%4];"
                 : "=r"(r[0]), "=r"(r[1]), "=r"(r[2]), "=r"(r[3]) : "r"(addr));
}
__device__ __forceinline__ void mma16816(float* c, const uint32_t* a,
                                         uint32_t b0, uint32_t b1) {
    asm volatile(
        "mma.sync.aligned.m16n8k16.row.col.f32.bf16.bf16.f32 "
        "{%0,%1,%2,%3}, {%4,%5,%6,%7}, {%8,%9}, {%0,%1,%2,%3};"
        : "+f"(c[0]), "+f"(c[1]), "+f"(c[2]), "+f"(c[3])
        : "r"(a[0]), "r"(a[1]), "r"(a[2]), "r"(a[3]), "r"(b0), "r"(b1));
}
__device__ __forceinline__ void split2(float a, float b, uint32_t& hi, uint32_t& lo) {
    bf16 ha = __float2bfloat16(a), hb = __float2bfloat16(b);
    bf16 la = __float2bfloat16(a - __bfloat162float(ha));
    bf16 lb = __float2bfloat16(b - __bfloat162float(hb));
    __nv_bfloat162 h(ha, hb), l(la, lb);
    hi = *(uint32_t*)&h; lo = *(uint32_t*)&l;
}

// 64B-row swizzle: conflict-free ldmatrix + cp.async for rows of 4x16B chunks
__device__ __forceinline__ uint32_t swz64(int row, int kbyte) {
    return (uint32_t)(row * 64 + (kbyte ^ (((row >> 1) & 3) << 4)));
}

// ============================================================
// Fused split: fp32 -> (bf16 hi, bf16 lo) for all 5 input tensors
// ============================================================
struct SplitJobs {
    const float4* in[5];
    __nv_bfloat162* hi[5];
    __nv_bfloat162* lo[5];
    int n4[5];
    int blk0[5];
};

__global__ void split_bf16_multi(SplitJobs j, int totblk)
{
    int r = 0;
    #pragma unroll
    for (int i = 1; i < 5; i++) if ((int)blockIdx.x >= j.blk0[i]) r = i;
    const int rel  = blockIdx.x - j.blk0[r];
    const int nblk = ((r + 1 < 5) ? j.blk0[r + 1] : totblk) - j.blk0[r];
    const float4* in = j.in[r];
    uint32_t* hi = (uint32_t*)j.hi[r];
    uint32_t* lo = (uint32_t*)j.lo[r];
    const int n4 = j.n4[r];
    for (int i = rel * blockDim.x + threadIdx.x; i < n4; i += nblk * blockDim.x) {
        float4 v = in[i];
        uint32_t h0, l0, h1, l1;
        split2(v.x, v.y, h0, l0);
        split2(v.z, v.w, h1, l1);
        hi[2*i] = h0; hi[2*i+1] = h1;
        lo[2*i] = l0; lo[2*i+1] = l1;
    }
}

// ============================================================
// mma.sync GEMM (3-pass bf16 split), CTA tile 128x128, BK=32.
// 3-stage cp.async + swizzled 64B rows -> ONE sync per k-iter,
// 2 CTAs/SM. 4 warps 2x2, warp tile 64x64.  (unchanged from R8)
// ============================================================
#define OFF_AH 0
#define OFF_AL (128*64)
#define OFF_BH (2*128*64)
#define OFF_BL (3*128*64)
#define STAGE_SZ (4*128*64)      // 32768
#define GSMEM3  (3*STAGE_SZ)     // 98304
#define GT 128

struct GemmPtrs {
    const bf16* Bh[3];
    const bf16* Bl[3];
    const float* bias[3];
    bf16* Ch[3];
    bf16* Cl[3];
    float* C[3];
};

__device__ __forceinline__ void g_load_tile(uint32_t sbase, const bf16* g,
                                            int row0, int k0, int tid)
{
    const char* gp = (const char*)(g + (size_t)row0 * Hsz + k0);
    #pragma unroll
    for (int c = tid; c < 512; c += GT) {
        int row = c >> 2, ch = (c & 3) << 4;
        CP_ASYNC16(sbase + swz64(row, ch), gp + (size_t)row * (Hsz * 2) + ch);
    }
}
__device__ __forceinline__ void g_load_stage(uint32_t st, const bf16* Ah, const bf16* Al,
                                             const bf16* Bh, const bf16* Bl,
                                             int bm, int bn, int k0, int tid)
{
    g_load_tile(st + OFF_AH, Ah, bm, k0, tid);
    g_load_tile(st + OFF_AL, Al, bm, k0, tid);
    g_load_tile(st + OFF_BH, Bh, bn, k0, tid);
    g_load_tile(st + OFF_BL, Bl, bn, k0, tid);
}

template <bool BF16OUT>
__global__ void __launch_bounds__(GT, 2)
gemm_mma3(const bf16* __restrict__ Ah, const bf16* __restrict__ Al, GemmPtrs p)
{
    extern __shared__ __align__(128) char sm[];
    const uint32_t sb = smem_u32(sm);
    const int tid  = threadIdx.x;
    const int lane = tid & 31;
    const int wid  = tid >> 5;
    const int wm   = wid >> 1;
    const int wn   = wid & 1;
    const int region = blockIdx.x >> 4;
    const int bm = blockIdx.y * 128;
    const int bn = (blockIdx.x & 15) * 128;
    const bf16* Bh = p.Bh[region];
    const bf16* Bl = p.Bl[region];

    float acc[4][8][4];
    #pragma unroll
    for (int i = 0; i < 4; i++)
        #pragma unroll
        for (int j = 0; j < 8; j++)
            #pragma unroll
            for (int t = 0; t < 4; t++) acc[i][j][t] = 0.f;

    g_load_stage(sb,            Ah, Al, Bh, Bl, bm, bn, 0,  tid); CP_COMMIT();
    g_load_stage(sb + STAGE_SZ, Ah, Al, Bh, Bl, bm, bn, 32, tid); CP_COMMIT();

    const int a_row = lane & 15;
    const int a_kb  = (lane >> 4) * 16;
    const int b_row = ((lane >> 4) & 1) * 8 + (lane & 7);
    const int b_kb  = ((lane >> 3) & 1) * 16;

    for (int kt = 0; kt < 64; kt++) {
        if (kt < 63) { CP_WAIT(1); } else { CP_WAIT(0); }
        __syncthreads();

        if (kt + 2 < 64) {
            g_load_stage(sb + ((kt + 2) % 3) * STAGE_SZ, Ah, Al, Bh, Bl,
                         bm, bn, (kt + 2) * 32, tid);
            CP_COMMIT();
        }

        const uint32_t st = sb + (kt % 3) * STAGE_SZ;
        #pragma unroll
        for (int kk = 0; kk < 2; kk++) {
            uint32_t ah[4][4], al[4][4];
            #pragma unroll
            for (int mi = 0; mi < 4; mi++) {
                const int row = wm * 64 + mi * 16 + a_row;
                uint32_t ra = swz64(row, a_kb + kk * 32);
                ldsm4(ah[mi], st + OFF_AH + ra);
                ldsm4(al[mi], st + OFF_AL + ra);
            }
            uint32_t bh[4][4], bl[4][4];
            #pragma unroll
            for (int g = 0; g < 4; g++) {
                const int row = wn * 64 + g * 16 + b_row;
                uint32_t rb = swz64(row, b_kb + kk * 32);
                ldsm4(bh[g], st + OFF_BH + rb);
                ldsm4(bl[g], st + OFF_BL + rb);
            }
            #pragma unroll
            for (int pp = 0; pp < 3; pp++) {
                #pragma unroll
                for (int mi = 0; mi < 4; mi++) {
                    #pragma unroll
                    for (int nj = 0; nj < 8; nj++) {
                        const int g = nj >> 1, hsel = nj & 1;
                        const uint32_t* af = (pp == 2) ? al[mi] : ah[mi];
                        const uint32_t* bf = (pp == 1) ? bl[g] : bh[g];
                        mma16816(acc[mi][nj], af, bf[hsel * 2], bf[hsel * 2 + 1]);
                    }
                }
            }
        }
    }

    const int rbase = bm + wm * 64 + (lane >> 2);
    const int cbase = bn + wn * 64 + (lane & 3) * 2;
    const float* bias = p.bias[region];
    #pragma unroll
    for (int mi = 0; mi < 4; mi++) {
        #pragma unroll
        for (int nj = 0; nj < 8; nj++) {
            int row = rbase + mi * 16;
            int col = cbase + nj * 8;
            float b0 = __ldg(&bias[col]), b1 = __ldg(&bias[col + 1]);
            float* c = acc[mi][nj];
            float v00 = c[0] + b0, v01 = c[1] + b1;
            float v10 = c[2] + b0, v11 = c[3] + b1;
            if (BF16OUT) {
                bf16* Ch = p.Ch[region];
                bf16* Cl = p.Cl[region];
                uint32_t h, l;
                split2(v00, v01, h, l);
                *(uint32_t*)(Ch + (size_t)row * Hsz + col) = h;
                *(uint32_t*)(Cl + (size_t)row * Hsz + col) = l;
                split2(v10, v11, h, l);
                *(uint32_t*)(Ch + (size_t)(row + 8) * Hsz + col) = h;
                *(uint32_t*)(Cl + (size_t)(row + 8) * Hsz + col) = l;
            } else {
                float* C = p.C[region];
                *(float2*)(C + (size_t)row * Hsz + col) = make_float2(v00, v01);
                *(float2*)(C + (size_t)(row + 8) * Hsz + col) = make_float2(v10, v11);
            }
        }
    }
}

// ============================================================
// Flash attention via mma.sync, 3-pass split on QK and PV.
// BQ=64, BKV=64, 128 threads (4 warps x 16 query rows), 2 CTAs/SM.
// Heavy tiles first (reversed blockIdx.x).
// ============================================================
#define VST 272
#define AKH 0
#define AKL (64*VST)
#define AVH (2*64*VST)
#define AVL (3*64*VST)
#define ASMEM (4*64*VST)          // 69632 per CTA, 2 CTAs/SM
#define FT 128                    // flash threads

__device__ __forceinline__ void fa_load64(uint32_t sbase, const bf16* g, size_t gelem, int tid) {
    const char* gp = (const char*)(g + gelem);
    #pragma unroll
    for (int c = tid; c < 1024; c += FT) {
        int r = c >> 4, ch = c & 15;
        CP_ASYNC16(sbase + r * VST + ch * 16, gp + (size_t)r * (Hsz * 2) + ch * 16);
    }
}

__global__ void __launch_bounds__(FT, 2)
flash_mma(const bf16* __restrict__ Qh, const bf16* __restrict__ Ql,
          const bf16* __restrict__ Kh, const bf16* __restrict__ Kl,
          const bf16* __restrict__ Vh, const bf16* __restrict__ Vl,
          bf16* __restrict__ AOh, bf16* __restrict__ AOl)
{
    extern __shared__ __align__(128) char sm[];
    const uint32_t sb = smem_u32(sm);
    const int tid = threadIdx.x;
    const int lane = tid & 31;
    const int w = tid >> 5;           // 0..3
    const int wrow = w * 16;
    const int qb = gridDim.x - 1 - blockIdx.x;   // heavy-first
    const int h = blockIdx.y, b = blockIdx.z;
    const int q0 = qb * 64;
    const size_t baseKV = (size_t)(b * Ssz) * Hsz + h * HDIM;
    const size_t baseQ  = baseKV + (size_t)q0 * Hsz;

    const int a_row = lane & 15;
    const int a_kb  = (lane >> 4) * 16;
    const int b_row = ((lane >> 4) & 1) * 8 + (lane & 7);
    const int b_kb  = ((lane >> 3) & 1) * 16;
    const int t_row = lane & 15;
    const int t_cb  = (lane >> 4) * 16;

    // ---- load Q fragments (hi then lo), staged through the K buffer ----
    uint32_t qfh[8][4], qfl[8][4];
    fa_load64(sb, Qh, baseQ, tid); CP_COMMIT(); CP_WAIT(0); __syncthreads();
    #pragma unroll
    for (int t = 0; t < 8; t++)
        ldsm4(qfh[t], sb + (uint32_t)((wrow + a_row) * VST + a_kb + t * 32));
    __syncthreads();
    fa_load64(sb, Ql, baseQ, tid); CP_COMMIT(); CP_WAIT(0); __syncthreads();
    #pragma unroll
    for (int t = 0; t < 8; t++)
        ldsm4(qfl[t], sb + (uint32_t)((wrow + a_row) * VST + a_kb + t * 32));
    __syncthreads();

    // kick off K(0)
    fa_load64(sb + AKH, Kh, baseKV, tid);
    fa_load64(sb + AKL, Kl, baseKV, tid);
    CP_COMMIT();

    float o[16][4];
    #pragma unroll
    for (int j = 0; j < 16; j++)
        #pragma unroll
        for (int t = 0; t < 4; t++) o[j][t] = 0.f;
    float m_i[2] = {-1e30f, -1e30f}, l_i[2] = {0.f, 0.f};

    const int ktmax = qb;             // kv tiles 0..qb (64-wide)
    const int r0 = lane >> 2;
    const float sc = 0.08838834764831845f;

    for (int kt = 0; kt <= ktmax; kt++) {
        // V(kt) load overlaps QK compute
        fa_load64(sb + AVH, Vh, baseKV + (size_t)(kt * 64) * Hsz, tid);
        fa_load64(sb + AVL, Vl, baseKV + (size_t)(kt * 64) * Hsz, tid);
        CP_COMMIT();
        CP_WAIT(1);              // K(kt) complete
        __syncthreads();

        float s[8][4];
        #pragma unroll
        for (int j = 0; j < 8; j++)
            #pragma unroll
            for (int t = 0; t < 4; t++) s[j][t] = 0.f;
        #pragma unroll
        for (int t = 0; t < 8; t++) {
            uint32_t kbh[4][4], kbl[4][4];
            #pragma unroll
            for (int pp = 0; pp < 4; pp++) {
                uint32_t ra = (uint32_t)((pp * 16 + b_row) * VST + b_kb + t * 32);
                ldsm4(kbh[pp], sb + AKH + ra);
                ldsm4(kbl[pp], sb + AKL + ra);
            }
            #pragma unroll
            for (int pp = 0; pp < 4; pp++) {
                #pragma unroll
                for (int hh = 0; hh < 2; hh++) {
                    mma16816(s[2*pp+hh], qfh[t], kbh[pp][hh*2], kbh[pp][hh*2+1]);
                    mma16816(s[2*pp+hh], qfh[t], kbl[pp][hh*2], kbl[pp][hh*2+1]);
                    mma16816(s[2*pp+hh], qfl[t], kbh[pp][hh*2], kbh[pp][hh*2+1]);
                }
            }
        }
        __syncthreads();         // everyone done reading K buf

        const bool more = kt < ktmax;
        if (more) {
            fa_load64(sb + AKH, Kh, baseKV + (size_t)((kt + 1) * 64) * Hsz, tid);
            fa_load64(sb + AKL, Kl, baseKV + (size_t)((kt + 1) * 64) * Hsz, tid);
            CP_COMMIT();
        }

        uint32_t pah[4][4], pal[4][4];
        float fac[2];
        {
            #pragma unroll
            for (int j = 0; j < 8; j++)
                #pragma unroll
                for (int t = 0; t < 4; t++) s[j][t] *= sc;
            if (kt == ktmax) {   // diagonal tile: causal mask
                #pragma unroll
                for (int j = 0; j < 8; j++) {
                    int col = kt * 64 + j * 8 + (lane & 3) * 2;
                    int row = q0 + wrow + r0;
                    if (col > row)          s[j][0] = -1e30f;
                    if (col + 1 > row)      s[j][1] = -1e30f;
                    if (col > row + 8)      s[j][2] = -1e30f;
                    if (col + 1 > row + 8)  s[j][3] = -1e30f;
                }
            }
            #pragma unroll
            for (int r = 0; r < 2; r++) {
                float rm = -1e30f;
                #pragma unroll
                for (int j = 0; j < 8; j++) rm = fmaxf(rm, fmaxf(s[j][r*2], s[j][r*2+1]));
                rm = fmaxf(rm, __shfl_xor_sync(0xffffffffu, rm, 1));
                rm = fmaxf(rm, __shfl_xor_sync(0xffffffffu, rm, 2));
                float mn = fmaxf(m_i[r], rm);
                fac[r] = __expf(m_i[r] - mn);
                float rs = 0.f;
                #pragma unroll
                for (int j = 0; j < 8; j++) {
                    s[j][r*2]   = __expf(s[j][r*2]   - mn);
                    s[j][r*2+1] = __expf(s[j][r*2+1] - mn);
                    rs += s[j][r*2] + s[j][r*2+1];
                }
                rs += __shfl_xor_sync(0xffffffffu, rs, 1);
                rs += __shfl_xor_sync(0xffffffffu, rs, 2);
                l_i[r] = l_i[r] * fac[r] + rs;
                m_i[r] = mn;
            }
            #pragma unroll
            for (int t2 = 0; t2 < 4; t2++) {
                split2(s[2*t2][0],   s[2*t2][1],   pah[t2][0], pal[t2][0]);
                split2(s[2*t2][2],   s[2*t2][3],   pah[t2][1], pal[t2][1]);
                split2(s[2*t2+1][0], s[2*t2+1][1], pah[t2][2], pal[t2][2]);
                split2(s[2*t2+1][2], s[2*t2+1][3], pah[t2][3], pal[t2][3]);
            }
            #pragma unroll
            for (int j = 0; j < 16; j++) {
                o[j][0] *= fac[0]; o[j][1] *= fac[0];
                o[j][2] *= fac[1]; o[j][3] *= fac[1];
            }
        }

        if (more) { CP_WAIT(1); } else { CP_WAIT(0); }   // V(kt) complete
        __syncthreads();

        #pragma unroll
        for (int j2 = 0; j2 < 8; j2++) {
            #pragma unroll
            for (int t = 0; t < 4; t++) {
                uint32_t bvh[4], bvl[4];
                uint32_t ra = (uint32_t)((t * 16 + t_row) * VST + t_cb + j2 * 32);
                ldsm4t(bvh, sb + AVH + ra);
                ldsm4t(bvl, sb + AVL + ra);
                mma16816(o[2*j2],   pah[t], bvh[0], bvh[1]);
                mma16816(o[2*j2+1], pah[t], bvh[2], bvh[3]);
                mma16816(o[2*j2],   pah[t], bvl[0], bvl[1]);
                mma16816(o[2*j2+1], pah[t], bvl[2], bvl[3]);
                mma16816(o[2*j2],   pal[t], bvh[0], bvh[1]);
                mma16816(o[2*j2+1], pal[t], bvh[2], bvh[3]);
            }
        }
        __syncthreads();         // everyone done reading V buf
    }

    const float inv0 = 1.0f / l_i[0], inv1 = 1.0f / l_i[1];
    const int grow0 = q0 + wrow + r0;
    #pragma unroll
    for (int j = 0; j < 16; j++) {
        int col = j * 8 + (lane & 3) * 2;
        size_t e0 = baseKV + (size_t)grow0 * Hsz + col;
        size_t e1 = baseKV + (size_t)(grow0 + 8) * Hsz + col;
        uint32_t hh, ll;
        split2(o[j][0] * inv0, o[j][1] * inv0, hh, ll);
        *(uint32_t*)(AOh + e0) = hh; *(uint32_t*)(AOl + e0) = ll;
        split2(o[j][2] * inv1, o[j][3] * inv1, hh, ll);
        *(uint32_t*)(AOh + e1) = hh; *(uint32_t*)(AOl + e1) = ll;
    }
}

// ============================================================
extern "C" void kernel_launch(void* const* d_in, const int* in_sizes, int n_in,
                              void* d_out, int out_size) {
    const float* x  = (const float*)d_in[0];
    const float* Wf[4] = { (const float*)d_in[1], (const float*)d_in[3],
                           (const float*)d_in[5], (const float*)d_in[7] };
    const float* bQ = (const float*)d_in[2];
    const float* bK = (const float*)d_in[4];
    const float* bV = (const float*)d_in[6];
    const float* bO = (const float*)d_in[8];
    float* out = (float*)d_out;

    bf16 *xh, *xl, *qh, *ql, *kh, *kl, *vh, *vl, *aoh, *aol, *wh, *wl;
    cudaGetSymbolAddress((void**)&xh,  g_xh);  cudaGetSymbolAddress((void**)&xl,  g_xl);
    cudaGetSymbolAddress((void**)&qh,  g_qh);  cudaGetSymbolAddress((void**)&ql,  g_ql);
    cudaGetSymbolAddress((void**)&kh,  g_kh);  cudaGetSymbolAddress((void**)&kl,  g_kl);
    cudaGetSymbolAddress((void**)&vh,  g_vh);  cudaGetSymbolAddress((void**)&vl,  g_vl);
    cudaGetSymbolAddress((void**)&aoh, g_aoh); cudaGetSymbolAddress((void**)&aol, g_aol);
    cudaGetSymbolAddress((void**)&wh,  g_wh);  cudaGetSymbolAddress((void**)&wl,  g_wl);

    const size_t HH = (size_t)Hsz * Hsz;

    // Launch 1: fused split (x + 4 weights)
    SplitJobs sj;
    sj.in[0] = (const float4*)x;
    sj.hi[0] = (__nv_bfloat162*)xh; sj.lo[0] = (__nv_bfloat162*)xl;
    sj.n4[0] = Mrows * Hsz / 4;     sj.blk0[0] = 0;
    for (int i = 0; i < 4; i++) {
        sj.in[i+1] = (const float4*)Wf[i];
        sj.hi[i+1] = (__nv_bfloat162*)(wh + i * HH);
        sj.lo[i+1] = (__nv_bfloat162*)(wl + i * HH);
        sj.n4[i+1] = Hsz * Hsz / 4;
        sj.blk0[i+1] = 768 + i * 384;
    }
    const int totblk = 768 + 4 * 384;   // 2304
    split_bf16_multi<<<totblk, 256>>>(sj, totblk);

    cudaFuncSetAttribute(gemm_mma3<true>,  cudaFuncAttributeMaxDynamicSharedMemorySize, GSMEM3);
    cudaFuncSetAttribute(gemm_mma3<false>, cudaFuncAttributeMaxDynamicSharedMemorySize, GSMEM3);

    // Launch 2: fused QKV GEMM
    GemmPtrs pq;
    pq.Bh[0] = wh;          pq.Bh[1] = wh + HH;     pq.Bh[2] = wh + 2 * HH;
    pq.Bl[0] = wl;          pq.Bl[1] = wl + HH;     pq.Bl[2] = wl + 2 * HH;
    pq.bias[0] = bQ;        pq.bias[1] = bK;        pq.bias[2] = bV;
    pq.Ch[0] = qh;          pq.Ch[1] = kh;          pq.Ch[2] = vh;
    pq.Cl[0] = ql;          pq.Cl[1] = kl;          pq.Cl[2] = vl;
    pq.C[0] = pq.C[1] = pq.C[2] = nullptr;
    gemm_mma3<true><<<dim3(48, Mrows / 128), GT, GSMEM3>>>(xh, xl, pq);

    // Launch 3: attention — BQ=64, 4-warp CTAs, 2 CTAs/SM
    cudaFuncSetAttribute(flash_mma, cudaFuncAttributeMaxDynamicSharedMemorySize, ASMEM);
    flash_mma<<<dim3(Ssz / 64, NHEAD, Bsz), FT, ASMEM>>>(qh, ql, kh, kl, vh, vl, aoh, aol);

    // Launch 4: output projection
    GemmPtrs po;
    po.Bh[0] = wh + 3 * HH; po.Bh[1] = po.Bh[2] = nullptr;
    po.Bl[0] = wl + 3 * HH; po.Bl[1] = po.Bl[2] = nullptr;
    po.bias[0] = bO;        po.bias[1] = po.bias[2] = nullptr;
    po.Ch[0] = po.Ch[1] = po.Ch[2] = nullptr;
    po.Cl[0] = po.Cl[1] = po.Cl[2] = nullptr;
    po.C[0] = out;          po.C[1] = po.C[2] = nullptr;
    gemm_mma3<false><<<dim3(16, Mrows / 128), GT, GSMEM3>>>(aoh, aol, po);
}

// round 11
// speedup vs baseline: 1.6515x; 1.2372x over previous
#include <cuda_runtime.h>
#include <cuda_bf16.h>
#include <cstdint>

// Problem dims
#define Bsz   2
#define Ssz   2048
#define Hsz   2048
#define NHEAD 16
#define HDIM  128
#define Mrows (Bsz*Ssz)   // 4096

typedef __nv_bfloat16 bf16;

// ---------------- scratch (static device globals) ----------------
__device__ float g_xt [Mrows*Hsz];          // RNA-rounded x
__device__ float g_wt [4][Hsz*Hsz];         // RNA-rounded weights
__device__ float g_ao [Mrows*Hsz];          // attention out (RNA-rounded)
__device__ bf16 g_qh [Mrows*Hsz], g_ql [Mrows*Hsz];
__device__ bf16 g_kh [Mrows*Hsz], g_kl [Mrows*Hsz];
__device__ bf16 g_vh [Mrows*Hsz], g_vl [Mrows*Hsz];

// ---------------- helpers ----------------
__device__ __forceinline__ uint32_t smem_u32(const void* p) {
    uint32_t a;
    asm("{ .reg .u64 t; cvta.to.shared.u64 t, %1; cvt.u32.u64 %0, t; }" : "=r"(a) : "l"(p));
    return a;
}
#define CP_ASYNC16(sa, ga) \
    asm volatile("cp.async.cg.shared.global [%0], [%1], 16;" :: "r"((uint32_t)(sa)), "l"(ga))
#define CP_COMMIT() asm volatile("cp.async.commit_group;" ::: "memory")
#define CP_WAIT(n)  asm volatile("cp.async.wait_group %0;" :: "n"(n) : "memory")

__device__ __forceinline__ void ldsm4(uint32_t* r, uint32_t addr) {
    asm volatile("ldmatrix.sync.aligned.m8n8.x4.shared.b16 {%0,%1,%2,%3}, [%4];"
                 : "=r"(r[0]), "=r"(r[1]), "=r"(r[2]), "=r"(r[3]) : "r"(addr));
}
__device__ __forceinline__ void ldsm4t(uint32_t* r, uint32_t addr) {
    asm volatile("ldmatrix.sync.aligned.m8n8.x4.trans.shared.b16 {%0,%1,%2,%3}, [%4];"
                 : "=r"(r[0]), "=r"(r[1]), "=r"(r[2]), "=r"(r[3]) : "r"(addr));
}
// bf16 mma (flash)
__device__ __forceinline__ void mma16816(float* c, const uint32_t* a,
                                         uint32_t b0, uint32_t b1) {
    asm volatile(
        "mma.sync.aligned.m16n8k16.row.col.f32.bf16.bf16.f32 "
        "{%0,%1,%2,%3}, {%4,%5,%6,%7}, {%8,%9}, {%0,%1,%2,%3};"
        : "+f"(c[0]), "+f"(c[1]), "+f"(c[2]), "+f"(c[3])
        : "r"(a[0]), "r"(a[1]), "r"(a[2]), "r"(a[3]), "r"(b0), "r"(b1));
}
// tf32 mma (projections)
__device__ __forceinline__ void mma1688t(float* c, const uint32_t* a,
                                         uint32_t b0, uint32_t b1) {
    asm volatile(
        "mma.sync.aligned.m16n8k8.row.col.f32.tf32.tf32.f32 "
        "{%0,%1,%2,%3}, {%4,%5,%6,%7}, {%8,%9}, {%0,%1,%2,%3};"
        : "+f"(c[0]), "+f"(c[1]), "+f"(c[2]), "+f"(c[3])
        : "r"(a[0]), "r"(a[1]), "r"(a[2]), "r"(a[3]), "r"(b0), "r"(b1));
}
__device__ __forceinline__ void split2(float a, float b, uint32_t& hi, uint32_t& lo) {
    bf16 ha = __float2bfloat16(a), hb = __float2bfloat16(b);
    bf16 la = __float2bfloat16(a - __bfloat162float(ha));
    bf16 lb = __float2bfloat16(b - __bfloat162float(hb));
    __nv_bfloat162 h(ha, hb), l(la, lb);
    hi = *(uint32_t*)&h; lo = *(uint32_t*)&l;
}
// RNA round to tf32-exact fp32. tf32 lives in b32 registers in PTX -> "=r".
__device__ __forceinline__ float rna_tf32(float v) {
    uint32_t o;
    asm("cvt.rna.tf32.f32 %0, %1;" : "=r"(o) : "f"(v));
    return __uint_as_float(o);
}
// 16B-chunk XOR swizzle for 32-float (128B) rows: chunk 0..7, rows 0..127
__device__ __forceinline__ uint32_t swzf(int row, int chunk) {
    return (uint32_t)(row * 128 + ((chunk ^ (row & 7)) << 4));
}

// ============================================================
// Prep: RNA-round fp32 -> tf32-exact fp32 copies (x + 4 weights)
// ============================================================
struct PrepJobs {
    const float4* in[5];
    float4* out[5];
    int n4[5];
    int blk0[5];
};

__global__ void prep_tf32(PrepJobs j, int totblk)
{
    int r = 0;
    #pragma unroll
    for (int i = 1; i < 5; i++) if ((int)blockIdx.x >= j.blk0[i]) r = i;
    const int rel  = blockIdx.x - j.blk0[r];
    const int nblk = ((r + 1 < 5) ? j.blk0[r + 1] : totblk) - j.blk0[r];
    const float4* in = j.in[r];
    float4* out = j.out[r];
    const int n4 = j.n4[r];
    for (int i = rel * blockDim.x + threadIdx.x; i < n4; i += nblk * blockDim.x) {
        float4 v = in[i];
        v.x = rna_tf32(v.x); v.y = rna_tf32(v.y);
        v.z = rna_tf32(v.z); v.w = rna_tf32(v.w);
        out[i] = v;
    }
}

// ============================================================
// tf32 GEMM: C[M,N] = A @ B^T + bias.  CTA 128x128, BK=32,
// 3-stage cp.async, 1 sync/iter, 2 CTAs/SM, 4 warps 2x2 (64x64/warp).
// Per k8: 4 A-ldsm.x4 + 4 B-ldsm.x4 -> 32 mma.m16n8k8.
// ============================================================
#define TOFF_A 0
#define TOFF_B (128*128)         // 16384 B
#define TSTAGE (2*128*128)       // 32768 B
#define TGSMEM (3*TSTAGE)        // 98304 B
#define GT 128

struct GemmPtrs {
    const float* B[3];
    const float* bias[3];
    bf16* Ch[3];
    bf16* Cl[3];
    float* C[3];
};

__device__ __forceinline__ void t_load_tile(uint32_t sbase, const float* g,
                                            int row0, int k0, int tid)
{
    const char* gp = (const char*)(g + (size_t)row0 * Hsz + k0);
    #pragma unroll
    for (int c = tid; c < 1024; c += GT) {
        int row = c >> 3, ch = c & 7;
        CP_ASYNC16(sbase + swzf(row, ch), gp + (size_t)row * (Hsz * 4) + ch * 16);
    }
}
__device__ __forceinline__ void t_load_stage(uint32_t st, const float* A, const float* B,
                                             int bm, int bn, int k0, int tid)
{
    t_load_tile(st + TOFF_A, A, bm, k0, tid);
    t_load_tile(st + TOFF_B, B, bn, k0, tid);
}

template <bool BF16OUT>
__global__ void __launch_bounds__(GT, 2)
gemm_tf32(const float* __restrict__ A, GemmPtrs p)
{
    extern __shared__ __align__(128) char sm[];
    const uint32_t sb = smem_u32(sm);
    const int tid  = threadIdx.x;
    const int lane = tid & 31;
    const int wid  = tid >> 5;
    const int wm   = wid >> 1;
    const int wn   = wid & 1;
    const int region = blockIdx.x >> 4;
    const int bm = blockIdx.y * 128;
    const int bn = (blockIdx.x & 15) * 128;
    const float* Bm = p.B[region];

    float acc[4][8][4];
    #pragma unroll
    for (int i = 0; i < 4; i++)
        #pragma unroll
        for (int j = 0; j < 8; j++)
            #pragma unroll
            for (int t = 0; t < 4; t++) acc[i][j][t] = 0.f;

    t_load_stage(sb,          A, Bm, bm, bn, 0,  tid); CP_COMMIT();
    t_load_stage(sb + TSTAGE, A, Bm, bm, bn, 32, tid); CP_COMMIT();

    const int g  = lane >> 3;      // ldmatrix address group (matrix index)
    const int t8 = lane & 7;       // row within matrix

    for (int kt = 0; kt < 64; kt++) {
        if (kt < 63) { CP_WAIT(1); } else { CP_WAIT(0); }
        __syncthreads();

        if (kt + 2 < 64) {
            t_load_stage(sb + ((kt + 2) % 3) * TSTAGE, A, Bm, bm, bn, (kt + 2) * 32, tid);
            CP_COMMIT();
        }

        const uint32_t st = sb + (kt % 3) * TSTAGE;
        #pragma unroll
        for (int kk = 0; kk < 4; kk++) {           // four k8 steps in BK=32
            // A fragments: x4 matrices {m0-7,k0-3},{m8-15,k0-3},{m0-7,k4-7},{m8-15,k4-7}
            uint32_t af[4][4];
            #pragma unroll
            for (int mi = 0; mi < 4; mi++) {
                int row = wm * 64 + mi * 16 + t8 + ((g & 1) << 3);
                int ch  = kk * 2 + (g >> 1);
                ldsm4(af[mi], st + TOFF_A + swzf(row, ch));
            }
            // B fragments: x4 covers n-tiles 2pj,2pj+1 (lo/hi k-halves)
            uint32_t bfr[4][4];
            #pragma unroll
            for (int pj = 0; pj < 4; pj++) {
                int row = wn * 64 + (2 * pj + (g >> 1)) * 8 + t8;
                int ch  = kk * 2 + (g & 1);
                ldsm4(bfr[pj], st + TOFF_B + swzf(row, ch));
            }
            #pragma unroll
            for (int mi = 0; mi < 4; mi++) {
                #pragma unroll
                for (int nj = 0; nj < 8; nj++) {
                    const uint32_t* bp = bfr[nj >> 1] + (nj & 1) * 2;
                    mma1688t(acc[mi][nj], af[mi], bp[0], bp[1]);
                }
            }
        }
    }

    const int rbase = bm + wm * 64 + (lane >> 2);
    const int cbase = bn + wn * 64 + (lane & 3) * 2;
    const float* bias = p.bias[region];
    #pragma unroll
    for (int mi = 0; mi < 4; mi++) {
        #pragma unroll
        for (int nj = 0; nj < 8; nj++) {
            int row = rbase + mi * 16;
            int col = cbase + nj * 8;
            float b0 = __ldg(&bias[col]), b1 = __ldg(&bias[col + 1]);
            float* c = acc[mi][nj];
            float v00 = c[0] + b0, v01 = c[1] + b1;
            float v10 = c[2] + b0, v11 = c[3] + b1;
            if (BF16OUT) {
                bf16* Ch = p.Ch[region];
                bf16* Cl = p.Cl[region];
                uint32_t h, l;
                split2(v00, v01, h, l);
                *(uint32_t*)(Ch + (size_t)row * Hsz + col) = h;
                *(uint32_t*)(Cl + (size_t)row * Hsz + col) = l;
                split2(v10, v11, h, l);
                *(uint32_t*)(Ch + (size_t)(row + 8) * Hsz + col) = h;
                *(uint32_t*)(Cl + (size_t)(row + 8) * Hsz + col) = l;
            } else {
                float* C = p.C[region];
                *(float2*)(C + (size_t)row * Hsz + col) = make_float2(v00, v01);
                *(float2*)(C + (size_t)(row + 8) * Hsz + col) = make_float2(v10, v11);
            }
        }
    }
}

// ============================================================
// Flash attention via mma.sync, 3-pass split on QK and PV.
// BQ=64, BKV=64, 128 threads (4 warps x 16 query rows), 2 CTAs/SM.
// Epilogue: RNA-rounded fp32 AO (feeds tf32 O-proj).
// ============================================================
#define VST 272
#define AKH 0
#define AKL (64*VST)
#define AVH (2*64*VST)
#define AVL (3*64*VST)
#define ASMEM (4*64*VST)
#define FT 128

__device__ __forceinline__ void fa_load64(uint32_t sbase, const bf16* g, size_t gelem, int tid) {
    const char* gp = (const char*)(g + gelem);
    #pragma unroll
    for (int c = tid; c < 1024; c += FT) {
        int r = c >> 4, ch = c & 15;
        CP_ASYNC16(sbase + r * VST + ch * 16, gp + (size_t)r * (Hsz * 2) + ch * 16);
    }
}

__global__ void __launch_bounds__(FT, 2)
flash_mma(const bf16* __restrict__ Qh, const bf16* __restrict__ Ql,
          const bf16* __restrict__ Kh, const bf16* __restrict__ Kl,
          const bf16* __restrict__ Vh, const bf16* __restrict__ Vl,
          float* __restrict__ AO)
{
    extern __shared__ __align__(128) char sm[];
    const uint32_t sb = smem_u32(sm);
    const int tid = threadIdx.x;
    const int lane = tid & 31;
    const int w = tid >> 5;
    const int wrow = w * 16;
    const int qb = gridDim.x - 1 - blockIdx.x;   // heavy-first
    const int h = blockIdx.y, b = blockIdx.z;
    const int q0 = qb * 64;
    const size_t baseKV = (size_t)(b * Ssz) * Hsz + h * HDIM;
    const size_t baseQ  = baseKV + (size_t)q0 * Hsz;

    const int a_row = lane & 15;
    const int a_kb  = (lane >> 4) * 16;
    const int b_row = ((lane >> 4) & 1) * 8 + (lane & 7);
    const int b_kb  = ((lane >> 3) & 1) * 16;
    const int t_row = lane & 15;
    const int t_cb  = (lane >> 4) * 16;

    uint32_t qfh[8][4], qfl[8][4];
    fa_load64(sb, Qh, baseQ, tid); CP_COMMIT(); CP_WAIT(0); __syncthreads();
    #pragma unroll
    for (int t = 0; t < 8; t++)
        ldsm4(qfh[t], sb + (uint32_t)((wrow + a_row) * VST + a_kb + t * 32));
    __syncthreads();
    fa_load64(sb, Ql, baseQ, tid); CP_COMMIT(); CP_WAIT(0); __syncthreads();
    #pragma unroll
    for (int t = 0; t < 8; t++)
        ldsm4(qfl[t], sb + (uint32_t)((wrow + a_row) * VST + a_kb + t * 32));
    __syncthreads();

    fa_load64(sb + AKH, Kh, baseKV, tid);
    fa_load64(sb + AKL, Kl, baseKV, tid);
    CP_COMMIT();

    float o[16][4];
    #pragma unroll
    for (int j = 0; j < 16; j++)
        #pragma unroll
        for (int t = 0; t < 4; t++) o[j][t] = 0.f;
    float m_i[2] = {-1e30f, -1e30f}, l_i[2] = {0.f, 0.f};

    const int ktmax = qb;
    const int r0 = lane >> 2;
    const float sc = 0.08838834764831845f;

    for (int kt = 0; kt <= ktmax; kt++) {
        fa_load64(sb + AVH, Vh, baseKV + (size_t)(kt * 64) * Hsz, tid);
        fa_load64(sb + AVL, Vl, baseKV + (size_t)(kt * 64) * Hsz, tid);
        CP_COMMIT();
        CP_WAIT(1);
        __syncthreads();

        float s[8][4];
        #pragma unroll
        for (int j = 0; j < 8; j++)
            #pragma unroll
            for (int t = 0; t < 4; t++) s[j][t] = 0.f;
        #pragma unroll
        for (int t = 0; t < 8; t++) {
            uint32_t kbh[4][4], kbl[4][4];
            #pragma unroll
            for (int pp = 0; pp < 4; pp++) {
                uint32_t ra = (uint32_t)((pp * 16 + b_row) * VST + b_kb + t * 32);
                ldsm4(kbh[pp], sb + AKH + ra);
                ldsm4(kbl[pp], sb + AKL + ra);
            }
            #pragma unroll
            for (int pp = 0; pp < 4; pp++) {
                #pragma unroll
                for (int hh = 0; hh < 2; hh++) {
                    mma16816(s[2*pp+hh], qfh[t], kbh[pp][hh*2], kbh[pp][hh*2+1]);
                    mma16816(s[2*pp+hh], qfh[t], kbl[pp][hh*2], kbl[pp][hh*2+1]);
                    mma16816(s[2*pp+hh], qfl[t], kbh[pp][hh*2], kbh[pp][hh*2+1]);
                }
            }
        }
        __syncthreads();

        const bool more = kt < ktmax;
        if (more) {
            fa_load64(sb + AKH, Kh, baseKV + (size_t)((kt + 1) * 64) * Hsz, tid);
            fa_load64(sb + AKL, Kl, baseKV + (size_t)((kt + 1) * 64) * Hsz, tid);
            CP_COMMIT();
        }

        uint32_t pah[4][4], pal[4][4];
        float fac[2];
        {
            #pragma unroll
            for (int j = 0; j < 8; j++)
                #pragma unroll
                for (int t = 0; t < 4; t++) s[j][t] *= sc;
            if (kt == ktmax) {
                #pragma unroll
                for (int j = 0; j < 8; j++) {
                    int col = kt * 64 + j * 8 + (lane & 3) * 2;
                    int row = q0 + wrow + r0;
                    if (col > row)          s[j][0] = -1e30f;
                    if (col + 1 > row)      s[j][1] = -1e30f;
                    if (col > row + 8)      s[j][2] = -1e30f;
                    if (col + 1 > row + 8)  s[j][3] = -1e30f;
                }
            }
            #pragma unroll
            for (int r = 0; r < 2; r++) {
                float rm = -1e30f;
                #pragma unroll
                for (int j = 0; j < 8; j++) rm = fmaxf(rm, fmaxf(s[j][r*2], s[j][r*2+1]));
                rm = fmaxf(rm, __shfl_xor_sync(0xffffffffu, rm, 1));
                rm = fmaxf(rm, __shfl_xor_sync(0xffffffffu, rm, 2));
                float mn = fmaxf(m_i[r], rm);
                fac[r] = __expf(m_i[r] - mn);
                float rs = 0.f;
                #pragma unroll
                for (int j = 0; j < 8; j++) {
                    s[j][r*2]   = __expf(s[j][r*2]   - mn);
                    s[j][r*2+1] = __expf(s[j][r*2+1] - mn);
                    rs += s[j][r*2] + s[j][r*2+1];
                }
                rs += __shfl_xor_sync(0xffffffffu, rs, 1);
                rs += __shfl_xor_sync(0xffffffffu, rs, 2);
                l_i[r] = l_i[r] * fac[r] + rs;
                m_i[r] = mn;
            }
            #pragma unroll
            for (int t2 = 0; t2 < 4; t2++) {
                split2(s[2*t2][0],   s[2*t2][1],   pah[t2][0], pal[t2][0]);
                split2(s[2*t2][2],   s[2*t2][3],   pah[t2][1], pal[t2][1]);
                split2(s[2*t2+1][0], s[2*t2+1][1], pah[t2][2], pal[t2][2]);
                split2(s[2*t2+1][2], s[2*t2+1][3], pah[t2][3], pal[t2][3]);
            }
            #pragma unroll
            for (int j = 0; j < 16; j++) {
                o[j][0] *= fac[0]; o[j][1] *= fac[0];
                o[j][2] *= fac[1]; o[j][3] *= fac[1];
            }
        }

        if (more) { CP_WAIT(1); } else { CP_WAIT(0); }
        __syncthreads();

        #pragma unroll
        for (int j2 = 0; j2 < 8; j2++) {
            #pragma unroll
            for (int t = 0; t < 4; t++) {
                uint32_t bvh[4], bvl[4];
                uint32_t ra = (uint32_t)((t * 16 + t_row) * VST + t_cb + j2 * 32);
                ldsm4t(bvh, sb + AVH + ra);
                ldsm4t(bvl, sb + AVL + ra);
                mma16816(o[2*j2],   pah[t], bvh[0], bvh[1]);
                mma16816(o[2*j2+1], pah[t], bvh[2], bvh[3]);
                mma16816(o[2*j2],   pah[t], bvl[0], bvl[1]);
                mma16816(o[2*j2+1], pah[t], bvl[2], bvl[3]);
                mma16816(o[2*j2],   pal[t], bvh[0], bvh[1]);
                mma16816(o[2*j2+1], pal[t], bvh[2], bvh[3]);
            }
        }
        __syncthreads();
    }

    // epilogue: normalize + RNA-round to tf32-exact fp32 (input of O-proj)
    const float inv0 = 1.0f / l_i[0], inv1 = 1.0f / l_i[1];
    const int grow0 = q0 + wrow + r0;
    #pragma unroll
    for (int j = 0; j < 16; j++) {
        int col = j * 8 + (lane & 3) * 2;
        size_t e0 = baseKV + (size_t)grow0 * Hsz + col;
        size_t e1 = baseKV + (size_t)(grow0 + 8) * Hsz + col;
        *(float2*)(AO + e0) = make_float2(rna_tf32(o[j][0] * inv0), rna_tf32(o[j][1] * inv0));
        *(float2*)(AO + e1) = make_float2(rna_tf32(o[j][2] * inv1), rna_tf32(o[j][3] * inv1));
    }
}

// ============================================================
extern "C" void kernel_launch(void* const* d_in, const int* in_sizes, int n_in,
                              void* d_out, int out_size) {
    const float* x  = (const float*)d_in[0];
    const float* Wf[4] = { (const float*)d_in[1], (const float*)d_in[3],
                           (const float*)d_in[5], (const float*)d_in[7] };
    const float* bQ = (const float*)d_in[2];
    const float* bK = (const float*)d_in[4];
    const float* bV = (const float*)d_in[6];
    const float* bO = (const float*)d_in[8];
    float* out = (float*)d_out;

    float *xt, *wt, *ao;
    bf16 *qh, *ql, *kh, *kl, *vh, *vl;
    cudaGetSymbolAddress((void**)&xt, g_xt);
    cudaGetSymbolAddress((void**)&wt, g_wt);
    cudaGetSymbolAddress((void**)&ao, g_ao);
    cudaGetSymbolAddress((void**)&qh, g_qh);  cudaGetSymbolAddress((void**)&ql, g_ql);
    cudaGetSymbolAddress((void**)&kh, g_kh);  cudaGetSymbolAddress((void**)&kl, g_kl);
    cudaGetSymbolAddress((void**)&vh, g_vh);  cudaGetSymbolAddress((void**)&vl, g_vl);

    const size_t HH = (size_t)Hsz * Hsz;

    // Launch 1: RNA-round x + weights into tf32-exact fp32 copies
    PrepJobs pj;
    pj.in[0]  = (const float4*)x;
    pj.out[0] = (float4*)xt;
    pj.n4[0]  = Mrows * Hsz / 4;
    pj.blk0[0] = 0;
    for (int i = 0; i < 4; i++) {
        pj.in[i+1]  = (const float4*)Wf[i];
        pj.out[i+1] = (float4*)(wt + i * HH);
        pj.n4[i+1]  = Hsz * Hsz / 4;
        pj.blk0[i+1] = 768 + i * 384;
    }
    const int totblk = 768 + 4 * 384;   // 2304
    prep_tf32<<<totblk, 256>>>(pj, totblk);

    cudaFuncSetAttribute(gemm_tf32<true>,  cudaFuncAttributeMaxDynamicSharedMemorySize, TGSMEM);
    cudaFuncSetAttribute(gemm_tf32<false>, cudaFuncAttributeMaxDynamicSharedMemorySize, TGSMEM);

    // Launch 2: fused QKV tf32 GEMM (bf16 hi/lo outputs for flash)
    GemmPtrs pq;
    pq.B[0] = wt;           pq.B[1] = wt + HH;      pq.B[2] = wt + 2 * HH;
    pq.bias[0] = bQ;        pq.bias[1] = bK;        pq.bias[2] = bV;
    pq.Ch[0] = qh;          pq.Ch[1] = kh;          pq.Ch[2] = vh;
    pq.Cl[0] = ql;          pq.Cl[1] = kl;          pq.Cl[2] = vl;
    pq.C[0] = pq.C[1] = pq.C[2] = nullptr;
    gemm_tf32<true><<<dim3(48, Mrows / 128), GT, TGSMEM>>>(xt, pq);

    // Launch 3: attention (bf16 3-pass, unchanged numerics)
    cudaFuncSetAttribute(flash_mma, cudaFuncAttributeMaxDynamicSharedMemorySize, ASMEM);
    flash_mma<<<dim3(Ssz / 64, NHEAD, Bsz), FT, ASMEM>>>(qh, ql, kh, kl, vh, vl, ao);

    // Launch 4: output projection (tf32, fp32 out)
    GemmPtrs po;
    po.B[0] = wt + 3 * HH;  po.B[1] = po.B[2] = nullptr;
    po.bias[0] = bO;        po.bias[1] = po.bias[2] = nullptr;
    po.Ch[0] = po.Ch[1] = po.Ch[2] = nullptr;
    po.Cl[0] = po.Cl[1] = po.Cl[2] = nullptr;
    po.C[0] = out;          po.C[1] = po.C[2] = nullptr;
    gemm_tf32<false><<<dim3(16, Mrows / 128), GT, TGSMEM>>>(ao, po);
}

// round 12
// speedup vs baseline: 1.7012x; 1.0301x over previous
#include <cuda_runtime.h>
#include <cuda_bf16.h>
#include <cstdint>

// Problem dims
#define Bsz   2
#define Ssz   2048
#define Hsz   2048
#define NHEAD 16
#define HDIM  128
#define Mrows (Bsz*Ssz)   // 4096

typedef __nv_bfloat16 bf16;

// ---------------- scratch (static device globals) ----------------
__device__ float g_xt [Mrows*Hsz];          // RNA-rounded x
__device__ float g_wt [4][Hsz*Hsz];         // RNA-rounded weights
__device__ float g_ao [Mrows*Hsz];          // attention out (RNA-rounded)
__device__ bf16 g_qh [Mrows*Hsz], g_ql [Mrows*Hsz];
__device__ bf16 g_kh [Mrows*Hsz], g_kl [Mrows*Hsz];
__device__ bf16 g_vh [Mrows*Hsz], g_vl [Mrows*Hsz];

// ---------------- helpers ----------------
__device__ __forceinline__ uint32_t smem_u32(const void* p) {
    uint32_t a;
    asm("{ .reg .u64 t; cvta.to.shared.u64 t, %1; cvt.u32.u64 %0, t; }" : "=r"(a) : "l"(p));
    return a;
}
#define CP_ASYNC16(sa, ga) \
    asm volatile("cp.async.cg.shared.global [%0], [%1], 16;" :: "r"((uint32_t)(sa)), "l"(ga))
#define CP_COMMIT() asm volatile("cp.async.commit_group;" ::: "memory")
#define CP_WAIT(n)  asm volatile("cp.async.wait_group %0;" :: "n"(n) : "memory")

__device__ __forceinline__ void ldsm4(uint32_t* r, uint32_t addr) {
    asm volatile("ldmatrix.sync.aligned.m8n8.x4.shared.b16 {%0,%1,%2,%3}, [%4];"
                 : "=r"(r[0]), "=r"(r[1]), "=r"(r[2]), "=r"(r[3]) : "r"(addr));
}
__device__ __forceinline__ void ldsm4t(uint32_t* r, uint32_t addr) {
    asm volatile("ldmatrix.sync.aligned.m8n8.x4.trans.shared.b16 {%0,%1,%2,%3}, [%4];"
                 : "=r"(r[0]), "=r"(r[1]), "=r"(r[2]), "=r"(r[3]) : "r"(addr));
}
// bf16 mma (flash)
__device__ __forceinline__ void mma16816(float* c, const uint32_t* a,
                                         uint32_t b0, uint32_t b1) {
    asm volatile(
        "mma.sync.aligned.m16n8k16.row.col.f32.bf16.bf16.f32 "
        "{%0,%1,%2,%3}, {%4,%5,%6,%7}, {%8,%9}, {%0,%1,%2,%3};"
        : "+f"(c[0]), "+f"(c[1]), "+f"(c[2]), "+f"(c[3])
        : "r"(a[0]), "r"(a[1]), "r"(a[2]), "r"(a[3]), "r"(b0), "r"(b1));
}
// tf32 mma (projections)
__device__ __forceinline__ void mma1688t(float* c, const uint32_t* a,
                                         uint32_t b0, uint32_t b1) {
    asm volatile(
        "mma.sync.aligned.m16n8k8.row.col.f32.tf32.tf32.f32 "
        "{%0,%1,%2,%3}, {%4,%5,%6,%7}, {%8,%9}, {%0,%1,%2,%3};"
        : "+f"(c[0]), "+f"(c[1]), "+f"(c[2]), "+f"(c[3])
        : "r"(a[0]), "r"(a[1]), "r"(a[2]), "r"(a[3]), "r"(b0), "r"(b1));
}
__device__ __forceinline__ void split2(float a, float b, uint32_t& hi, uint32_t& lo) {
    bf16 ha = __float2bfloat16(a), hb = __float2bfloat16(b);
    bf16 la = __float2bfloat16(a - __bfloat162float(ha));
    bf16 lb = __float2bfloat16(b - __bfloat162float(hb));
    __nv_bfloat162 h(ha, hb), l(la, lb);
    hi = *(uint32_t*)&h; lo = *(uint32_t*)&l;
}
// cheap truncation split: hi = packed high-16 bits (RZ bf16), lo = residual RN bf16x2
__device__ __forceinline__ void split2t(float a, float b, uint32_t& hi, uint32_t& lo) {
    uint32_t ia = __float_as_uint(a), ib = __float_as_uint(b);
    hi = __byte_perm(ia, ib, 0x7632);          // {bf16(a) lo-half, bf16(b) hi-half}
    float fa = __uint_as_float(ia & 0xFFFF0000u);
    float fb = __uint_as_float(ib & 0xFFFF0000u);
    float la = a - fa, lb = b - fb;
    asm("cvt.rn.bf16x2.f32 %0, %1, %2;" : "=r"(lo) : "f"(lb), "f"(la));
}
// RNA round to tf32-exact fp32. tf32 lives in b32 registers in PTX -> "=r".
__device__ __forceinline__ float rna_tf32(float v) {
    uint32_t o;
    asm("cvt.rna.tf32.f32 %0, %1;" : "=r"(o) : "f"(v));
    return __uint_as_float(o);
}
// 16B-chunk XOR swizzle for 32-float (128B) rows: chunk 0..7, rows 0..127
__device__ __forceinline__ uint32_t swzf(int row, int chunk) {
    return (uint32_t)(row * 128 + ((chunk ^ (row & 7)) << 4));
}

// ============================================================
// Prep: RNA-round fp32 -> tf32-exact fp32 copies (x + 4 weights)
// ============================================================
struct PrepJobs {
    const float4* in[5];
    float4* out[5];
    int n4[5];
    int blk0[5];
};

__global__ void prep_tf32(PrepJobs j, int totblk)
{
    int r = 0;
    #pragma unroll
    for (int i = 1; i < 5; i++) if ((int)blockIdx.x >= j.blk0[i]) r = i;
    const int rel  = blockIdx.x - j.blk0[r];
    const int nblk = ((r + 1 < 5) ? j.blk0[r + 1] : totblk) - j.blk0[r];
    const float4* in = j.in[r];
    float4* out = j.out[r];
    const int n4 = j.n4[r];
    for (int i = rel * blockDim.x + threadIdx.x; i < n4; i += nblk * blockDim.x) {
        float4 v = in[i];
        v.x = rna_tf32(v.x); v.y = rna_tf32(v.y);
        v.z = rna_tf32(v.z); v.w = rna_tf32(v.w);
        out[i] = v;
    }
}

// ============================================================
// tf32 GEMM: C[M,N] = A @ B^T + bias.  CTA 128x128, BK=32,
// 3-stage cp.async, 1 sync/iter, 2 CTAs/SM, 4 warps 2x2 (64x64/warp).
// ============================================================
#define TOFF_A 0
#define TOFF_B (128*128)         // 16384 B
#define TSTAGE (2*128*128)       // 32768 B
#define TGSMEM (3*TSTAGE)        // 98304 B
#define GT 128

struct GemmPtrs {
    const float* B[3];
    const float* bias[3];
    bf16* Ch[3];
    bf16* Cl[3];
    float* C[3];
};

__device__ __forceinline__ void t_load_tile(uint32_t sbase, const float* g,
                                            int row0, int k0, int tid)
{
    const char* gp = (const char*)(g + (size_t)row0 * Hsz + k0);
    #pragma unroll
    for (int c = tid; c < 1024; c += GT) {
        int row = c >> 3, ch = c & 7;
        CP_ASYNC16(sbase + swzf(row, ch), gp + (size_t)row * (Hsz * 4) + ch * 16);
    }
}
__device__ __forceinline__ void t_load_stage(uint32_t st, const float* A, const float* B,
                                             int bm, int bn, int k0, int tid)
{
    t_load_tile(st + TOFF_A, A, bm, k0, tid);
    t_load_tile(st + TOFF_B, B, bn, k0, tid);
}

template <bool BF16OUT>
__global__ void __launch_bounds__(GT, 2)
gemm_tf32(const float* __restrict__ A, GemmPtrs p)
{
    extern __shared__ __align__(128) char sm[];
    const uint32_t sb = smem_u32(sm);
    const int tid  = threadIdx.x;
    const int lane = tid & 31;
    const int wid  = tid >> 5;
    const int wm   = wid >> 1;
    const int wn   = wid & 1;
    const int region = blockIdx.x >> 4;
    const int bm = blockIdx.y * 128;
    const int bn = (blockIdx.x & 15) * 128;
    const float* Bm = p.B[region];

    float acc[4][8][4];
    #pragma unroll
    for (int i = 0; i < 4; i++)
        #pragma unroll
        for (int j = 0; j < 8; j++)
            #pragma unroll
            for (int t = 0; t < 4; t++) acc[i][j][t] = 0.f;

    t_load_stage(sb,          A, Bm, bm, bn, 0,  tid); CP_COMMIT();
    t_load_stage(sb + TSTAGE, A, Bm, bm, bn, 32, tid); CP_COMMIT();

    const int g  = lane >> 3;
    const int t8 = lane & 7;

    for (int kt = 0; kt < 64; kt++) {
        if (kt < 63) { CP_WAIT(1); } else { CP_WAIT(0); }
        __syncthreads();

        if (kt + 2 < 64) {
            t_load_stage(sb + ((kt + 2) % 3) * TSTAGE, A, Bm, bm, bn, (kt + 2) * 32, tid);
            CP_COMMIT();
        }

        const uint32_t st = sb + (kt % 3) * TSTAGE;
        #pragma unroll
        for (int kk = 0; kk < 4; kk++) {
            uint32_t af[4][4];
            #pragma unroll
            for (int mi = 0; mi < 4; mi++) {
                int row = wm * 64 + mi * 16 + t8 + ((g & 1) << 3);
                int ch  = kk * 2 + (g >> 1);
                ldsm4(af[mi], st + TOFF_A + swzf(row, ch));
            }
            uint32_t bfr[4][4];
            #pragma unroll
            for (int pj = 0; pj < 4; pj++) {
                int row = wn * 64 + (2 * pj + (g >> 1)) * 8 + t8;
                int ch  = kk * 2 + (g & 1);
                ldsm4(bfr[pj], st + TOFF_B + swzf(row, ch));
            }
            #pragma unroll
            for (int mi = 0; mi < 4; mi++) {
                #pragma unroll
                for (int nj = 0; nj < 8; nj++) {
                    const uint32_t* bp = bfr[nj >> 1] + (nj & 1) * 2;
                    mma1688t(acc[mi][nj], af[mi], bp[0], bp[1]);
                }
            }
        }
    }

    const int rbase = bm + wm * 64 + (lane >> 2);
    const int cbase = bn + wn * 64 + (lane & 3) * 2;
    const float* bias = p.bias[region];
    #pragma unroll
    for (int mi = 0; mi < 4; mi++) {
        #pragma unroll
        for (int nj = 0; nj < 8; nj++) {
            int row = rbase + mi * 16;
            int col = cbase + nj * 8;
            float b0 = __ldg(&bias[col]), b1 = __ldg(&bias[col + 1]);
            float* c = acc[mi][nj];
            float v00 = c[0] + b0, v01 = c[1] + b1;
            float v10 = c[2] + b0, v11 = c[3] + b1;
            if (BF16OUT) {
                bf16* Ch = p.Ch[region];
                bf16* Cl = p.Cl[region];
                uint32_t h, l;
                split2(v00, v01, h, l);
                *(uint32_t*)(Ch + (size_t)row * Hsz + col) = h;
                *(uint32_t*)(Cl + (size_t)row * Hsz + col) = l;
                split2(v10, v11, h, l);
                *(uint32_t*)(Ch + (size_t)(row + 8) * Hsz + col) = h;
                *(uint32_t*)(Cl + (size_t)(row + 8) * Hsz + col) = l;
            } else {
                float* C = p.C[region];
                *(float2*)(C + (size_t)row * Hsz + col) = make_float2(v00, v01);
                *(float2*)(C + (size_t)(row + 8) * Hsz + col) = make_float2(v10, v11);
            }
        }
    }
}

// ============================================================
// Flash attention via mma.sync, 3-pass split on QK and PV.
// BQ=64, BKV=64, 128 threads (4 warps x 16 query rows), 2 CTAs/SM.
// V double-buffered -> 2 syncs/iter, no softmax->PV wait.
// exp2-domain softmax; truncation split for P.
// ============================================================
#define VST 272
#define AKH 0
#define AKL (64*VST)
#define AVB (2*64*VST)            // V buffer region base
#define VBUF (2*64*VST)           // one V buffer (h+l)
#define ASMEM (6*64*VST)          // 104448 per CTA, 2 CTAs/SM
#define FT 128

__device__ __forceinline__ void fa_load64(uint32_t sbase, const bf16* g, size_t gelem, int tid) {
    const char* gp = (const char*)(g + gelem);
    #pragma unroll
    for (int c = tid; c < 1024; c += FT) {
        int r = c >> 4, ch = c & 15;
        CP_ASYNC16(sbase + r * VST + ch * 16, gp + (size_t)r * (Hsz * 2) + ch * 16);
    }
}

__global__ void __launch_bounds__(FT, 2)
flash_mma(const bf16* __restrict__ Qh, const bf16* __restrict__ Ql,
          const bf16* __restrict__ Kh, const bf16* __restrict__ Kl,
          const bf16* __restrict__ Vh, const bf16* __restrict__ Vl,
          float* __restrict__ AO)
{
    extern __shared__ __align__(128) char sm[];
    const uint32_t sb = smem_u32(sm);
    const int tid = threadIdx.x;
    const int lane = tid & 31;
    const int w = tid >> 5;
    const int wrow = w * 16;
    const int qb = gridDim.x - 1 - blockIdx.x;   // heavy-first
    const int h = blockIdx.y, b = blockIdx.z;
    const int q0 = qb * 64;
    const size_t baseKV = (size_t)(b * Ssz) * Hsz + h * HDIM;
    const size_t baseQ  = baseKV + (size_t)q0 * Hsz;

    const int a_row = lane & 15;
    const int a_kb  = (lane >> 4) * 16;
    const int b_row = ((lane >> 4) & 1) * 8 + (lane & 7);
    const int b_kb  = ((lane >> 3) & 1) * 16;
    const int t_row = lane & 15;
    const int t_cb  = (lane >> 4) * 16;

    // ---- load Q fragments (hi then lo), staged through the K buffer ----
    uint32_t qfh[8][4], qfl[8][4];
    fa_load64(sb, Qh, baseQ, tid); CP_COMMIT(); CP_WAIT(0); __syncthreads();
    #pragma unroll
    for (int t = 0; t < 8; t++)
        ldsm4(qfh[t], sb + (uint32_t)((wrow + a_row) * VST + a_kb + t * 32));
    __syncthreads();
    fa_load64(sb, Ql, baseQ, tid); CP_COMMIT(); CP_WAIT(0); __syncthreads();
    #pragma unroll
    for (int t = 0; t < 8; t++)
        ldsm4(qfl[t], sb + (uint32_t)((wrow + a_row) * VST + a_kb + t * 32));
    __syncthreads();

    // prologue: V(0) into vbuf0, K(0)
    fa_load64(sb + AVB,           Vh, baseKV, tid);
    fa_load64(sb + AVB + 64*VST,  Vl, baseKV, tid);
    CP_COMMIT();
    fa_load64(sb + AKH, Kh, baseKV, tid);
    fa_load64(sb + AKL, Kl, baseKV, tid);
    CP_COMMIT();

    float o[16][4];
    #pragma unroll
    for (int j = 0; j < 16; j++)
        #pragma unroll
        for (int t = 0; t < 4; t++) o[j][t] = 0.f;
    float m_i[2] = {-1e30f, -1e30f}, l_i[2] = {0.f, 0.f};

    const int ktmax = qb;
    const int r0 = lane >> 2;
    const float sc2 = 0.1275174112f;   // (1/sqrt(128)) * log2(e)

    for (int kt = 0; kt <= ktmax; kt++) {
        CP_WAIT(0);                // K(kt) and V(kt) complete
        __syncthreads();           // + all warps done with PV(kt-1) (vbuf[(kt+1)&1])

        // prefetch V(kt+1) into the buffer PV(kt-1) just finished with
        if (kt < ktmax) {
            uint32_t vb = sb + AVB + ((kt + 1) & 1) * VBUF;
            fa_load64(vb,           Vh, baseKV + (size_t)((kt + 1) * 64) * Hsz, tid);
            fa_load64(vb + 64*VST,  Vl, baseKV + (size_t)((kt + 1) * 64) * Hsz, tid);
            CP_COMMIT();
        }

        // ---- QK ----
        float s[8][4];
        #pragma unroll
        for (int j = 0; j < 8; j++)
            #pragma unroll
            for (int t = 0; t < 4; t++) s[j][t] = 0.f;
        #pragma unroll
        for (int t = 0; t < 8; t++) {
            uint32_t kbh[4][4], kbl[4][4];
            #pragma unroll
            for (int pp = 0; pp < 4; pp++) {
                uint32_t ra = (uint32_t)((pp * 16 + b_row) * VST + b_kb + t * 32);
                ldsm4(kbh[pp], sb + AKH + ra);
                ldsm4(kbl[pp], sb + AKL + ra);
            }
            #pragma unroll
            for (int pp = 0; pp < 4; pp++) {
                #pragma unroll
                for (int hh = 0; hh < 2; hh++) {
                    mma16816(s[2*pp+hh], qfh[t], kbh[pp][hh*2], kbh[pp][hh*2+1]);
                    mma16816(s[2*pp+hh], qfh[t], kbl[pp][hh*2], kbl[pp][hh*2+1]);
                    mma16816(s[2*pp+hh], qfl[t], kbh[pp][hh*2], kbh[pp][hh*2+1]);
                }
            }
        }
        __syncthreads();           // K buffer free

        if (kt < ktmax) {
            fa_load64(sb + AKH, Kh, baseKV + (size_t)((kt + 1) * 64) * Hsz, tid);
            fa_load64(sb + AKL, Kl, baseKV + (size_t)((kt + 1) * 64) * Hsz, tid);
            CP_COMMIT();
        }

        // ---- softmax (exp2 domain) ----
        uint32_t pah[4][4], pal[4][4];
        float fac[2];
        {
            #pragma unroll
            for (int j = 0; j < 8; j++)
                #pragma unroll
                for (int t = 0; t < 4; t++) s[j][t] *= sc2;
            if (kt == ktmax) {
                #pragma unroll
                for (int j = 0; j < 8; j++) {
                    int col = kt * 64 + j * 8 + (lane & 3) * 2;
                    int row = q0 + wrow + r0;
                    if (col > row)          s[j][0] = -1e30f;
                    if (col + 1 > row)      s[j][1] = -1e30f;
                    if (col > row + 8)      s[j][2] = -1e30f;
                    if (col + 1 > row + 8)  s[j][3] = -1e30f;
                }
            }
            #pragma unroll
            for (int r = 0; r < 2; r++) {
                float rm = -1e30f;
                #pragma unroll
                for (int j = 0; j < 8; j++) rm = fmaxf(rm, fmaxf(s[j][r*2], s[j][r*2+1]));
                rm = fmaxf(rm, __shfl_xor_sync(0xffffffffu, rm, 1));
                rm = fmaxf(rm, __shfl_xor_sync(0xffffffffu, rm, 2));
                float mn = fmaxf(m_i[r], rm);
                fac[r] = exp2f(m_i[r] - mn);
                float rs = 0.f;
                #pragma unroll
                for (int j = 0; j < 8; j++) {
                    s[j][r*2]   = exp2f(s[j][r*2]   - mn);
                    s[j][r*2+1] = exp2f(s[j][r*2+1] - mn);
                    rs += s[j][r*2] + s[j][r*2+1];
                }
                rs += __shfl_xor_sync(0xffffffffu, rs, 1);
                rs += __shfl_xor_sync(0xffffffffu, rs, 2);
                l_i[r] = l_i[r] * fac[r] + rs;
                m_i[r] = mn;
            }
            #pragma unroll
            for (int t2 = 0; t2 < 4; t2++) {
                split2t(s[2*t2][0],   s[2*t2][1],   pah[t2][0], pal[t2][0]);
                split2t(s[2*t2][2],   s[2*t2][3],   pah[t2][1], pal[t2][1]);
                split2t(s[2*t2+1][0], s[2*t2+1][1], pah[t2][2], pal[t2][2]);
                split2t(s[2*t2+1][2], s[2*t2+1][3], pah[t2][3], pal[t2][3]);
            }
            #pragma unroll
            for (int j = 0; j < 16; j++) {
                o[j][0] *= fac[0]; o[j][1] *= fac[0];
                o[j][2] *= fac[1]; o[j][3] *= fac[1];
            }
        }

        // ---- PV (V(kt) already resident in vbuf[kt&1]) ----
        const uint32_t vb = sb + AVB + (kt & 1) * VBUF;
        #pragma unroll
        for (int j2 = 0; j2 < 8; j2++) {
            #pragma unroll
            for (int t = 0; t < 4; t++) {
                uint32_t bvh[4], bvl[4];
                uint32_t ra = (uint32_t)((t * 16 + t_row) * VST + t_cb + j2 * 32);
                ldsm4t(bvh, vb + ra);
                ldsm4t(bvl, vb + 64*VST + ra);
                mma16816(o[2*j2],   pah[t], bvh[0], bvh[1]);
                mma16816(o[2*j2+1], pah[t], bvh[2], bvh[3]);
                mma16816(o[2*j2],   pah[t], bvl[0], bvl[1]);
                mma16816(o[2*j2+1], pah[t], bvl[2], bvl[3]);
                mma16816(o[2*j2],   pal[t], bvh[0], bvh[1]);
                mma16816(o[2*j2+1], pal[t], bvh[2], bvh[3]);
            }
        }
        // no trailing sync: next-iter top sync protects vbuf reuse
    }

    // epilogue: normalize + RNA-round to tf32-exact fp32 (input of O-proj)
    const float inv0 = 1.0f / l_i[0], inv1 = 1.0f / l_i[1];
    const int grow0 = q0 + wrow + r0;
    #pragma unroll
    for (int j = 0; j < 16; j++) {
        int col = j * 8 + (lane & 3) * 2;
        size_t e0 = baseKV + (size_t)grow0 * Hsz + col;
        size_t e1 = baseKV + (size_t)(grow0 + 8) * Hsz + col;
        *(float2*)(AO + e0) = make_float2(rna_tf32(o[j][0] * inv0), rna_tf32(o[j][1] * inv0));
        *(float2*)(AO + e1) = make_float2(rna_tf32(o[j][2] * inv1), rna_tf32(o[j][3] * inv1));
    }
}

// ============================================================
extern "C" void kernel_launch(void* const* d_in, const int* in_sizes, int n_in,
                              void* d_out, int out_size) {
    const float* x  = (const float*)d_in[0];
    const float* Wf[4] = { (const float*)d_in[1], (const float*)d_in[3],
                           (const float*)d_in[5], (const float*)d_in[7] };
    const float* bQ = (const float*)d_in[2];
    const float* bK = (const float*)d_in[4];
    const float* bV = (const float*)d_in[6];
    const float* bO = (const float*)d_in[8];
    float* out = (float*)d_out;

    float *xt, *wt, *ao;
    bf16 *qh, *ql, *kh, *kl, *vh, *vl;
    cudaGetSymbolAddress((void**)&xt, g_xt);
    cudaGetSymbolAddress((void**)&wt, g_wt);
    cudaGetSymbolAddress((void**)&ao, g_ao);
    cudaGetSymbolAddress((void**)&qh, g_qh);  cudaGetSymbolAddress((void**)&ql, g_ql);
    cudaGetSymbolAddress((void**)&kh, g_kh);  cudaGetSymbolAddress((void**)&kl, g_kl);
    cudaGetSymbolAddress((void**)&vh, g_vh);  cudaGetSymbolAddress((void**)&vl, g_vl);

    const size_t HH = (size_t)Hsz * Hsz;

    // Launch 1: RNA-round x + weights into tf32-exact fp32 copies
    PrepJobs pj;
    pj.in[0]  = (const float4*)x;
    pj.out[0] = (float4*)xt;
    pj.n4[0]  = Mrows * Hsz / 4;
    pj.blk0[0] = 0;
    for (int i = 0; i < 4; i++) {
        pj.in[i+1]  = (const float4*)Wf[i];
        pj.out[i+1] = (float4*)(wt + i * HH);
        pj.n4[i+1]  = Hsz * Hsz / 4;
        pj.blk0[i+1] = 768 + i * 384;
    }
    const int totblk = 768 + 4 * 384;   // 2304
    prep_tf32<<<totblk, 256>>>(pj, totblk);

    cudaFuncSetAttribute(gemm_tf32<true>,  cudaFuncAttributeMaxDynamicSharedMemorySize, TGSMEM);
    cudaFuncSetAttribute(gemm_tf32<false>, cudaFuncAttributeMaxDynamicSharedMemorySize, TGSMEM);

    // Launch 2: fused QKV tf32 GEMM (bf16 hi/lo outputs for flash)
    GemmPtrs pq;
    pq.B[0] = wt;           pq.B[1] = wt + HH;      pq.B[2] = wt + 2 * HH;
    pq.bias[0] = bQ;        pq.bias[1] = bK;        pq.bias[2] = bV;
    pq.Ch[0] = qh;          pq.Ch[1] = kh;          pq.Ch[2] = vh;
    pq.Cl[0] = ql;          pq.Cl[1] = kl;          pq.Cl[2] = vl;
    pq.C[0] = pq.C[1] = pq.C[2] = nullptr;
    gemm_tf32<true><<<dim3(48, Mrows / 128), GT, TGSMEM>>>(xt, pq);

    // Launch 3: attention (bf16 3-pass, V double-buffered)
    cudaFuncSetAttribute(flash_mma, cudaFuncAttributeMaxDynamicSharedMemorySize, ASMEM);
    flash_mma<<<dim3(Ssz / 64, NHEAD, Bsz), FT, ASMEM>>>(qh, ql, kh, kl, vh, vl, ao);

    // Launch 4: output projection (tf32, fp32 out)
    GemmPtrs po;
    po.B[0] = wt + 3 * HH;  po.B[1] = po.B[2] = nullptr;
    po.bias[0] = bO;        po.bias[1] = po.bias[2] = nullptr;
    po.Ch[0] = po.Ch[1] = po.Ch[2] = nullptr;
    po.Cl[0] = po.Cl[1] = po.Cl[2] = nullptr;
    po.C[0] = out;          po.C[1] = po.C[2] = nullptr;
    gemm_tf32<false><<<dim3(16, Mrows / 128), GT, TGSMEM>>>(ao, po);
}

// round 14
// speedup vs baseline: 1.7701x; 1.0405x over previous
#include <cuda_runtime.h>
#include <cuda_bf16.h>
#include <cstdint>

// Problem dims
#define Bsz   2
#define Ssz   2048
#define Hsz   2048
#define NHEAD 16
#define HDIM  128
#define Mrows (Bsz*Ssz)   // 4096

typedef __nv_bfloat16 bf16;

// ---------------- scratch (static device globals) ----------------
__device__ float g_xt [Mrows*Hsz];          // RNA-rounded x
__device__ float g_wt [4][Hsz*Hsz];         // RNA-rounded weights
__device__ float g_ao [Mrows*Hsz];          // attention out (RNA-rounded)
__device__ bf16 g_qh [Mrows*Hsz], g_ql [Mrows*Hsz];
__device__ bf16 g_kh [Mrows*Hsz], g_kl [Mrows*Hsz];
__device__ bf16 g_vh [Mrows*Hsz], g_vl [Mrows*Hsz];

// ---------------- helpers ----------------
__device__ __forceinline__ uint32_t smem_u32(const void* p) {
    uint32_t a;
    asm("{ .reg .u64 t; cvta.to.shared.u64 t, %1; cvt.u32.u64 %0, t; }" : "=r"(a) : "l"(p));
    return a;
}
#define CP_ASYNC16(sa, ga) \
    asm volatile("cp.async.cg.shared.global [%0], [%1], 16;" :: "r"((uint32_t)(sa)), "l"(ga))
#define CP_COMMIT() asm volatile("cp.async.commit_group;" ::: "memory")
#define CP_WAIT(n)  asm volatile("cp.async.wait_group %0;" :: "n"(n) : "memory")

__device__ __forceinline__ void ldsm4(uint32_t* r, uint32_t addr) {
    asm volatile("ldmatrix.sync.aligned.m8n8.x4.shared.b16 {%0,%1,%2,%3}, [%4];"
                 : "=r"(r[0]), "=r"(r[1]), "=r"(r[2]), "=r"(r[3]) : "r"(addr));
}
__device__ __forceinline__ void ldsm4t(uint32_t* r, uint32_t addr) {
    asm volatile("ldmatrix.sync.aligned.m8n8.x4.trans.shared.b16 {%0,%1,%2,%3}, [%4];"
                 : "=r"(r[0]), "=r"(r[1]), "=r"(r[2]), "=r"(r[3]) : "r"(addr));
}
// bf16 mma (flash)
__device__ __forceinline__ void mma16816(float* c, const uint32_t* a,
                                         uint32_t b0, uint32_t b1) {
    asm volatile(
        "mma.sync.aligned.m16n8k16.row.col.f32.bf16.bf16.f32 "
        "{%0,%1,%2,%3}, {%4,%5,%6,%7}, {%8,%9}, {%0,%1,%2,%3};"
        : "+f"(c[0]), "+f"(c[1]), "+f"(c[2]), "+f"(c[3])
        : "r"(a[0]), "r"(a[1]), "r"(a[2]), "r"(a[3]), "r"(b0), "r"(b1));
}
// tf32 mma (projections)
__device__ __forceinline__ void mma1688t(float* c, const uint32_t* a,
                                         uint32_t b0, uint32_t b1) {
    asm volatile(
        "mma.sync.aligned.m16n8k8.row.col.f32.tf32.tf32.f32 "
        "{%0,%1,%2,%3}, {%4,%5,%6,%7}, {%8,%9}, {%0,%1,%2,%3};"
        : "+f"(c[0]), "+f"(c[1]), "+f"(c[2]), "+f"(c[3])
        : "r"(a[0]), "r"(a[1]), "r"(a[2]), "r"(a[3]), "r"(b0), "r"(b1));
}
__device__ __forceinline__ void split2(float a, float b, uint32_t& hi, uint32_t& lo) {
    bf16 ha = __float2bfloat16(a), hb = __float2bfloat16(b);
    bf16 la = __float2bfloat16(a - __bfloat162float(ha));
    bf16 lb = __float2bfloat16(b - __bfloat162float(hb));
    __nv_bfloat162 h(ha, hb), l(la, lb);
    hi = *(uint32_t*)&h; lo = *(uint32_t*)&l;
}
// cheap truncation split: hi = packed high-16 bits (RZ bf16), lo = residual RN bf16x2
__device__ __forceinline__ void split2t(float a, float b, uint32_t& hi, uint32_t& lo) {
    uint32_t ia = __float_as_uint(a), ib = __float_as_uint(b);
    hi = __byte_perm(ia, ib, 0x7632);
    float fa = __uint_as_float(ia & 0xFFFF0000u);
    float fb = __uint_as_float(ib & 0xFFFF0000u);
    float la = a - fa, lb = b - fb;
    asm("cvt.rn.bf16x2.f32 %0, %1, %2;" : "=r"(lo) : "f"(lb), "f"(la));
}
// RNA round to tf32-exact fp32. tf32 lives in b32 registers in PTX -> "=r".
__device__ __forceinline__ float rna_tf32(float v) {
    uint32_t o;
    asm("cvt.rna.tf32.f32 %0, %1;" : "=r"(o) : "f"(v));
    return __uint_as_float(o);
}
// 16B-chunk XOR swizzle for 32-float (128B) rows: chunk 0..7, rows 0..127
__device__ __forceinline__ uint32_t swzf(int row, int chunk) {
    return (uint32_t)(row * 128 + ((chunk ^ (row & 7)) << 4));
}
// 16B-chunk XOR swizzle for 128-bf16 (256B) rows: chunk 0..15, rows 0..63
__device__ __forceinline__ uint32_t swzb(int row, int chunk) {
    return (uint32_t)(row * 256 + ((chunk ^ (row & 7)) << 4));
}

// ============================================================
// Prep: RNA-round fp32 -> tf32-exact fp32 copies (x + 4 weights)
// ============================================================
struct PrepJobs {
    const float4* in[5];
    float4* out[5];
    int n4[5];
    int blk0[5];
};

__global__ void prep_tf32(PrepJobs j, int totblk)
{
    int r = 0;
    #pragma unroll
    for (int i = 1; i < 5; i++) if ((int)blockIdx.x >= j.blk0[i]) r = i;
    const int rel  = blockIdx.x - j.blk0[r];
    const int nblk = ((r + 1 < 5) ? j.blk0[r + 1] : totblk) - j.blk0[r];
    const float4* in = j.in[r];
    float4* out = j.out[r];
    const int n4 = j.n4[r];
    for (int i = rel * blockDim.x + threadIdx.x; i < n4; i += nblk * blockDim.x) {
        float4 v = in[i];
        v.x = rna_tf32(v.x); v.y = rna_tf32(v.y);
        v.z = rna_tf32(v.z); v.w = rna_tf32(v.w);
        out[i] = v;
    }
}

// ============================================================
// tf32 GEMM: C[M,N] = A @ B^T + bias.  CTA 128x128, BK=32,
// 3-stage cp.async, 1 sync/iter, 2 CTAs/SM, 4 warps 2x2 (64x64/warp).
// (unchanged — proven)
// ============================================================
#define TOFF_A 0
#define TOFF_B (128*128)
#define TSTAGE (2*128*128)       // 32768 B
#define TGSMEM (3*TSTAGE)        // 98304 B
#define GT 128

struct GemmPtrs {
    const float* B[3];
    const float* bias[3];
    bf16* Ch[3];
    bf16* Cl[3];
    float* C[3];
};

__device__ __forceinline__ void t_load_tile(uint32_t sbase, const float* g,
                                            int row0, int k0, int tid)
{
    const char* gp = (const char*)(g + (size_t)row0 * Hsz + k0);
    #pragma unroll
    for (int c = tid; c < 1024; c += GT) {
        int row = c >> 3, ch = c & 7;
        CP_ASYNC16(sbase + swzf(row, ch), gp + (size_t)row * (Hsz * 4) + ch * 16);
    }
}
__device__ __forceinline__ void t_load_stage(uint32_t st, const float* A, const float* B,
                                             int bm, int bn, int k0, int tid)
{
    t_load_tile(st + TOFF_A, A, bm, k0, tid);
    t_load_tile(st + TOFF_B, B, bn, k0, tid);
}

template <bool BF16OUT>
__global__ void __launch_bounds__(GT, 2)
gemm_tf32(const float* __restrict__ A, GemmPtrs p)
{
    extern __shared__ __align__(128) char sm[];
    const uint32_t sb = smem_u32(sm);
    const int tid  = threadIdx.x;
    const int lane = tid & 31;
    const int wid  = tid >> 5;
    const int wm   = wid >> 1;
    const int wn   = wid & 1;
    const int region = blockIdx.x >> 4;
    const int bm = blockIdx.y * 128;
    const int bn = (blockIdx.x & 15) * 128;
    const float* Bm = p.B[region];

    float acc[4][8][4];
    #pragma unroll
    for (int i = 0; i < 4; i++)
        #pragma unroll
        for (int j = 0; j < 8; j++)
            #pragma unroll
            for (int t = 0; t < 4; t++) acc[i][j][t] = 0.f;

    t_load_stage(sb,          A, Bm, bm, bn, 0,  tid); CP_COMMIT();
    t_load_stage(sb + TSTAGE, A, Bm, bm, bn, 32, tid); CP_COMMIT();

    const int g  = lane >> 3;
    const int t8 = lane & 7;

    for (int kt = 0; kt < 64; kt++) {
        if (kt < 63) { CP_WAIT(1); } else { CP_WAIT(0); }
        __syncthreads();

        if (kt + 2 < 64) {
            t_load_stage(sb + ((kt + 2) % 3) * TSTAGE, A, Bm, bm, bn, (kt + 2) * 32, tid);
            CP_COMMIT();
        }

        const uint32_t st = sb + (kt % 3) * TSTAGE;
        #pragma unroll
        for (int kk = 0; kk < 4; kk++) {
            uint32_t af[4][4];
            #pragma unroll
            for (int mi = 0; mi < 4; mi++) {
                int row = wm * 64 + mi * 16 + t8 + ((g & 1) << 3);
                int ch  = kk * 2 + (g >> 1);
                ldsm4(af[mi], st + TOFF_A + swzf(row, ch));
            }
            uint32_t bfr[4][4];
            #pragma unroll
            for (int pj = 0; pj < 4; pj++) {
                int row = wn * 64 + (2 * pj + (g >> 1)) * 8 + t8;
                int ch  = kk * 2 + (g & 1);
                ldsm4(bfr[pj], st + TOFF_B + swzf(row, ch));
            }
            #pragma unroll
            for (int mi = 0; mi < 4; mi++) {
                #pragma unroll
                for (int nj = 0; nj < 8; nj++) {
                    const uint32_t* bp = bfr[nj >> 1] + (nj & 1) * 2;
                    mma1688t(acc[mi][nj], af[mi], bp[0], bp[1]);
                }
            }
        }
    }

    const int rbase = bm + wm * 64 + (lane >> 2);
    const int cbase = bn + wn * 64 + (lane & 3) * 2;
    const float* bias = p.bias[region];
    #pragma unroll
    for (int mi = 0; mi < 4; mi++) {
        #pragma unroll
        for (int nj = 0; nj < 8; nj++) {
            int row = rbase + mi * 16;
            int col = cbase + nj * 8;
            float b0 = __ldg(&bias[col]), b1 = __ldg(&bias[col + 1]);
            float* c = acc[mi][nj];
            float v00 = c[0] + b0, v01 = c[1] + b1;
            float v10 = c[2] + b0, v11 = c[3] + b1;
            if (BF16OUT) {
                bf16* Ch = p.Ch[region];
                bf16* Cl = p.Cl[region];
                uint32_t h, l;
                split2(v00, v01, h, l);
                *(uint32_t*)(Ch + (size_t)row * Hsz + col) = h;
                *(uint32_t*)(Cl + (size_t)row * Hsz + col) = l;
                split2(v10, v11, h, l);
                *(uint32_t*)(Ch + (size_t)(row + 8) * Hsz + col) = h;
                *(uint32_t*)(Cl + (size_t)(row + 8) * Hsz + col) = l;
            } else {
                float* C = p.C[region];
                *(float2*)(C + (size_t)row * Hsz + col) = make_float2(v00, v01);
                *(float2*)(C + (size_t)(row + 8) * Hsz + col) = make_float2(v10, v11);
            }
        }
    }
}

// ============================================================
// Flash attention via mma.sync, 3-pass split on QK and PV.
// BQ=64, BKV=64, 128 threads (4 warps x 16 query rows), 2 CTAs/SM.
// K double-buffered + V single. Correct pipeline:
//   CP_WAIT -> syncthreads -> read  at BOTH read points.
// ============================================================
#define KTILE 16384               // one 64x128 bf16 tile, swizzled 256B rows
#define KB0   0                   // K buffer 0: h @ +0, l @ +KTILE
#define KB1   (2*KTILE)           // K buffer 1
#define VB    (4*KTILE)           // V buffer: h @ +0, l @ +KTILE
#define ASMEM (6*KTILE)           // 98304 per CTA, 2 CTAs/SM
#define FT 128

__device__ __forceinline__ void fa_load64s(uint32_t sbase, const bf16* g, size_t gelem, int tid) {
    const char* gp = (const char*)(g + gelem);
    #pragma unroll
    for (int c = tid; c < 1024; c += FT) {
        int r = c >> 4, ch = c & 15;
        CP_ASYNC16(sbase + swzb(r, ch), gp + (size_t)r * (Hsz * 2) + ch * 16);
    }
}

__global__ void __launch_bounds__(FT, 2)
flash_mma(const bf16* __restrict__ Qh, const bf16* __restrict__ Ql,
          const bf16* __restrict__ Kh, const bf16* __restrict__ Kl,
          const bf16* __restrict__ Vh, const bf16* __restrict__ Vl,
          float* __restrict__ AO)
{
    extern __shared__ __align__(128) char sm[];
    const uint32_t sb = smem_u32(sm);
    const int tid = threadIdx.x;
    const int lane = tid & 31;
    const int w = tid >> 5;
    const int wrow = w * 16;
    const int qb = gridDim.x - 1 - blockIdx.x;   // heavy-first
    const int h = blockIdx.y, b = blockIdx.z;
    const int q0 = qb * 64;
    const size_t baseKV = (size_t)(b * Ssz) * Hsz + h * HDIM;
    const size_t baseQ  = baseKV + (size_t)q0 * Hsz;

    const int a_row = lane & 15;
    const int a_ch  = lane >> 4;              // Q/A chunk base (0/1)
    const int b_row = ((lane >> 4) & 1) * 8 + (lane & 7);
    const int b_ch  = (lane >> 3) & 1;        // K/B chunk base (0/1)
    const int t_row = lane & 15;
    const int t_ch  = lane >> 4;              // V trans chunk base (0/1)

    // ---- load Q fragments (hi then lo), staged through KB0 ----
    uint32_t qfh[8][4], qfl[8][4];
    fa_load64s(sb + KB0, Qh, baseQ, tid); CP_COMMIT(); CP_WAIT(0); __syncthreads();
    #pragma unroll
    for (int t = 0; t < 8; t++)
        ldsm4(qfh[t], sb + KB0 + swzb(wrow + a_row, a_ch + t * 2));
    __syncthreads();
    fa_load64s(sb + KB0, Ql, baseQ, tid); CP_COMMIT(); CP_WAIT(0); __syncthreads();
    #pragma unroll
    for (int t = 0; t < 8; t++)
        ldsm4(qfl[t], sb + KB0 + swzb(wrow + a_row, a_ch + t * 2));
    __syncthreads();

    // prologue: K(0) -> KB0
    fa_load64s(sb + KB0,         Kh, baseKV, tid);
    fa_load64s(sb + KB0 + KTILE, Kl, baseKV, tid);
    CP_COMMIT();

    float o[16][4];
    #pragma unroll
    for (int j = 0; j < 16; j++)
        #pragma unroll
        for (int t = 0; t < 4; t++) o[j][t] = 0.f;
    float m_i[2] = {-1e30f, -1e30f}, l_i[2] = {0.f, 0.f};

    const int ktmax = qb;
    const int r0 = lane >> 2;
    const float sc2 = 0.1275174112f;   // (1/sqrt(128)) * log2(e)

    // Loop invariant at top: pending cp.async groups = { K(kt) } only.
    for (int kt = 0; kt <= ktmax; kt++) {
        CP_WAIT(0);                // [A] my K(kt) copies complete
        __syncthreads();           // [B] K(kt) visible from ALL threads;
                                   //     V buf + kbuf[(kt+1)&1] free (all warps past
                                   //     PV(kt-1) and QK(kt-1))

        // [C] issue V(kt), then K(kt+1)
        fa_load64s(sb + VB,         Vh, baseKV + (size_t)(kt * 64) * Hsz, tid);
        fa_load64s(sb + VB + KTILE, Vl, baseKV + (size_t)(kt * 64) * Hsz, tid);
        CP_COMMIT();
        const bool more = kt < ktmax;
        if (more) {
            uint32_t kb = sb + (((kt + 1) & 1) ? KB1 : KB0);
            fa_load64s(kb,         Kh, baseKV + (size_t)((kt + 1) * 64) * Hsz, tid);
            fa_load64s(kb + KTILE, Kl, baseKV + (size_t)((kt + 1) * 64) * Hsz, tid);
            CP_COMMIT();
        }

        // [D] QK from kbuf[kt&1]
        const uint32_t kb = sb + ((kt & 1) ? KB1 : KB0);
        float s[8][4];
        #pragma unroll
        for (int j = 0; j < 8; j++)
            #pragma unroll
            for (int t = 0; t < 4; t++) s[j][t] = 0.f;
        #pragma unroll
        for (int t = 0; t < 8; t++) {
            uint32_t kbh[4][4], kbl[4][4];
            #pragma unroll
            for (int pp = 0; pp < 4; pp++) {
                uint32_t ra = swzb(pp * 16 + b_row, b_ch + t * 2);
                ldsm4(kbh[pp], kb + ra);
                ldsm4(kbl[pp], kb + KTILE + ra);
            }
            #pragma unroll
            for (int pp = 0; pp < 4; pp++) {
                #pragma unroll
                for (int hh = 0; hh < 2; hh++) {
                    mma16816(s[2*pp+hh], qfh[t], kbh[pp][hh*2], kbh[pp][hh*2+1]);
                    mma16816(s[2*pp+hh], qfh[t], kbl[pp][hh*2], kbl[pp][hh*2+1]);
                    mma16816(s[2*pp+hh], qfl[t], kbh[pp][hh*2], kbh[pp][hh*2+1]);
                }
            }
        }

        // [E] softmax (exp2 domain)
        uint32_t pah[4][4], pal[4][4];
        float fac[2];
        {
            #pragma unroll
            for (int j = 0; j < 8; j++)
                #pragma unroll
                for (int t = 0; t < 4; t++) s[j][t] *= sc2;
            if (kt == ktmax) {
                #pragma unroll
                for (int j = 0; j < 8; j++) {
                    int col = kt * 64 + j * 8 + (lane & 3) * 2;
                    int row = q0 + wrow + r0;
                    if (col > row)          s[j][0] = -1e30f;
                    if (col + 1 > row)      s[j][1] = -1e30f;
                    if (col > row + 8)      s[j][2] = -1e30f;
                    if (col + 1 > row + 8)  s[j][3] = -1e30f;
                }
            }
            #pragma unroll
            for (int r = 0; r < 2; r++) {
                float rm = -1e30f;
                #pragma unroll
                for (int j = 0; j < 8; j++) rm = fmaxf(rm, fmaxf(s[j][r*2], s[j][r*2+1]));
                rm = fmaxf(rm, __shfl_xor_sync(0xffffffffu, rm, 1));
                rm = fmaxf(rm, __shfl_xor_sync(0xffffffffu, rm, 2));
                float mn = fmaxf(m_i[r], rm);
                fac[r] = exp2f(m_i[r] - mn);
                float rs = 0.f;
                #pragma unroll
                for (int j = 0; j < 8; j++) {
                    s[j][r*2]   = exp2f(s[j][r*2]   - mn);
                    s[j][r*2+1] = exp2f(s[j][r*2+1] - mn);
                    rs += s[j][r*2] + s[j][r*2+1];
                }
                rs += __shfl_xor_sync(0xffffffffu, rs, 1);
                rs += __shfl_xor_sync(0xffffffffu, rs, 2);
                l_i[r] = l_i[r] * fac[r] + rs;
                m_i[r] = mn;
            }
            #pragma unroll
            for (int t2 = 0; t2 < 4; t2++) {
                split2t(s[2*t2][0],   s[2*t2][1],   pah[t2][0], pal[t2][0]);
                split2t(s[2*t2][2],   s[2*t2][3],   pah[t2][1], pal[t2][1]);
                split2t(s[2*t2+1][0], s[2*t2+1][1], pah[t2][2], pal[t2][2]);
                split2t(s[2*t2+1][2], s[2*t2+1][3], pah[t2][3], pal[t2][3]);
            }
            #pragma unroll
            for (int j = 0; j < 16; j++) {
                o[j][0] *= fac[0]; o[j][1] *= fac[0];
                o[j][2] *= fac[1]; o[j][3] *= fac[1];
            }
        }

        // [F] my V(kt) copies complete (K(kt+1) may remain in flight)
        if (more) { CP_WAIT(1); } else { CP_WAIT(0); }
        __syncthreads();           // [G] V(kt) visible from ALL threads

        // [H] PV from V buffer
        #pragma unroll
        for (int j2 = 0; j2 < 8; j2++) {
            #pragma unroll
            for (int t = 0; t < 4; t++) {
                uint32_t bvh[4], bvl[4];
                uint32_t ra = swzb(t * 16 + t_row, t_ch + j2 * 2);
                ldsm4t(bvh, sb + VB + ra);
                ldsm4t(bvl, sb + VB + KTILE + ra);
                mma16816(o[2*j2],   pah[t], bvh[0], bvh[1]);
                mma16816(o[2*j2+1], pah[t], bvh[2], bvh[3]);
                mma16816(o[2*j2],   pah[t], bvl[0], bvl[1]);
                mma16816(o[2*j2+1], pah[t], bvl[2], bvl[3]);
                mma16816(o[2*j2],   pal[t], bvh[0], bvh[1]);
                mma16816(o[2*j2+1], pal[t], bvh[2], bvh[3]);
            }
        }
        // loop-end pending: { K(kt+1) } -> invariant holds
    }

    // epilogue: normalize + RNA-round to tf32-exact fp32 (input of O-proj)
    const float inv0 = 1.0f / l_i[0], inv1 = 1.0f / l_i[1];
    const int grow0 = q0 + wrow + r0;
    #pragma unroll
    for (int j = 0; j < 16; j++) {
        int col = j * 8 + (lane & 3) * 2;
        size_t e0 = baseKV + (size_t)grow0 * Hsz + col;
        size_t e1 = baseKV + (size_t)(grow0 + 8) * Hsz + col;
        *(float2*)(AO + e0) = make_float2(rna_tf32(o[j][0] * inv0), rna_tf32(o[j][1] * inv0));
        *(float2*)(AO + e1) = make_float2(rna_tf32(o[j][2] * inv1), rna_tf32(o[j][3] * inv1));
    }
}

// ============================================================
extern "C" void kernel_launch(void* const* d_in, const int* in_sizes, int n_in,
                              void* d_out, int out_size) {
    const float* x  = (const float*)d_in[0];
    const float* Wf[4] = { (const float*)d_in[1], (const float*)d_in[3],
                           (const float*)d_in[5], (const float*)d_in[7] };
    const float* bQ = (const float*)d_in[2];
    const float* bK = (const float*)d_in[4];
    const float* bV = (const float*)d_in[6];
    const float* bO = (const float*)d_in[8];
    float* out = (float*)d_out;

    float *xt, *wt, *ao;
    bf16 *qh, *ql, *kh, *kl, *vh, *vl;
    cudaGetSymbolAddress((void**)&xt, g_xt);
    cudaGetSymbolAddress((void**)&wt, g_wt);
    cudaGetSymbolAddress((void**)&ao, g_ao);
    cudaGetSymbolAddress((void**)&qh, g_qh);  cudaGetSymbolAddress((void**)&ql, g_ql);
    cudaGetSymbolAddress((void**)&kh, g_kh);  cudaGetSymbolAddress((void**)&kl, g_kl);
    cudaGetSymbolAddress((void**)&vh, g_vh);  cudaGetSymbolAddress((void**)&vl, g_vl);

    const size_t HH = (size_t)Hsz * Hsz;

    // Launch 1: RNA-round x + weights into tf32-exact fp32 copies
    PrepJobs pj;
    pj.in[0]  = (const float4*)x;
    pj.out[0] = (float4*)xt;
    pj.n4[0]  = Mrows * Hsz / 4;
    pj.blk0[0] = 0;
    for (int i = 0; i < 4; i++) {
        pj.in[i+1]  = (const float4*)Wf[i];
        pj.out[i+1] = (float4*)(wt + i * HH);
        pj.n4[i+1]  = Hsz * Hsz / 4;
        pj.blk0[i+1] = 768 + i * 384;
    }
    const int totblk = 768 + 4 * 384;   // 2304
    prep_tf32<<<totblk, 256>>>(pj, totblk);

    cudaFuncSetAttribute(gemm_tf32<true>,  cudaFuncAttributeMaxDynamicSharedMemorySize, TGSMEM);
    cudaFuncSetAttribute(gemm_tf32<false>, cudaFuncAttributeMaxDynamicSharedMemorySize, TGSMEM);

    // Launch 2: fused QKV tf32 GEMM (bf16 hi/lo outputs for flash)
    GemmPtrs pq;
    pq.B[0] = wt;           pq.B[1] = wt + HH;      pq.B[2] = wt + 2 * HH;
    pq.bias[0] = bQ;        pq.bias[1] = bK;        pq.bias[2] = bV;
    pq.Ch[0] = qh;          pq.Ch[1] = kh;          pq.Ch[2] = vh;
    pq.Cl[0] = ql;          pq.Cl[1] = kl;          pq.Cl[2] = vl;
    pq.C[0] = pq.C[1] = pq.C[2] = nullptr;
    gemm_tf32<true><<<dim3(48, Mrows / 128), GT, TGSMEM>>>(xt, pq);

    // Launch 3: attention (bf16 3-pass, K double-buffered, corrected pipeline)
    cudaFuncSetAttribute(flash_mma, cudaFuncAttributeMaxDynamicSharedMemorySize, ASMEM);
    flash_mma<<<dim3(Ssz / 64, NHEAD, Bsz), FT, ASMEM>>>(qh, ql, kh, kl, vh, vl, ao);

    // Launch 4: output projection (tf32, fp32 out)
    GemmPtrs po;
    po.B[0] = wt + 3 * HH;  po.B[1] = po.B[2] = nullptr;
    po.bias[0] = bO;        po.bias[1] = po.bias[2] = nullptr;
    po.Ch[0] = po.Ch[1] = po.Ch[2] = nullptr;
    po.Cl[0] = po.Cl[1] = po.Cl[2] = nullptr;
    po.C[0] = out;          po.C[1] = po.C[2] = nullptr;
    gemm_tf32<false><<<dim3(16, Mrows / 128), GT, TGSMEM>>>(ao, po);
}